// round 4
// baseline (speedup 1.0000x reference)
#include <cuda_runtime.h>
#include <cuda_bf16.h>
#include <math.h>
#include <stdint.h>

#define NN 50000
#define NP 50048          // NN padded to 128 (391*128)
#define RR 6
#define EE 32768
#define HH 256
#define FF 16
#define KVO 272
#define KVP 320           // 272 padded to 64-multiple
#define NHD 8
#define HDD 32
#define RH 1536

typedef __nv_bfloat16 bf16;

#if defined(__CUDA_ARCH__) && defined(__CUDA_ARCH_FEAT_SM103_ALL)
#define HAS_TC05 1
#else
#define HAS_TC05 0
#endif

// ---------------- scratch (device globals; zero-initialized at load) ----------------
__device__ __align__(1024) bf16 g_kvin_h[EE * KVP], g_kvin_l[EE * KVP];
__device__ __align__(1024) bf16 g_xd_h[EE * HH],   g_xd_l[EE * HH];
__device__ float g_qe[EE * HH], g_k[EE * HH], g_v[EE * HH];
__device__ float g_sc[EE * NHD], g_m[NN * NHD], g_denom[NN * NHD];
__device__ float g_agg[NN * HH];
__device__ __align__(1024) bf16 g_agg_h[NP * HH], g_agg_l[NP * HH];
__device__ __align__(1024) bf16 g_rel_h[NP * RH], g_rel_l[NP * RH];
__device__ float g_hbuf[NP * HH];
__device__ float g_interw[NN * NHD];
__device__ __align__(1024) bf16 g_cat_h[NP * 2 * HH], g_cat_l[NP * 2 * HH];
__device__ __align__(1024) bf16 g_pth_h[3 * NP * HH], g_pth_l[3 * NP * HH];
__device__ float g_stacked[NP * 3 * HH];
__device__ __align__(1024) bf16 g_stk_h[NP * 3 * HH], g_stk_l[NP * 3 * HH];
__device__ float g_t[3 * NP * (HH / 2)];
// transposed + split weights: [Ncol][Kpad]
__device__ __align__(1024) bf16 g_wqt_h[RR * HH * HH],  g_wqt_l[RR * HH * HH];
__device__ __align__(1024) bf16 g_wkt_h[RR * HH * KVP], g_wkt_l[RR * HH * KVP];
__device__ __align__(1024) bf16 g_wvt_h[RR * HH * KVP], g_wvt_l[RR * HH * KVP];
__device__ __align__(1024) bf16 g_wmt_h[RR * HH * HH],  g_wmt_l[RR * HH * HH];
__device__ __align__(1024) bf16 g_wir1t_h[HH * RH],     g_wir1t_l[HH * RH];
__device__ __align__(1024) bf16 g_wmpt_h[3 * HH * HH],  g_wmpt_l[3 * HH * HH];
__device__ __align__(1024) bf16 g_wa1t_h[(HH/2) * HH],  g_wa1t_l[(HH/2) * HH];
__device__ __align__(1024) bf16 g_wct_h[HH * 2 * HH],   g_wct_l[HH * 2 * HH];

// ---------------- common helpers ----------------
__device__ __forceinline__ float gelu_exact(float x) {
    return 0.5f * x * (1.0f + erff(x * 0.7071067811865475f));
}
__device__ __forceinline__ void split_store(float v, bf16* ph, bf16* pl) {
    bf16 h = __float2bfloat16(v);
    *ph = h;
    *pl = __float2bfloat16(v - __bfloat162float(h));
}
__device__ __forceinline__ void atomicMaxF(float* addr, float v) {
    int* ai = (int*)addr;
    int old = *ai;
    while (__int_as_float(old) < v) {
        int assumed = old;
        old = atomicCAS(ai, assumed, __float_as_int(v));
        if (old == assumed) break;
    }
}

#if HAS_TC05
// ---------------- tcgen05-only PTX helpers ----------------
__device__ __forceinline__ uint32_t smem_u32(const void* p) {
    uint32_t a;
    asm("{ .reg .u64 t; cvta.to.shared.u64 t, %1; cvt.u32.u64 %0, t; }" : "=r"(a) : "l"(p));
    return a;
}
#define SWZ128(o) ((o) ^ (((o) >> 3) & 0x70))

__device__ __forceinline__ uint64_t mkdesc(uint32_t addr) {
    return ((uint64_t)2 << 61) | ((uint64_t)1 << 46) | ((uint64_t)64 << 32) |
           ((uint64_t)1 << 16) | ((addr >> 4) & 0x3FFF);
}

__device__ __forceinline__ void mma_f16_ss(uint32_t d, uint64_t ad, uint64_t bd,
                                           uint32_t idesc, bool acc) {
    uint32_t en = acc ? 1u : 0u;
    asm volatile(
        "{\n\t.reg .pred p;\n\tsetp.ne.u32 p, %5, 0;\n\t"
        "tcgen05.mma.cta_group::1.kind::f16 [%0], %1, %2, %3, {%4,%4,%4,%4}, p;\n\t}"
        :: "r"(d), "l"(ad), "l"(bd), "r"(idesc), "r"(0u), "r"(en) : "memory");
}

__device__ __forceinline__ void mbar_init(uint32_t mb, uint32_t cnt) {
    asm volatile("mbarrier.init.shared.b64 [%0], %1;" :: "r"(mb), "r"(cnt) : "memory");
}
__device__ __forceinline__ void mbar_wait(uint32_t mb, int parity) {
    asm volatile(
        "{\n\t.reg .pred P1;\n\t"
        "WL_%=:\n\t"
        "mbarrier.try_wait.parity.acquire.cta.shared::cta.b64 P1, [%0], %1, 0x989680;\n\t"
        "@P1 bra.uni WD_%=;\n\t"
        "bra.uni WL_%=;\n\t"
        "WD_%=:\n\t}"
        :: "r"(mb), "r"(parity) : "memory");
}
#define CP_ASYNC16(dst, src) \
    asm volatile("cp.async.cg.shared.global [%0], [%1], 16;" :: "r"(dst), "l"(src))
#define CP_COMMIT() asm volatile("cp.async.commit_group;")
#define CP_WAIT1()  asm volatile("cp.async.wait_group 1;")
#define CP_WAIT0()  asm volatile("cp.async.wait_group 0;")

#define LDTM_X32(r, a) \
    asm volatile( \
        "tcgen05.ld.sync.aligned.32x32b.x32.b32 " \
        "{%0, %1, %2, %3, %4, %5, %6, %7, " \
        " %8, %9, %10, %11, %12, %13, %14, %15, " \
        " %16, %17, %18, %19, %20, %21, %22, %23, " \
        " %24, %25, %26, %27, %28, %29, %30, %31}, [%32];" \
        : "=r"((r)[0]),  "=r"((r)[1]),  "=r"((r)[2]),  "=r"((r)[3]), \
          "=r"((r)[4]),  "=r"((r)[5]),  "=r"((r)[6]),  "=r"((r)[7]), \
          "=r"((r)[8]),  "=r"((r)[9]),  "=r"((r)[10]), "=r"((r)[11]), \
          "=r"((r)[12]), "=r"((r)[13]), "=r"((r)[14]), "=r"((r)[15]), \
          "=r"((r)[16]), "=r"((r)[17]), "=r"((r)[18]), "=r"((r)[19]), \
          "=r"((r)[20]), "=r"((r)[21]), "=r"((r)[22]), "=r"((r)[23]), \
          "=r"((r)[24]), "=r"((r)[25]), "=r"((r)[26]), "=r"((r)[27]), \
          "=r"((r)[28]), "=r"((r)[29]), "=r"((r)[30]), "=r"((r)[31]) \
        : "r"(a))
#endif  // HAS_TC05

#if !HAS_TC05
// mma.sync fallback helper (valid on any sm_80+ target)
__device__ __forceinline__ void hmma16816(float* c, const uint32_t* a, const uint32_t* b) {
    asm volatile(
        "mma.sync.aligned.m16n8k16.row.col.f32.bf16.bf16.f32 "
        "{%0,%1,%2,%3}, {%4,%5,%6,%7}, {%8,%9}, {%0,%1,%2,%3};"
        : "+f"(c[0]), "+f"(c[1]), "+f"(c[2]), "+f"(c[3])
        : "r"(a[0]), "r"(a[1]), "r"(a[2]), "r"(a[3]), "r"(b[0]), "r"(b[1]));
}
#endif

// ---------------- bf16x3 GEMM ----------------
// C[m, coff+n] = act( sum_k (Ah+Al)[m,k] * (Bh+Bl)[n,k] + bias[n] )  via AhBh+AhBl+AlBh
// A: [M,K] bf16 row-major (hi,lo).  B: [NT,K] bf16 row-major (weights pre-transposed).
// STORE: 0 = fp32 C only; 1 = fp32 C + bf16 hi/lo; 2 = bf16 hi/lo only.
template <int NT, int ACT, int STORE>
__global__ __launch_bounds__(128)
void tcmm(const bf16* __restrict__ Ah, const bf16* __restrict__ Al,
          const bf16* __restrict__ Bh, const bf16* __restrict__ Bl,
          const float* __restrict__ bias,
          float* __restrict__ C, int ldc, int coff,
          bf16* __restrict__ Ch, bf16* __restrict__ Cl, int ldh, int offh,
          int M, int K) {
    extern __shared__ char smem[];
    const int tid = threadIdx.x, wid = tid >> 5, lid = tid & 31;
    const int m0 = blockIdx.x * 128;

#if HAS_TC05
    // ================= tcgen05 path =================
    const uint32_t sb = smem_u32(smem);
    const int ABYTES = 128 * 128;       // 16 KB A tile (128 rows x 64 bf16)
    const int BBYTES = NT * 128;        // B tile
    const int BUF = ABYTES + BBYTES;
    const uint32_t mbar0 = sb + 8, mbar1 = sb + 16;
    const uint32_t buf0 = sb + 1024;

    if (wid == 0) {
        asm volatile("tcgen05.alloc.cta_group::1.sync.aligned.shared::cta.b32 [%0], %1;"
                     :: "r"(sb), "r"(256u) : "memory");
        asm volatile("tcgen05.relinquish_alloc_permit.cta_group::1.sync.aligned;");
    }
    __syncthreads();
    uint32_t tmem;
    asm volatile("ld.shared.b32 %0, [%1];" : "=r"(tmem) : "r"(sb));
    if (tid == 0) { mbar_init(mbar0, 1); mbar_init(mbar1, 1); }
    __syncthreads();

    const int KC = K >> 6;
    const int T = KC * 3;
    // M=128, N=64 per MMA (the exact shape class verified by test_mma_mxf8_512)
    const uint32_t idesc64 = (1u << 4) | (1u << 7) | (1u << 10) | (8u << 17) | (8u << 24);

    auto load_chunk = [&](int c, uint32_t bufbase) {
        int p = c / KC, kc = (c - p * KC) << 6;
        const bf16* Ap = (p == 2) ? Al : Ah;
        const bf16* Bp = (p == 1) ? Bl : Bh;
        const int TOT = (128 + NT) * 8;
        for (int i = tid; i < TOT; i += 128) {
            uint32_t dst;
            const bf16* src;
            if (i < 1024) {
                int r = i >> 3, g = i & 7;
                dst = bufbase + SWZ128(r * 128 + g * 16);
                src = Ap + (size_t)(m0 + r) * K + kc + g * 8;
            } else {
                int j = i - 1024;
                int r = j >> 3, g = j & 7;
                dst = bufbase + ABYTES + SWZ128(r * 128 + g * 16);
                src = Bp + (size_t)r * K + kc + g * 8;
            }
            CP_ASYNC16(dst, src);
        }
        CP_COMMIT();
    };

    int ph0 = 0, ph1 = 0;
    load_chunk(0, buf0);
    for (int c = 0; c < T; c++) {
        int b = c & 1;
        if (c + 1 < T) {
            int nb = b ^ 1;
            if (c >= 1) {   // wait mma of chunk c-1 (same buffer) before refill
                if (nb) { mbar_wait(mbar1, ph1); ph1 ^= 1; }
                else    { mbar_wait(mbar0, ph0); ph0 ^= 1; }
            }
            load_chunk(c + 1, buf0 + nb * BUF);
            CP_WAIT1();
        } else {
            CP_WAIT0();
        }
        __syncthreads();
        if (tid == 0) {
            asm volatile("fence.proxy.async.shared::cta;" ::: "memory");
            uint64_t ad = mkdesc(buf0 + b * BUF);
            uint64_t bd = mkdesc(buf0 + b * BUF + ABYTES);
#pragma unroll
            for (int ks = 0; ks < 4; ks++)
#pragma unroll
                for (int ns = 0; ns < NT / 64; ns++)
                    // B sub-tile: 64 rows x 128B = 8192B = 512 x 16B units
                    mma_f16_ss(tmem + ns * 64, ad + ks * 2, bd + ns * 512 + ks * 2,
                               idesc64, (c > 0) || (ks > 0));
            asm volatile("tcgen05.commit.cta_group::1.mbarrier::arrive::one.shared::cluster.b64 [%0];"
                         :: "r"(b ? mbar1 : mbar0) : "memory");
        }
    }
    {   // final completion
        int lb = (T - 1) & 1;
        if (lb) mbar_wait(mbar1, ph1); else mbar_wait(mbar0, ph0);
    }
    asm volatile("tcgen05.fence::after_thread_sync;" ::: "memory");

    // epilogue: warp w handles rows m0 + w*32 + lane (its own TMEM subpartition)
    int row = m0 + wid * 32 + lid;
    for (int cb = 0; cb < NT; cb += 32) {
        uint32_t regs[32];
        LDTM_X32(regs, tmem + cb);
        asm volatile("tcgen05.wait::ld.sync.aligned;" ::: "memory");
        if (row < M) {
#pragma unroll
            for (int j = 0; j < 32; j++) {
                int col = cb + j;
                float v = __uint_as_float(regs[j]) + bias[col];
                if (ACT == 1) v = gelu_exact(v);
                else if (ACT == 2) v = tanhf(v);
                if (STORE != 2) C[(size_t)row * ldc + coff + col] = v;
                if (STORE != 0)
                    split_store(v, Ch + (size_t)row * ldh + offh + col,
                                   Cl + (size_t)row * ldh + offh + col);
            }
        }
    }
    __syncthreads();
    if (wid == 0)
        asm volatile("tcgen05.dealloc.cta_group::1.sync.aligned.b32 %0, %1;"
                     :: "r"(tmem), "r"(256u));

#else
    // ================= mma.sync (HMMA) fallback path =================
    // 4 warps; warp w computes rows [m0+w*32, +32), N processed in 64-wide chunks.
    bf16* As = (bf16*)smem;          // [128][40]
    bf16* Bs = As + 128 * 40;        // [64][40]
    const int g = lid >> 2, tig = lid & 3;

    for (int nc = 0; nc < NT / 64; nc++) {
        float acc[2][8][4];
#pragma unroll
        for (int i = 0; i < 2; i++)
#pragma unroll
            for (int j = 0; j < 8; j++)
#pragma unroll
                for (int q = 0; q < 4; q++) acc[i][j][q] = 0.f;

        for (int ph = 0; ph < 3; ph++) {
            const bf16* Ap = (ph == 2) ? Al : Ah;
            const bf16* Bp = (ph == 1) ? Bl : Bh;
            for (int k0 = 0; k0 < K; k0 += 32) {
#pragma unroll
                for (int rep = 0; rep < 4; rep++) {
                    int i = tid + 128 * rep;      // 0..511: A 128 rows x 4 segs
                    int r = i >> 2, s = i & 3;
                    *(uint4*)(As + r * 40 + s * 8) =
                        *(const uint4*)(Ap + (size_t)(m0 + r) * K + k0 + s * 8);
                }
#pragma unroll
                for (int rep = 0; rep < 2; rep++) {
                    int i = tid + 128 * rep;      // 0..255: B 64 rows x 4 segs
                    int r = i >> 2, s = i & 3;
                    *(uint4*)(Bs + r * 40 + s * 8) =
                        *(const uint4*)(Bp + (size_t)(nc * 64 + r) * K + k0 + s * 8);
                }
                __syncthreads();
#pragma unroll
                for (int kk = 0; kk < 32; kk += 16) {
                    uint32_t afr[2][4], bfr[8][2];
#pragma unroll
                    for (int i = 0; i < 2; i++) {
                        int rb = wid * 32 + i * 16;
                        afr[i][0] = *(const uint32_t*)(As + (rb + g) * 40 + kk + 2 * tig);
                        afr[i][1] = *(const uint32_t*)(As + (rb + g + 8) * 40 + kk + 2 * tig);
                        afr[i][2] = *(const uint32_t*)(As + (rb + g) * 40 + kk + 2 * tig + 8);
                        afr[i][3] = *(const uint32_t*)(As + (rb + g + 8) * 40 + kk + 2 * tig + 8);
                    }
#pragma unroll
                    for (int j = 0; j < 8; j++) {
                        bfr[j][0] = *(const uint32_t*)(Bs + (j * 8 + g) * 40 + kk + 2 * tig);
                        bfr[j][1] = *(const uint32_t*)(Bs + (j * 8 + g) * 40 + kk + 2 * tig + 8);
                    }
#pragma unroll
                    for (int i = 0; i < 2; i++)
#pragma unroll
                        for (int j = 0; j < 8; j++)
                            hmma16816(acc[i][j], afr[i], bfr[j]);
                }
                __syncthreads();
            }
        }

        // epilogue for this 64-col chunk
#pragma unroll
        for (int i = 0; i < 2; i++)
#pragma unroll
            for (int j = 0; j < 8; j++) {
                int col0 = nc * 64 + j * 8 + 2 * tig;
#pragma unroll
                for (int r8 = 0; r8 < 2; r8++) {
                    int row = m0 + wid * 32 + i * 16 + g + r8 * 8;
                    if (row < M) {
#pragma unroll
                        for (int cc = 0; cc < 2; cc++) {
                            int col = col0 + cc;
                            float v = acc[i][j][r8 * 2 + cc] + bias[col];
                            if (ACT == 1) v = gelu_exact(v);
                            else if (ACT == 2) v = tanhf(v);
                            if (STORE != 2) C[(size_t)row * ldc + coff + col] = v;
                            if (STORE != 0)
                                split_store(v, Ch + (size_t)row * ldh + offh + col,
                                               Cl + (size_t)row * ldh + offh + col);
                        }
                    }
                }
            }
    }
#endif
}

// ---------------- conversion / small kernels ----------------
__global__ void tsplit(const float* __restrict__ W, bf16* __restrict__ oh,
                       bf16* __restrict__ ol, int Kin, int Ncol, int Kpad) {
    int idx = blockIdx.x * blockDim.x + threadIdx.x;
    if (idx >= Ncol * Kpad) return;
    int n = idx / Kpad, k = idx - n * Kpad;
    float v = (k < Kin) ? W[(size_t)k * Ncol + n] : 0.f;
    split_store(v, oh + idx, ol + idx);
}

__global__ void fill_kernel(float* p, int n, float v) {
    int i = blockIdx.x * blockDim.x + threadIdx.x;
    if (i < n) p[i] = v;
}

__global__ void gather_split(const float* __restrict__ x, const int* __restrict__ ei,
                             const float* __restrict__ ea, int r) {
    int idx = blockIdx.x * blockDim.x + threadIdx.x;
    const int tot1 = EE * KVP;
    if (idx < tot1) {
        int e = idx / KVP, c = idx - e * KVP;
        int src = ei[(r * 2 + 0) * EE + e];
        float v = (c < HH) ? x[src * HH + c]
                : ((c < KVO) ? ea[((size_t)r * EE + e) * FF + (c - HH)] : 0.f);
        split_store(v, g_kvin_h + idx, g_kvin_l + idx);
    } else {
        int j = idx - tot1;
        if (j < EE * HH) {
            int e = j >> 8, c = j & 255;
            int dst = ei[(r * 2 + 1) * EE + e];
            split_store(x[dst * HH + c], g_xd_h + j, g_xd_l + j);
        }
    }
}

__global__ void scores_kernel(const int* __restrict__ ei, const float* __restrict__ prior, int r) {
    int idx = blockIdx.x * blockDim.x + threadIdx.x;
    if (idx >= EE * NHD) return;
    int e = idx >> 3, h = idx & 7;
    const float* qp = g_qe + e * HH + h * HDD;
    const float* kp = g_k + e * HH + h * HDD;
    float s = 0.f;
#pragma unroll
    for (int d = 0; d < HDD; d++) s += qp[d] * kp[d];
    s *= 0.17677669529663687f * prior[r * NHD + h];
    g_sc[idx] = s;
    int dst = ei[(r * 2 + 1) * EE + e];
    atomicMaxF(&g_m[dst * NHD + h], s);
}

__global__ void ex_kernel(const int* __restrict__ ei, int r) {
    int idx = blockIdx.x * blockDim.x + threadIdx.x;
    if (idx >= EE * NHD) return;
    int e = idx >> 3, h = idx & 7;
    int dst = ei[(r * 2 + 1) * EE + e];
    float exv = expf(g_sc[idx] - g_m[dst * NHD + h]);
    g_sc[idx] = exv;
    atomicAdd(&g_denom[dst * NHD + h], exv);
}

__global__ void agg_kernel(const int* __restrict__ ei, int r) {
    int idx = blockIdx.x * blockDim.x + threadIdx.x;
    if (idx >= EE * HH) return;
    int e = idx >> 8, c = idx & 255;
    int h = c >> 5;
    int dst = ei[(r * 2 + 1) * EE + e];
    float w = g_sc[e * NHD + h] / (g_denom[dst * NHD + h] + 1e-16f);
    atomicAdd(&g_agg[dst * HH + c], w * g_v[idx]);
}

__global__ void agg_split_kernel() {
    int idx = blockIdx.x * blockDim.x + threadIdx.x;
    if (idx >= NN * HH) return;
    split_store(g_agg[idx], g_agg_h + idx, g_agg_l + idx);
}

__global__ void interw_kernel(const float* __restrict__ Wir2, const float* __restrict__ bir2) {
    int gwarp = (blockIdx.x * blockDim.x + threadIdx.x) >> 5;
    int lane = threadIdx.x & 31;
    if (gwarp >= NN) return;
    float acc[RR] = {};
    for (int k = lane; k < HH; k += 32) {
        float hv = g_hbuf[gwarp * HH + k];
#pragma unroll
        for (int rr = 0; rr < RR; rr++) acc[rr] += hv * Wir2[k * RR + rr];
    }
#pragma unroll
    for (int rr = 0; rr < RR; rr++)
#pragma unroll
        for (int off = 16; off; off >>= 1)
            acc[rr] += __shfl_down_sync(0xffffffff, acc[rr], off);
    if (lane == 0) {
        float mx = -1e30f;
#pragma unroll
        for (int rr = 0; rr < RR; rr++) { acc[rr] += bir2[rr]; mx = fmaxf(mx, acc[rr]); }
        float s = 0.f;
#pragma unroll
        for (int rr = 0; rr < RR; rr++) { acc[rr] = expf(acc[rr] - mx); s += acc[rr]; }
        float inv = 1.f / s;
#pragma unroll
        for (int rr = 0; rr < RR; rr++) g_interw[gwarp * NHD + rr] = acc[rr] * inv;
    }
}

__global__ void interagg_kernel() {
    int idx = blockIdx.x * blockDim.x + threadIdx.x;
    if (idx >= NN * HH) return;
    int n = idx >> 8, c = idx & 255;
    float s = 0.f;
#pragma unroll
    for (int rr = 0; rr < RR; rr++) {
        size_t b = (size_t)n * RH + rr * HH + c;
        s += g_interw[n * NHD + rr] *
             (__bfloat162float(g_rel_h[b]) + __bfloat162float(g_rel_l[b]));
    }
    split_store(s, g_cat_h + (size_t)n * 2 * HH + c, g_cat_l + (size_t)n * 2 * HH + c);
}

__global__ void paths_kernel() {
    int idx = blockIdx.x * blockDim.x + threadIdx.x;
    if (idx >= NN * HH) return;
    int n = idx >> 8, c = idx & 255;
    float v[RR];
#pragma unroll
    for (int rr = 0; rr < RR; rr++) {
        size_t b = (size_t)n * RH + rr * HH + c;
        v[rr] = __bfloat162float(g_rel_h[b]) + __bfloat162float(g_rel_l[b]);
    }
    split_store(v[2] + v[3], g_pth_h + ((size_t)0 * NP + n) * HH + c, g_pth_l + ((size_t)0 * NP + n) * HH + c);
    split_store(v[4] + v[0], g_pth_h + ((size_t)1 * NP + n) * HH + c, g_pth_l + ((size_t)1 * NP + n) * HH + c);
    split_store(v[1] + v[5], g_pth_h + ((size_t)2 * NP + n) * HH + c, g_pth_l + ((size_t)2 * NP + n) * HH + c);
}

__global__ void attnmeta_kernel(const float* __restrict__ Wa2,
                                const float* __restrict__ gm, const float* __restrict__ bm_) {
    __shared__ float lg[3];
    __shared__ float rbuf[256];
    int n = blockIdx.x, t = threadIdx.x;
    int lane = t & 31, w = t >> 5;
    if (w < 3) {
        float a = 0.f;
        for (int j = lane; j < 128; j += 32)
            a += g_t[((size_t)n * 3 + w) * 128 + j] * Wa2[j];
#pragma unroll
        for (int off = 16; off; off >>= 1) a += __shfl_down_sync(0xffffffff, a, off);
        if (lane == 0) lg[w] = a;
    }
    __syncthreads();
    float l0 = lg[0], l1 = lg[1], l2 = lg[2];
    float mx = fmaxf(l0, fmaxf(l1, l2));
    float e0 = expf(l0 - mx), e1 = expf(l1 - mx), e2 = expf(l2 - mx);
    float inv = 1.f / (e0 + e1 + e2);
    const float* st = g_stacked + (size_t)n * 3 * HH;
    float s = (e0 * st[t] + e1 * st[HH + t] + e2 * st[2 * HH + t]) * inv;
    rbuf[t] = s;
    __syncthreads();
    for (int off = 128; off; off >>= 1) { if (t < off) rbuf[t] += rbuf[t + off]; __syncthreads(); }
    float mu = rbuf[0] * (1.f / 256.f);
    __syncthreads();
    float d = s - mu;
    rbuf[t] = d * d;
    __syncthreads();
    for (int off = 128; off; off >>= 1) { if (t < off) rbuf[t] += rbuf[t + off]; __syncthreads(); }
    float var = rbuf[0] * (1.f / 256.f);
    float o = d * rsqrtf(var + 1e-5f) * gm[t] + bm_[t];
    split_store(o, g_cat_h + (size_t)n * 2 * HH + HH + t, g_cat_l + (size_t)n * 2 * HH + HH + t);
}

__global__ void outln_kernel(const float* __restrict__ x, const float* __restrict__ gout,
                             const float* __restrict__ bout, float* __restrict__ out) {
    __shared__ float rbuf[256];
    int n = blockIdx.x, t = threadIdx.x;
    float v = x[(size_t)n * HH + t] + g_hbuf[(size_t)n * HH + t];
    rbuf[t] = v;
    __syncthreads();
    for (int off = 128; off; off >>= 1) { if (t < off) rbuf[t] += rbuf[t + off]; __syncthreads(); }
    float mu = rbuf[0] * (1.f / 256.f);
    __syncthreads();
    float d = v - mu;
    rbuf[t] = d * d;
    __syncthreads();
    for (int off = 128; off; off >>= 1) { if (t < off) rbuf[t] += rbuf[t + off]; __syncthreads(); }
    float var = rbuf[0] * (1.f / 256.f);
    out[(size_t)n * HH + t] = d * rsqrtf(var + 1e-5f) * gout[t] + bout[t];
}

// ---------------- host ----------------
extern "C" void kernel_launch(void* const* d_in, const int* in_sizes, int n_in,
                              void* d_out, int out_size) {
    const float* x     = (const float*)d_in[0];
    const int*   ei    = (const int*)d_in[1];
    const float* ea    = (const float*)d_in[2];
    const float* Wq    = (const float*)d_in[3];
    const float* bq    = (const float*)d_in[4];
    const float* Wk    = (const float*)d_in[5];
    const float* bk    = (const float*)d_in[6];
    const float* Wv    = (const float*)d_in[7];
    const float* bv    = (const float*)d_in[8];
    const float* prior = (const float*)d_in[9];
    const float* Wm    = (const float*)d_in[10];
    const float* bm    = (const float*)d_in[11];
    const float* W_ir1 = (const float*)d_in[12];
    const float* b_ir1 = (const float*)d_in[13];
    const float* W_ir2 = (const float*)d_in[14];
    const float* b_ir2 = (const float*)d_in[15];
    const float* Wmp   = (const float*)d_in[16];
    const float* bmp   = (const float*)d_in[17];
    const float* Wa1   = (const float*)d_in[18];
    const float* ba1   = (const float*)d_in[19];
    const float* Wa2   = (const float*)d_in[20];
    const float* gmeta = (const float*)d_in[21];
    const float* bmeta = (const float*)d_in[22];
    const float* Wc    = (const float*)d_in[23];
    const float* bc    = (const float*)d_in[24];
    const float* gout  = (const float*)d_in[25];
    const float* bout  = (const float*)d_in[26];
    float* out = (float*)d_out;

    void* p;
#define SYM(v, s) cudaGetSymbolAddress(&p, s); auto* v = (decltype(&s[0]))p
    SYM(p_kvin_h, g_kvin_h);  SYM(p_kvin_l, g_kvin_l);
    SYM(p_xd_h, g_xd_h);      SYM(p_xd_l, g_xd_l);
    SYM(p_qe, g_qe); SYM(p_k, g_k); SYM(p_v, g_v);
    SYM(p_m, g_m); SYM(p_denom, g_denom); SYM(p_agg, g_agg);
    SYM(p_agg_h, g_agg_h);    SYM(p_agg_l, g_agg_l);
    SYM(p_rel_h, g_rel_h);    SYM(p_rel_l, g_rel_l);
    SYM(p_hbuf, g_hbuf);
    SYM(p_cat_h, g_cat_h);    SYM(p_cat_l, g_cat_l);
    SYM(p_pth_h, g_pth_h);    SYM(p_pth_l, g_pth_l);
    SYM(p_stacked, g_stacked);
    SYM(p_stk_h, g_stk_h);    SYM(p_stk_l, g_stk_l);
    SYM(p_t, g_t);
    SYM(p_wqt_h, g_wqt_h);    SYM(p_wqt_l, g_wqt_l);
    SYM(p_wkt_h, g_wkt_h);    SYM(p_wkt_l, g_wkt_l);
    SYM(p_wvt_h, g_wvt_h);    SYM(p_wvt_l, g_wvt_l);
    SYM(p_wmt_h, g_wmt_h);    SYM(p_wmt_l, g_wmt_l);
    SYM(p_wir1t_h, g_wir1t_h); SYM(p_wir1t_l, g_wir1t_l);
    SYM(p_wmpt_h, g_wmpt_h);  SYM(p_wmpt_l, g_wmpt_l);
    SYM(p_wa1t_h, g_wa1t_h);  SYM(p_wa1t_l, g_wa1t_l);
    SYM(p_wct_h, g_wct_h);    SYM(p_wct_l, g_wct_l);
#undef SYM

    const int SM256 = 1024 + 2 * (16384 + 256 * 128);  // 99328 (tcgen05 path)
    const int SM128 = 1024 + 2 * (16384 + 128 * 128);  // 66560
    cudaFuncSetAttribute((const void*)&tcmm<256, 0, 0>, cudaFuncAttributeMaxDynamicSharedMemorySize, SM256);
    cudaFuncSetAttribute((const void*)&tcmm<256, 1, 2>, cudaFuncAttributeMaxDynamicSharedMemorySize, SM256);
    cudaFuncSetAttribute((const void*)&tcmm<256, 1, 0>, cudaFuncAttributeMaxDynamicSharedMemorySize, SM256);
    cudaFuncSetAttribute((const void*)&tcmm<256, 0, 1>, cudaFuncAttributeMaxDynamicSharedMemorySize, SM256);
    cudaFuncSetAttribute((const void*)&tcmm<128, 2, 0>, cudaFuncAttributeMaxDynamicSharedMemorySize, SM128);

    const int TB = 256;
    bf16* nb16 = nullptr;

    // ---- weight transposes + splits ----
    for (int r = 0; r < RR; r++) {
        tsplit<<<(HH * HH + TB - 1) / TB, TB>>>(Wq + (size_t)r * HH * HH,
            p_wqt_h + (size_t)r * HH * HH, p_wqt_l + (size_t)r * HH * HH, HH, HH, HH);
        tsplit<<<(HH * KVP + TB - 1) / TB, TB>>>(Wk + (size_t)r * KVO * HH,
            p_wkt_h + (size_t)r * HH * KVP, p_wkt_l + (size_t)r * HH * KVP, KVO, HH, KVP);
        tsplit<<<(HH * KVP + TB - 1) / TB, TB>>>(Wv + (size_t)r * KVO * HH,
            p_wvt_h + (size_t)r * HH * KVP, p_wvt_l + (size_t)r * HH * KVP, KVO, HH, KVP);
        tsplit<<<(HH * HH + TB - 1) / TB, TB>>>(Wm + (size_t)r * HH * HH,
            p_wmt_h + (size_t)r * HH * HH, p_wmt_l + (size_t)r * HH * HH, HH, HH, HH);
    }
    tsplit<<<(HH * RH + TB - 1) / TB, TB>>>(W_ir1, p_wir1t_h, p_wir1t_l, RH, HH, RH);
    for (int pp = 0; pp < 3; pp++)
        tsplit<<<(HH * HH + TB - 1) / TB, TB>>>(Wmp + (size_t)pp * HH * HH,
            p_wmpt_h + (size_t)pp * HH * HH, p_wmpt_l + (size_t)pp * HH * HH, HH, HH, HH);
    tsplit<<<((HH / 2) * HH + TB - 1) / TB, TB>>>(Wa1, p_wa1t_h, p_wa1t_l, HH, HH / 2, HH);
    tsplit<<<(HH * 2 * HH + TB - 1) / TB, TB>>>(Wc, p_wct_h, p_wct_l, 2 * HH, HH, 2 * HH);

    // ---- per-relation message passing ----
    for (int r = 0; r < RR; r++) {
        fill_kernel<<<(NN * NHD + TB - 1) / TB, TB>>>(p_m, NN * NHD, -INFINITY);
        fill_kernel<<<(NN * NHD + TB - 1) / TB, TB>>>(p_denom, NN * NHD, 0.f);
        fill_kernel<<<(NN * HH + TB - 1) / TB, TB>>>(p_agg, NN * HH, 0.f);
        gather_split<<<(EE * (KVP + HH) + TB - 1) / TB, TB>>>(x, ei, ea, r);
        tcmm<256, 0, 0><<<EE / 128, 128, SM256>>>(p_xd_h, p_xd_l,
            p_wqt_h + (size_t)r * HH * HH, p_wqt_l + (size_t)r * HH * HH,
            bq + r * HH, p_qe, HH, 0, nb16, nb16, 0, 0, EE, HH);
        tcmm<256, 0, 0><<<EE / 128, 128, SM256>>>(p_kvin_h, p_kvin_l,
            p_wkt_h + (size_t)r * HH * KVP, p_wkt_l + (size_t)r * HH * KVP,
            bk + r * HH, p_k, HH, 0, nb16, nb16, 0, 0, EE, KVP);
        tcmm<256, 0, 0><<<EE / 128, 128, SM256>>>(p_kvin_h, p_kvin_l,
            p_wvt_h + (size_t)r * HH * KVP, p_wvt_l + (size_t)r * HH * KVP,
            bv + r * HH, p_v, HH, 0, nb16, nb16, 0, 0, EE, KVP);
        scores_kernel<<<EE * NHD / TB, TB>>>(ei, prior, r);
        ex_kernel<<<EE * NHD / TB, TB>>>(ei, r);
        agg_kernel<<<EE * HH / TB, TB>>>(ei, r);
        agg_split_kernel<<<(NN * HH + TB - 1) / TB, TB>>>();
        tcmm<256, 1, 2><<<NP / 128, 128, SM256>>>(p_agg_h, p_agg_l,
            p_wmt_h + (size_t)r * HH * HH, p_wmt_l + (size_t)r * HH * HH,
            bm + r * HH, (float*)nullptr, 0, 0, p_rel_h, p_rel_l, RH, r * HH, NN, HH);
    }

    // ---- inter-relation attention ----
    tcmm<256, 1, 0><<<NP / 128, 128, SM256>>>(p_rel_h, p_rel_l, p_wir1t_h, p_wir1t_l,
        b_ir1, p_hbuf, HH, 0, nb16, nb16, 0, 0, NN, RH);
    interw_kernel<<<(NN * 32 + TB - 1) / TB, TB>>>(W_ir2, b_ir2);
    interagg_kernel<<<(NN * HH + TB - 1) / TB, TB>>>();

    // ---- meta paths ----
    paths_kernel<<<(NN * HH + TB - 1) / TB, TB>>>();
    for (int pp = 0; pp < 3; pp++)
        tcmm<256, 0, 1><<<NP / 128, 128, SM256>>>(
            p_pth_h + (size_t)pp * NP * HH, p_pth_l + (size_t)pp * NP * HH,
            p_wmpt_h + (size_t)pp * HH * HH, p_wmpt_l + (size_t)pp * HH * HH,
            bmp + pp * HH, p_stacked, 3 * HH, pp * HH,
            p_stk_h, p_stk_l, 3 * HH, pp * HH, NN, HH);
    tcmm<128, 2, 0><<<(3 * NN + 127) / 128, 128, SM128>>>(p_stk_h, p_stk_l,
        p_wa1t_h, p_wa1t_l, ba1, p_t, HH / 2, 0, nb16, nb16, 0, 0, 3 * NN, HH);
    attnmeta_kernel<<<NN, TB>>>(Wa2, gmeta, bmeta);

    // ---- combine + output LN ----
    tcmm<256, 1, 0><<<NP / 128, 128, SM256>>>(p_cat_h, p_cat_l, p_wct_h, p_wct_l,
        bc, p_hbuf, HH, 0, nb16, nb16, 0, 0, NN, 2 * HH);
    outln_kernel<<<NN, TB>>>(x, gout, bout, out);
}

// round 5
// speedup vs baseline: 1.1530x; 1.1530x over previous
#include <cuda_runtime.h>
#include <cuda_bf16.h>
#include <math.h>
#include <stdint.h>

#define NN 50000
#define NP 50048          // NN padded to 128 (391*128)
#define RR 6
#define EE 32768
#define HH 256
#define FF 16
#define KVO 272
#define KVP 320           // 272 padded to 64-multiple
#define NHD 8
#define HDD 32
#define RH 1536

typedef __nv_bfloat16 bf16;

#if defined(__CUDA_ARCH__) && defined(__CUDA_ARCH_FEAT_SM103_ALL)
#define HAS_TC05 1
#else
#define HAS_TC05 0
#endif

// ---------------- scratch (device globals; zero-initialized at load) ----------------
__device__ __align__(1024) bf16 g_kvin_h[EE * KVP], g_kvin_l[EE * KVP];
__device__ __align__(1024) bf16 g_xd_h[EE * HH],   g_xd_l[EE * HH];
__device__ float g_qe[EE * HH], g_k[EE * HH], g_v[EE * HH];
__device__ float g_sc[EE * NHD], g_m[NN * NHD], g_denom[NN * NHD];
__device__ float g_agg[NN * HH];
__device__ __align__(1024) bf16 g_agg_h[NP * HH], g_agg_l[NP * HH];
__device__ __align__(1024) bf16 g_rel_h[NP * RH], g_rel_l[NP * RH];
__device__ float g_hbuf[NP * HH];
__device__ float g_interw[NN * NHD];
__device__ __align__(1024) bf16 g_cat_h[NP * 2 * HH], g_cat_l[NP * 2 * HH];
__device__ __align__(1024) bf16 g_pth_h[3 * NP * HH], g_pth_l[3 * NP * HH];
__device__ float g_stacked[NP * 3 * HH];
__device__ __align__(1024) bf16 g_stk_h[NP * 3 * HH], g_stk_l[NP * 3 * HH];
__device__ float g_t[3 * NP * (HH / 2)];
// transposed + split weights: [Ncol][Kpad]
__device__ __align__(1024) bf16 g_wqt_h[RR * HH * HH],  g_wqt_l[RR * HH * HH];
__device__ __align__(1024) bf16 g_wkt_h[RR * HH * KVP], g_wkt_l[RR * HH * KVP];
__device__ __align__(1024) bf16 g_wvt_h[RR * HH * KVP], g_wvt_l[RR * HH * KVP];
__device__ __align__(1024) bf16 g_wmt_h[RR * HH * HH],  g_wmt_l[RR * HH * HH];
__device__ __align__(1024) bf16 g_wir1t_h[HH * RH],     g_wir1t_l[HH * RH];
__device__ __align__(1024) bf16 g_wmpt_h[3 * HH * HH],  g_wmpt_l[3 * HH * HH];
__device__ __align__(1024) bf16 g_wa1t_h[(HH/2) * HH],  g_wa1t_l[(HH/2) * HH];
__device__ __align__(1024) bf16 g_wct_h[HH * 2 * HH],   g_wct_l[HH * 2 * HH];

// ---------------- common helpers ----------------
__device__ __forceinline__ float gelu_exact(float x) {
    return 0.5f * x * (1.0f + erff(x * 0.7071067811865475f));
}
__device__ __forceinline__ void split_store(float v, bf16* ph, bf16* pl) {
    bf16 h = __float2bfloat16(v);
    *ph = h;
    *pl = __float2bfloat16(v - __bfloat162float(h));
}
__device__ __forceinline__ void atomicMaxF(float* addr, float v) {
    int* ai = (int*)addr;
    int old = *ai;
    while (__int_as_float(old) < v) {
        int assumed = old;
        old = atomicCAS(ai, assumed, __float_as_int(v));
        if (old == assumed) break;
    }
}
__device__ __forceinline__ uint32_t smem_u32(const void* p) {
    uint32_t a;
    asm("{ .reg .u64 t; cvta.to.shared.u64 t, %1; cvt.u32.u64 %0, t; }" : "=r"(a) : "l"(p));
    return a;
}
#define CP_ASYNC16(dst, src) \
    asm volatile("cp.async.cg.shared.global [%0], [%1], 16;" :: "r"(dst), "l"(src))
#define CP_COMMIT() asm volatile("cp.async.commit_group;")
#define CP_WAIT1()  asm volatile("cp.async.wait_group 1;")
#define CP_WAIT0()  asm volatile("cp.async.wait_group 0;")

#if HAS_TC05
// ---------------- tcgen05-only PTX helpers ----------------
#define SWZ128(o) ((o) ^ (((o) >> 3) & 0x70))

__device__ __forceinline__ uint64_t mkdesc(uint32_t addr) {
    return ((uint64_t)2 << 61) | ((uint64_t)1 << 46) | ((uint64_t)64 << 32) |
           ((uint64_t)1 << 16) | ((addr >> 4) & 0x3FFF);
}
__device__ __forceinline__ void mma_f16_ss(uint32_t d, uint64_t ad, uint64_t bd,
                                           uint32_t idesc, bool acc) {
    uint32_t en = acc ? 1u : 0u;
    asm volatile(
        "{\n\t.reg .pred p;\n\tsetp.ne.u32 p, %5, 0;\n\t"
        "tcgen05.mma.cta_group::1.kind::f16 [%0], %1, %2, %3, {%4,%4,%4,%4}, p;\n\t}"
        :: "r"(d), "l"(ad), "l"(bd), "r"(idesc), "r"(0u), "r"(en) : "memory");
}
__device__ __forceinline__ void mbar_init(uint32_t mb, uint32_t cnt) {
    asm volatile("mbarrier.init.shared.b64 [%0], %1;" :: "r"(mb), "r"(cnt) : "memory");
}
__device__ __forceinline__ void mbar_wait(uint32_t mb, int parity) {
    asm volatile(
        "{\n\t.reg .pred P1;\n\t"
        "WL_%=:\n\t"
        "mbarrier.try_wait.parity.acquire.cta.shared::cta.b64 P1, [%0], %1, 0x989680;\n\t"
        "@P1 bra.uni WD_%=;\n\t"
        "bra.uni WL_%=;\n\t"
        "WD_%=:\n\t}"
        :: "r"(mb), "r"(parity) : "memory");
}
#define LDTM_X32(r, a) \
    asm volatile( \
        "tcgen05.ld.sync.aligned.32x32b.x32.b32 " \
        "{%0, %1, %2, %3, %4, %5, %6, %7, " \
        " %8, %9, %10, %11, %12, %13, %14, %15, " \
        " %16, %17, %18, %19, %20, %21, %22, %23, " \
        " %24, %25, %26, %27, %28, %29, %30, %31}, [%32];" \
        : "=r"((r)[0]),  "=r"((r)[1]),  "=r"((r)[2]),  "=r"((r)[3]), \
          "=r"((r)[4]),  "=r"((r)[5]),  "=r"((r)[6]),  "=r"((r)[7]), \
          "=r"((r)[8]),  "=r"((r)[9]),  "=r"((r)[10]), "=r"((r)[11]), \
          "=r"((r)[12]), "=r"((r)[13]), "=r"((r)[14]), "=r"((r)[15]), \
          "=r"((r)[16]), "=r"((r)[17]), "=r"((r)[18]), "=r"((r)[19]), \
          "=r"((r)[20]), "=r"((r)[21]), "=r"((r)[22]), "=r"((r)[23]), \
          "=r"((r)[24]), "=r"((r)[25]), "=r"((r)[26]), "=r"((r)[27]), \
          "=r"((r)[28]), "=r"((r)[29]), "=r"((r)[30]), "=r"((r)[31]) \
        : "r"(a))
#else
// mma.sync helper (valid on any sm_80+ target)
__device__ __forceinline__ void hmma16816(float* c, const uint32_t* a, const uint32_t* b) {
    asm volatile(
        "mma.sync.aligned.m16n8k16.row.col.f32.bf16.bf16.f32 "
        "{%0,%1,%2,%3}, {%4,%5,%6,%7}, {%8,%9}, {%0,%1,%2,%3};"
        : "+f"(c[0]), "+f"(c[1]), "+f"(c[2]), "+f"(c[3])
        : "r"(a[0]), "r"(a[1]), "r"(a[2]), "r"(a[3]), "r"(b[0]), "r"(b[1]));
}
#endif

// ---------------- bf16x3 GEMM ----------------
// Block tile 128x128 at (m0, n0) = (blockIdx.y*128, blockIdx.x*128).
// C[m, coff+n] = act( sum_k (Ah+Al)[m,k]*(Bh+Bl)[n,k] + bias[n] )  via AhBh+AhBl+AlBh.
// A: [M,K] bf16 row-major (hi,lo). B: [Ncols,K] bf16 row-major (weights pre-transposed).
// STORE: 0 = fp32 C only; 1 = fp32 C + bf16 hi/lo; 2 = bf16 hi/lo only.
template <int ACT, int STORE>
__global__ __launch_bounds__(256)
void tcmm(const bf16* __restrict__ Ah, const bf16* __restrict__ Al,
          const bf16* __restrict__ Bh, const bf16* __restrict__ Bl,
          const float* __restrict__ bias,
          float* __restrict__ C, int ldc, int coff,
          bf16* __restrict__ Ch, bf16* __restrict__ Cl, int ldh, int offh,
          int M, int K) {
    extern __shared__ char smem[];
    const int tid = threadIdx.x, wid = tid >> 5, lid = tid & 31;
    const int m0 = blockIdx.y * 128;
    const int n0 = blockIdx.x * 128;
    const int KC32 = K >> 5;

#if HAS_TC05
    // ================= tcgen05 path =================
    const uint32_t sb = smem_u32(smem);
    const int ABYTES = 128 * 128;       // 16 KB (128 rows x 64 bf16, SW128)
    const int BBYTES = 128 * 128;       // 16 KB (128 cols x 64 bf16)
    const int BUF = ABYTES + BBYTES;
    const uint32_t mbar0 = sb + 8, mbar1 = sb + 16;
    const uint32_t buf0 = sb + 1024;

    if (wid == 0) {
        asm volatile("tcgen05.alloc.cta_group::1.sync.aligned.shared::cta.b32 [%0], %1;"
                     :: "r"(sb), "r"(128u) : "memory");
        asm volatile("tcgen05.relinquish_alloc_permit.cta_group::1.sync.aligned;");
    }
    __syncthreads();
    uint32_t tmem;
    asm volatile("ld.shared.b32 %0, [%1];" : "=r"(tmem) : "r"(sb));
    if (tid == 0) { mbar_init(mbar0, 1); mbar_init(mbar1, 1); }
    __syncthreads();

    const int KC = K >> 6;
    const int T = KC * 3;
    const uint32_t idesc64 = (1u << 4) | (1u << 7) | (1u << 10) | (8u << 17) | (8u << 24);

    auto load_chunk = [&](int c, uint32_t bufbase) {
        int p = c / KC, kc = (c - p * KC) << 6;
        const bf16* Ap = (p == 2) ? Al : Ah;
        const bf16* Bp = (p == 1) ? Bl : Bh;
        for (int i = tid; i < 2048; i += 256) {
            uint32_t dst;
            const bf16* src;
            if (i < 1024) {
                int r = i >> 3, g = i & 7;
                dst = bufbase + SWZ128(r * 128 + g * 16);
                src = Ap + (size_t)(m0 + r) * K + kc + g * 8;
            } else {
                int j = i - 1024;
                int r = j >> 3, g = j & 7;
                dst = bufbase + ABYTES + SWZ128(r * 128 + g * 16);
                src = Bp + (size_t)(n0 + r) * K + kc + g * 8;
            }
            CP_ASYNC16(dst, src);
        }
        CP_COMMIT();
    };

    int ph0 = 0, ph1 = 0;
    load_chunk(0, buf0);
    for (int c = 0; c < T; c++) {
        int b = c & 1;
        if (c + 1 < T) {
            int nb = b ^ 1;
            if (c >= 1) {
                if (nb) { mbar_wait(mbar1, ph1); ph1 ^= 1; }
                else    { mbar_wait(mbar0, ph0); ph0 ^= 1; }
            }
            load_chunk(c + 1, buf0 + nb * BUF);
            CP_WAIT1();
        } else {
            CP_WAIT0();
        }
        __syncthreads();
        if (tid == 0) {
            asm volatile("fence.proxy.async.shared::cta;" ::: "memory");
            uint64_t ad = mkdesc(buf0 + b * BUF);
            uint64_t bd = mkdesc(buf0 + b * BUF + ABYTES);
#pragma unroll
            for (int ks = 0; ks < 4; ks++)
#pragma unroll
                for (int ns = 0; ns < 2; ns++)
                    mma_f16_ss(tmem + ns * 64, ad + ks * 2, bd + ns * 512 + ks * 2,
                               idesc64, (c > 0) || (ks > 0));
            asm volatile("tcgen05.commit.cta_group::1.mbarrier::arrive::one.shared::cluster.b64 [%0];"
                         :: "r"(b ? mbar1 : mbar0) : "memory");
        }
    }
    {
        int lb = (T - 1) & 1;
        if (lb) mbar_wait(mbar1, ph1); else mbar_wait(mbar0, ph0);
    }
    asm volatile("tcgen05.fence::after_thread_sync;" ::: "memory");

    // epilogue: warps 0-3 cols 0-63, warps 4-7 cols 64-127; rows by subpartition
    {
        int row = m0 + (wid & 3) * 32 + lid;
        int colbase = (wid >> 2) * 64;
        for (int cb = 0; cb < 64; cb += 32) {
            uint32_t regs[32];
            LDTM_X32(regs, tmem + colbase + cb);
            asm volatile("tcgen05.wait::ld.sync.aligned;" ::: "memory");
            if (row < M) {
#pragma unroll
                for (int j = 0; j < 32; j++) {
                    int col = n0 + colbase + cb + j;
                    float v = __uint_as_float(regs[j]) + bias[col];
                    if (ACT == 1) v = gelu_exact(v);
                    else if (ACT == 2) v = tanhf(v);
                    if (STORE != 2) C[(size_t)row * ldc + coff + col] = v;
                    if (STORE != 0)
                        split_store(v, Ch + (size_t)row * ldh + offh + col,
                                       Cl + (size_t)row * ldh + offh + col);
                }
            }
        }
    }
    __syncthreads();
    if (wid == 0)
        asm volatile("tcgen05.dealloc.cta_group::1.sync.aligned.b32 %0, %1;"
                     :: "r"(tmem), "r"(128u));

#else
    // ================= pipelined mma.sync (HMMA) path =================
    // 8 warps in 2x4: warp tile 64x32. cp.async double-buffered 32-K slabs.
    const int STG = 128 * 40 * 2;            // bytes per operand stage (rows x 40 bf16)
    bf16* Asm = (bf16*)smem;                 // [2][128][40]
    bf16* Bsm = (bf16*)(smem + 2 * STG);     // [2][128][40]
    const uint32_t Asm_u = smem_u32(Asm), Bsm_u = smem_u32(Bsm);
    const int g = lid >> 2, tig = lid & 3;
    const int wr = wid >> 2, wc = wid & 3;
    const int rowbase = wr * 64, colbase = wc * 32;

    const int S = KC32 * 3;

    auto load_stage = [&](int s, int buf) {
        int p = s / KC32, k0 = (s - p * KC32) << 5;
        const bf16* Ap = (p == 2) ? Al : Ah;
        const bf16* Bp = (p == 1) ? Bl : Bh;
        uint32_t ab = Asm_u + buf * STG, bb = Bsm_u + buf * STG;
#pragma unroll
        for (int rep = 0; rep < 2; rep++) {
            int i = tid + 256 * rep;
            int r = i >> 2, sc = i & 3;
            CP_ASYNC16(ab + r * 80 + sc * 16, Ap + (size_t)(m0 + r) * K + k0 + sc * 8);
        }
#pragma unroll
        for (int rep = 0; rep < 2; rep++) {
            int i = tid + 256 * rep;
            int r = i >> 2, sc = i & 3;
            CP_ASYNC16(bb + r * 80 + sc * 16, Bp + (size_t)(n0 + r) * K + k0 + sc * 8);
        }
        CP_COMMIT();
    };

    float acc[4][4][4];
#pragma unroll
    for (int mf = 0; mf < 4; mf++)
#pragma unroll
        for (int nf = 0; nf < 4; nf++)
#pragma unroll
            for (int q = 0; q < 4; q++) acc[mf][nf][q] = 0.f;

    load_stage(0, 0);
    for (int s = 0; s < S; s++) {
        int b = s & 1;
        if (s + 1 < S) { load_stage(s + 1, b ^ 1); CP_WAIT1(); }
        else CP_WAIT0();
        __syncthreads();
        const bf16* As = Asm + b * 128 * 40;
        const bf16* Bs = Bsm + b * 128 * 40;
#pragma unroll
        for (int kk = 0; kk < 32; kk += 16) {
            uint32_t afr[4][4], bfr[4][2];
#pragma unroll
            for (int mf = 0; mf < 4; mf++) {
                int rb = rowbase + mf * 16;
                afr[mf][0] = *(const uint32_t*)(As + (rb + g) * 40 + kk + 2 * tig);
                afr[mf][1] = *(const uint32_t*)(As + (rb + g + 8) * 40 + kk + 2 * tig);
                afr[mf][2] = *(const uint32_t*)(As + (rb + g) * 40 + kk + 2 * tig + 8);
                afr[mf][3] = *(const uint32_t*)(As + (rb + g + 8) * 40 + kk + 2 * tig + 8);
            }
#pragma unroll
            for (int nf = 0; nf < 4; nf++) {
                int nb_ = colbase + nf * 8;
                bfr[nf][0] = *(const uint32_t*)(Bs + (nb_ + g) * 40 + kk + 2 * tig);
                bfr[nf][1] = *(const uint32_t*)(Bs + (nb_ + g) * 40 + kk + 2 * tig + 8);
            }
#pragma unroll
            for (int mf = 0; mf < 4; mf++)
#pragma unroll
                for (int nf = 0; nf < 4; nf++)
                    hmma16816(acc[mf][nf], afr[mf], bfr[nf]);
        }
        __syncthreads();
    }

    // epilogue
#pragma unroll
    for (int mf = 0; mf < 4; mf++)
#pragma unroll
        for (int nf = 0; nf < 4; nf++) {
            int col0 = n0 + colbase + nf * 8 + 2 * tig;
#pragma unroll
            for (int r8 = 0; r8 < 2; r8++) {
                int row = m0 + rowbase + mf * 16 + g + r8 * 8;
                if (row < M) {
#pragma unroll
                    for (int cc = 0; cc < 2; cc++) {
                        int col = col0 + cc;
                        float v = acc[mf][nf][r8 * 2 + cc] + bias[col];
                        if (ACT == 1) v = gelu_exact(v);
                        else if (ACT == 2) v = tanhf(v);
                        if (STORE != 2) C[(size_t)row * ldc + coff + col] = v;
                        if (STORE != 0)
                            split_store(v, Ch + (size_t)row * ldh + offh + col,
                                           Cl + (size_t)row * ldh + offh + col);
                    }
                }
            }
        }
#endif
}

// ---------------- conversion / small kernels ----------------
__global__ void tsplit(const float* __restrict__ W, bf16* __restrict__ oh,
                       bf16* __restrict__ ol, int Kin, int Ncol, int Kpad) {
    int idx = blockIdx.x * blockDim.x + threadIdx.x;
    if (idx >= Ncol * Kpad) return;
    int n = idx / Kpad, k = idx - n * Kpad;
    float v = (k < Kin) ? W[(size_t)k * Ncol + n] : 0.f;
    split_store(v, oh + idx, ol + idx);
}

__global__ void fill_kernel(float* p, int n, float v) {
    int i = blockIdx.x * blockDim.x + threadIdx.x;
    if (i < n) p[i] = v;
}

__global__ void gather_split(const float* __restrict__ x, const int* __restrict__ ei,
                             const float* __restrict__ ea, int r) {
    int idx = blockIdx.x * blockDim.x + threadIdx.x;
    const int tot1 = EE * KVP;
    if (idx < tot1) {
        int e = idx / KVP, c = idx - e * KVP;
        int src = ei[(r * 2 + 0) * EE + e];
        float v = (c < HH) ? x[src * HH + c]
                : ((c < KVO) ? ea[((size_t)r * EE + e) * FF + (c - HH)] : 0.f);
        split_store(v, g_kvin_h + idx, g_kvin_l + idx);
    } else {
        int j = idx - tot1;
        if (j < EE * HH) {
            int e = j >> 8, c = j & 255;
            int dst = ei[(r * 2 + 1) * EE + e];
            split_store(x[dst * HH + c], g_xd_h + j, g_xd_l + j);
        }
    }
}

__global__ void scores_kernel(const int* __restrict__ ei, const float* __restrict__ prior, int r) {
    int idx = blockIdx.x * blockDim.x + threadIdx.x;
    if (idx >= EE * NHD) return;
    int e = idx >> 3, h = idx & 7;
    const float* qp = g_qe + e * HH + h * HDD;
    const float* kp = g_k + e * HH + h * HDD;
    float s = 0.f;
#pragma unroll
    for (int d = 0; d < HDD; d++) s += qp[d] * kp[d];
    s *= 0.17677669529663687f * prior[r * NHD + h];
    g_sc[idx] = s;
    int dst = ei[(r * 2 + 1) * EE + e];
    atomicMaxF(&g_m[dst * NHD + h], s);
}

__global__ void ex_kernel(const int* __restrict__ ei, int r) {
    int idx = blockIdx.x * blockDim.x + threadIdx.x;
    if (idx >= EE * NHD) return;
    int e = idx >> 3, h = idx & 7;
    int dst = ei[(r * 2 + 1) * EE + e];
    float exv = expf(g_sc[idx] - g_m[dst * NHD + h]);
    g_sc[idx] = exv;
    atomicAdd(&g_denom[dst * NHD + h], exv);
}

__global__ void agg_kernel(const int* __restrict__ ei, int r) {
    int idx = blockIdx.x * blockDim.x + threadIdx.x;
    if (idx >= EE * HH) return;
    int e = idx >> 8, c = idx & 255;
    int h = c >> 5;
    int dst = ei[(r * 2 + 1) * EE + e];
    float w = g_sc[e * NHD + h] / (g_denom[dst * NHD + h] + 1e-16f);
    atomicAdd(&g_agg[dst * HH + c], w * g_v[idx]);
}

__global__ void agg_split_kernel() {
    int idx = blockIdx.x * blockDim.x + threadIdx.x;
    if (idx >= NN * HH) return;
    split_store(g_agg[idx], g_agg_h + idx, g_agg_l + idx);
}

__global__ void interw_kernel(const float* __restrict__ Wir2, const float* __restrict__ bir2) {
    int gwarp = (blockIdx.x * blockDim.x + threadIdx.x) >> 5;
    int lane = threadIdx.x & 31;
    if (gwarp >= NN) return;
    float acc[RR] = {};
    for (int k = lane; k < HH; k += 32) {
        float hv = g_hbuf[gwarp * HH + k];
#pragma unroll
        for (int rr = 0; rr < RR; rr++) acc[rr] += hv * Wir2[k * RR + rr];
    }
#pragma unroll
    for (int rr = 0; rr < RR; rr++)
#pragma unroll
        for (int off = 16; off; off >>= 1)
            acc[rr] += __shfl_down_sync(0xffffffff, acc[rr], off);
    if (lane == 0) {
        float mx = -1e30f;
#pragma unroll
        for (int rr = 0; rr < RR; rr++) { acc[rr] += bir2[rr]; mx = fmaxf(mx, acc[rr]); }
        float s = 0.f;
#pragma unroll
        for (int rr = 0; rr < RR; rr++) { acc[rr] = expf(acc[rr] - mx); s += acc[rr]; }
        float inv = 1.f / s;
#pragma unroll
        for (int rr = 0; rr < RR; rr++) g_interw[gwarp * NHD + rr] = acc[rr] * inv;
    }
}

__global__ void interagg_kernel() {
    int idx = blockIdx.x * blockDim.x + threadIdx.x;
    if (idx >= NN * HH) return;
    int n = idx >> 8, c = idx & 255;
    float s = 0.f;
#pragma unroll
    for (int rr = 0; rr < RR; rr++) {
        size_t b = (size_t)n * RH + rr * HH + c;
        s += g_interw[n * NHD + rr] *
             (__bfloat162float(g_rel_h[b]) + __bfloat162float(g_rel_l[b]));
    }
    split_store(s, g_cat_h + (size_t)n * 2 * HH + c, g_cat_l + (size_t)n * 2 * HH + c);
}

__global__ void paths_kernel() {
    int idx = blockIdx.x * blockDim.x + threadIdx.x;
    if (idx >= NN * HH) return;
    int n = idx >> 8, c = idx & 255;
    float v[RR];
#pragma unroll
    for (int rr = 0; rr < RR; rr++) {
        size_t b = (size_t)n * RH + rr * HH + c;
        v[rr] = __bfloat162float(g_rel_h[b]) + __bfloat162float(g_rel_l[b]);
    }
    split_store(v[2] + v[3], g_pth_h + ((size_t)0 * NP + n) * HH + c, g_pth_l + ((size_t)0 * NP + n) * HH + c);
    split_store(v[4] + v[0], g_pth_h + ((size_t)1 * NP + n) * HH + c, g_pth_l + ((size_t)1 * NP + n) * HH + c);
    split_store(v[1] + v[5], g_pth_h + ((size_t)2 * NP + n) * HH + c, g_pth_l + ((size_t)2 * NP + n) * HH + c);
}

__global__ void attnmeta_kernel(const float* __restrict__ Wa2,
                                const float* __restrict__ gm, const float* __restrict__ bm_) {
    __shared__ float lg[3];
    __shared__ float rbuf[256];
    int n = blockIdx.x, t = threadIdx.x;
    int lane = t & 31, w = t >> 5;
    if (w < 3) {
        float a = 0.f;
        for (int j = lane; j < 128; j += 32)
            a += g_t[((size_t)n * 3 + w) * 128 + j] * Wa2[j];
#pragma unroll
        for (int off = 16; off; off >>= 1) a += __shfl_down_sync(0xffffffff, a, off);
        if (lane == 0) lg[w] = a;
    }
    __syncthreads();
    float l0 = lg[0], l1 = lg[1], l2 = lg[2];
    float mx = fmaxf(l0, fmaxf(l1, l2));
    float e0 = expf(l0 - mx), e1 = expf(l1 - mx), e2 = expf(l2 - mx);
    float inv = 1.f / (e0 + e1 + e2);
    const float* st = g_stacked + (size_t)n * 3 * HH;
    float s = (e0 * st[t] + e1 * st[HH + t] + e2 * st[2 * HH + t]) * inv;
    rbuf[t] = s;
    __syncthreads();
    for (int off = 128; off; off >>= 1) { if (t < off) rbuf[t] += rbuf[t + off]; __syncthreads(); }
    float mu = rbuf[0] * (1.f / 256.f);
    __syncthreads();
    float d = s - mu;
    rbuf[t] = d * d;
    __syncthreads();
    for (int off = 128; off; off >>= 1) { if (t < off) rbuf[t] += rbuf[t + off]; __syncthreads(); }
    float var = rbuf[0] * (1.f / 256.f);
    float o = d * rsqrtf(var + 1e-5f) * gm[t] + bm_[t];
    split_store(o, g_cat_h + (size_t)n * 2 * HH + HH + t, g_cat_l + (size_t)n * 2 * HH + HH + t);
}

__global__ void outln_kernel(const float* __restrict__ x, const float* __restrict__ gout,
                             const float* __restrict__ bout, float* __restrict__ out) {
    __shared__ float rbuf[256];
    int n = blockIdx.x, t = threadIdx.x;
    float v = x[(size_t)n * HH + t] + g_hbuf[(size_t)n * HH + t];
    rbuf[t] = v;
    __syncthreads();
    for (int off = 128; off; off >>= 1) { if (t < off) rbuf[t] += rbuf[t + off]; __syncthreads(); }
    float mu = rbuf[0] * (1.f / 256.f);
    __syncthreads();
    float d = v - mu;
    rbuf[t] = d * d;
    __syncthreads();
    for (int off = 128; off; off >>= 1) { if (t < off) rbuf[t] += rbuf[t + off]; __syncthreads(); }
    float var = rbuf[0] * (1.f / 256.f);
    out[(size_t)n * HH + t] = d * rsqrtf(var + 1e-5f) * gout[t] + bout[t];
}

// ---------------- host ----------------
extern "C" void kernel_launch(void* const* d_in, const int* in_sizes, int n_in,
                              void* d_out, int out_size) {
    const float* x     = (const float*)d_in[0];
    const int*   ei    = (const int*)d_in[1];
    const float* ea    = (const float*)d_in[2];
    const float* Wq    = (const float*)d_in[3];
    const float* bq    = (const float*)d_in[4];
    const float* Wk    = (const float*)d_in[5];
    const float* bk    = (const float*)d_in[6];
    const float* Wv    = (const float*)d_in[7];
    const float* bv    = (const float*)d_in[8];
    const float* prior = (const float*)d_in[9];
    const float* Wm    = (const float*)d_in[10];
    const float* bm    = (const float*)d_in[11];
    const float* W_ir1 = (const float*)d_in[12];
    const float* b_ir1 = (const float*)d_in[13];
    const float* W_ir2 = (const float*)d_in[14];
    const float* b_ir2 = (const float*)d_in[15];
    const float* Wmp   = (const float*)d_in[16];
    const float* bmp   = (const float*)d_in[17];
    const float* Wa1   = (const float*)d_in[18];
    const float* ba1   = (const float*)d_in[19];
    const float* Wa2   = (const float*)d_in[20];
    const float* gmeta = (const float*)d_in[21];
    const float* bmeta = (const float*)d_in[22];
    const float* Wc    = (const float*)d_in[23];
    const float* bc    = (const float*)d_in[24];
    const float* gout  = (const float*)d_in[25];
    const float* bout  = (const float*)d_in[26];
    float* out = (float*)d_out;

    void* p;
#define SYM(v, s) cudaGetSymbolAddress(&p, s); auto* v = (decltype(&s[0]))p
    SYM(p_kvin_h, g_kvin_h);  SYM(p_kvin_l, g_kvin_l);
    SYM(p_xd_h, g_xd_h);      SYM(p_xd_l, g_xd_l);
    SYM(p_qe, g_qe); SYM(p_k, g_k); SYM(p_v, g_v);
    SYM(p_m, g_m); SYM(p_denom, g_denom); SYM(p_agg, g_agg);
    SYM(p_agg_h, g_agg_h);    SYM(p_agg_l, g_agg_l);
    SYM(p_rel_h, g_rel_h);    SYM(p_rel_l, g_rel_l);
    SYM(p_hbuf, g_hbuf);
    SYM(p_cat_h, g_cat_h);    SYM(p_cat_l, g_cat_l);
    SYM(p_pth_h, g_pth_h);    SYM(p_pth_l, g_pth_l);
    SYM(p_stacked, g_stacked);
    SYM(p_stk_h, g_stk_h);    SYM(p_stk_l, g_stk_l);
    SYM(p_t, g_t);
    SYM(p_wqt_h, g_wqt_h);    SYM(p_wqt_l, g_wqt_l);
    SYM(p_wkt_h, g_wkt_h);    SYM(p_wkt_l, g_wkt_l);
    SYM(p_wvt_h, g_wvt_h);    SYM(p_wvt_l, g_wvt_l);
    SYM(p_wmt_h, g_wmt_h);    SYM(p_wmt_l, g_wmt_l);
    SYM(p_wir1t_h, g_wir1t_h); SYM(p_wir1t_l, g_wir1t_l);
    SYM(p_wmpt_h, g_wmpt_h);  SYM(p_wmpt_l, g_wmpt_l);
    SYM(p_wa1t_h, g_wa1t_h);  SYM(p_wa1t_l, g_wa1t_l);
    SYM(p_wct_h, g_wct_h);    SYM(p_wct_l, g_wct_l);
#undef SYM

    const int SMB = 66560;   // covers tcgen05 path (66560) and HMMA path (40960)
    cudaFuncSetAttribute((const void*)&tcmm<0, 0>, cudaFuncAttributeMaxDynamicSharedMemorySize, SMB);
    cudaFuncSetAttribute((const void*)&tcmm<1, 2>, cudaFuncAttributeMaxDynamicSharedMemorySize, SMB);
    cudaFuncSetAttribute((const void*)&tcmm<1, 0>, cudaFuncAttributeMaxDynamicSharedMemorySize, SMB);
    cudaFuncSetAttribute((const void*)&tcmm<0, 1>, cudaFuncAttributeMaxDynamicSharedMemorySize, SMB);
    cudaFuncSetAttribute((const void*)&tcmm<2, 0>, cudaFuncAttributeMaxDynamicSharedMemorySize, SMB);

    const int TB = 256;
    bf16* nb16 = nullptr;
    const dim3 gE(2, EE / 128);              // edges: N=256
    const dim3 gN(2, NP / 128);              // nodes: N=256
    const dim3 gA1(1, (3 * NN + 127) / 128); // Wa1: N=128

    // ---- weight transposes + splits ----
    for (int r = 0; r < RR; r++) {
        tsplit<<<(HH * HH + TB - 1) / TB, TB>>>(Wq + (size_t)r * HH * HH,
            p_wqt_h + (size_t)r * HH * HH, p_wqt_l + (size_t)r * HH * HH, HH, HH, HH);
        tsplit<<<(HH * KVP + TB - 1) / TB, TB>>>(Wk + (size_t)r * KVO * HH,
            p_wkt_h + (size_t)r * HH * KVP, p_wkt_l + (size_t)r * HH * KVP, KVO, HH, KVP);
        tsplit<<<(HH * KVP + TB - 1) / TB, TB>>>(Wv + (size_t)r * KVO * HH,
            p_wvt_h + (size_t)r * HH * KVP, p_wvt_l + (size_t)r * HH * KVP, KVO, HH, KVP);
        tsplit<<<(HH * HH + TB - 1) / TB, TB>>>(Wm + (size_t)r * HH * HH,
            p_wmt_h + (size_t)r * HH * HH, p_wmt_l + (size_t)r * HH * HH, HH, HH, HH);
    }
    tsplit<<<(HH * RH + TB - 1) / TB, TB>>>(W_ir1, p_wir1t_h, p_wir1t_l, RH, HH, RH);
    for (int pp = 0; pp < 3; pp++)
        tsplit<<<(HH * HH + TB - 1) / TB, TB>>>(Wmp + (size_t)pp * HH * HH,
            p_wmpt_h + (size_t)pp * HH * HH, p_wmpt_l + (size_t)pp * HH * HH, HH, HH, HH);
    tsplit<<<((HH / 2) * HH + TB - 1) / TB, TB>>>(Wa1, p_wa1t_h, p_wa1t_l, HH, HH / 2, HH);
    tsplit<<<(HH * 2 * HH + TB - 1) / TB, TB>>>(Wc, p_wct_h, p_wct_l, 2 * HH, HH, 2 * HH);

    // ---- per-relation message passing ----
    for (int r = 0; r < RR; r++) {
        fill_kernel<<<(NN * NHD + TB - 1) / TB, TB>>>(p_m, NN * NHD, -INFINITY);
        fill_kernel<<<(NN * NHD + TB - 1) / TB, TB>>>(p_denom, NN * NHD, 0.f);
        fill_kernel<<<(NN * HH + TB - 1) / TB, TB>>>(p_agg, NN * HH, 0.f);
        gather_split<<<(EE * (KVP + HH) + TB - 1) / TB, TB>>>(x, ei, ea, r);
        tcmm<0, 0><<<gE, 256, SMB>>>(p_xd_h, p_xd_l,
            p_wqt_h + (size_t)r * HH * HH, p_wqt_l + (size_t)r * HH * HH,
            bq + r * HH, p_qe, HH, 0, nb16, nb16, 0, 0, EE, HH);
        tcmm<0, 0><<<gE, 256, SMB>>>(p_kvin_h, p_kvin_l,
            p_wkt_h + (size_t)r * HH * KVP, p_wkt_l + (size_t)r * HH * KVP,
            bk + r * HH, p_k, HH, 0, nb16, nb16, 0, 0, EE, KVP);
        tcmm<0, 0><<<gE, 256, SMB>>>(p_kvin_h, p_kvin_l,
            p_wvt_h + (size_t)r * HH * KVP, p_wvt_l + (size_t)r * HH * KVP,
            bv + r * HH, p_v, HH, 0, nb16, nb16, 0, 0, EE, KVP);
        scores_kernel<<<EE * NHD / TB, TB>>>(ei, prior, r);
        ex_kernel<<<EE * NHD / TB, TB>>>(ei, r);
        agg_kernel<<<EE * HH / TB, TB>>>(ei, r);
        agg_split_kernel<<<(NN * HH + TB - 1) / TB, TB>>>();
        tcmm<1, 2><<<gN, 256, SMB>>>(p_agg_h, p_agg_l,
            p_wmt_h + (size_t)r * HH * HH, p_wmt_l + (size_t)r * HH * HH,
            bm + r * HH, (float*)nullptr, 0, 0, p_rel_h, p_rel_l, RH, r * HH, NN, HH);
    }

    // ---- inter-relation attention ----
    tcmm<1, 0><<<gN, 256, SMB>>>(p_rel_h, p_rel_l, p_wir1t_h, p_wir1t_l,
        b_ir1, p_hbuf, HH, 0, nb16, nb16, 0, 0, NN, RH);
    interw_kernel<<<(NN * 32 + TB - 1) / TB, TB>>>(W_ir2, b_ir2);
    interagg_kernel<<<(NN * HH + TB - 1) / TB, TB>>>();

    // ---- meta paths ----
    paths_kernel<<<(NN * HH + TB - 1) / TB, TB>>>();
    for (int pp = 0; pp < 3; pp++)
        tcmm<0, 1><<<gN, 256, SMB>>>(
            p_pth_h + (size_t)pp * NP * HH, p_pth_l + (size_t)pp * NP * HH,
            p_wmpt_h + (size_t)pp * HH * HH, p_wmpt_l + (size_t)pp * HH * HH,
            bmp + pp * HH, p_stacked, 3 * HH, pp * HH,
            p_stk_h, p_stk_l, 3 * HH, pp * HH, NN, HH);
    tcmm<2, 0><<<gA1, 256, SMB>>>(p_stk_h, p_stk_l,
        p_wa1t_h, p_wa1t_l, ba1, p_t, HH / 2, 0, nb16, nb16, 0, 0, 3 * NN, HH);
    attnmeta_kernel<<<NN, TB>>>(Wa2, gmeta, bmeta);

    // ---- combine + output LN ----
    tcmm<1, 0><<<gN, 256, SMB>>>(p_cat_h, p_cat_l, p_wct_h, p_wct_l,
        bc, p_hbuf, HH, 0, nb16, nb16, 0, 0, NN, 2 * HH);
    outln_kernel<<<NN, TB>>>(x, gout, bout, out);
}

// round 6
// speedup vs baseline: 1.2314x; 1.0679x over previous
#include <cuda_runtime.h>
#include <cuda_bf16.h>
#include <math.h>
#include <stdint.h>

#define NN 50000
#define NP 50048          // NN padded to 128
#define RR 6
#define EE 32768
#define HH 256
#define FF 16
#define KVO 272
#define KVP 320           // 272 padded to 64-multiple
#define NHD 8
#define HDD 32
#define RH 1536

typedef __nv_bfloat16 bf16;

#if defined(__CUDA_ARCH__) && (defined(__CUDA_ARCH_FEAT_SM103_ALL) \
    || (defined(__CUDA_ARCH_SPECIFIC__) && (__CUDA_ARCH_SPECIFIC__ == 1030)) \
    || (defined(__CUDA_ARCH_FAMILY_SPECIFIC__) && (__CUDA_ARCH_FAMILY_SPECIFIC__ == 1030)))
#define HAS_TC05 1
#else
#define HAS_TC05 0
#endif

// ---------------- scratch (device globals; zero-initialized at load) ----------------
// per-relation batched buffers
__device__ __align__(1024) bf16 g_kvin_h[RR * EE * KVP], g_kvin_l[RR * EE * KVP];
__device__ __align__(1024) bf16 g_xd_h[RR * EE * HH],   g_xd_l[RR * EE * HH];
__device__ float g_qe[(size_t)RR * EE * HH], g_k[(size_t)RR * EE * HH], g_v[(size_t)RR * EE * HH];
__device__ float g_sc[RR * EE * NHD], g_m[RR * NN * NHD], g_denom[RR * NN * NHD];
__device__ float g_agg[(size_t)RR * NN * HH];
__device__ __align__(1024) bf16 g_agg_h[(size_t)RR * NP * HH], g_agg_l[(size_t)RR * NP * HH];
__device__ __align__(1024) bf16 g_rel_h[(size_t)NP * RH], g_rel_l[(size_t)NP * RH];
__device__ float g_hbuf[NP * HH];
__device__ float g_interw[NN * NHD];
__device__ __align__(1024) bf16 g_cat_h[NP * 2 * HH], g_cat_l[NP * 2 * HH];
__device__ __align__(1024) bf16 g_pth_h[3 * NP * HH], g_pth_l[3 * NP * HH];
__device__ float g_stacked[NP * 3 * HH];
__device__ __align__(1024) bf16 g_stk_h[NP * 3 * HH], g_stk_l[NP * 3 * HH];
__device__ float g_t[3 * NP * (HH / 2)];
// transposed + split weights: [Ncol][Kpad]
__device__ __align__(1024) bf16 g_wqt_h[RR * HH * HH],  g_wqt_l[RR * HH * HH];
__device__ __align__(1024) bf16 g_wkt_h[RR * HH * KVP], g_wkt_l[RR * HH * KVP];
__device__ __align__(1024) bf16 g_wvt_h[RR * HH * KVP], g_wvt_l[RR * HH * KVP];
__device__ __align__(1024) bf16 g_wmt_h[RR * HH * HH],  g_wmt_l[RR * HH * HH];
__device__ __align__(1024) bf16 g_wir1t_h[HH * RH],     g_wir1t_l[HH * RH];
__device__ __align__(1024) bf16 g_wmpt_h[3 * HH * HH],  g_wmpt_l[3 * HH * HH];
__device__ __align__(1024) bf16 g_wa1t_h[(HH/2) * HH],  g_wa1t_l[(HH/2) * HH];
__device__ __align__(1024) bf16 g_wct_h[HH * 2 * HH],   g_wct_l[HH * 2 * HH];

// ---------------- common helpers ----------------
__device__ __forceinline__ float gelu_exact(float x) {
    return 0.5f * x * (1.0f + erff(x * 0.7071067811865475f));
}
__device__ __forceinline__ void split_store(float v, bf16* ph, bf16* pl) {
    bf16 h = __float2bfloat16(v);
    *ph = h;
    *pl = __float2bfloat16(v - __bfloat162float(h));
}
__device__ __forceinline__ void atomicMaxF(float* addr, float v) {
    int* ai = (int*)addr;
    int old = *ai;
    while (__int_as_float(old) < v) {
        int assumed = old;
        old = atomicCAS(ai, assumed, __float_as_int(v));
        if (old == assumed) break;
    }
}
__device__ __forceinline__ uint32_t smem_u32(const void* p) {
    uint32_t a;
    asm("{ .reg .u64 t; cvta.to.shared.u64 t, %1; cvt.u32.u64 %0, t; }" : "=r"(a) : "l"(p));
    return a;
}
#define CP_ASYNC16(dst, src) \
    asm volatile("cp.async.cg.shared.global [%0], [%1], 16;" :: "r"(dst), "l"(src))
#define CP_COMMIT() asm volatile("cp.async.commit_group;")
#define CP_WAIT2()  asm volatile("cp.async.wait_group 2;")
#define CP_WAIT1()  asm volatile("cp.async.wait_group 1;")
#define CP_WAIT0()  asm volatile("cp.async.wait_group 0;")

#if HAS_TC05
#define SWZ128(o) ((o) ^ (((o) >> 3) & 0x70))
__device__ __forceinline__ uint64_t mkdesc(uint32_t addr) {
    return ((uint64_t)2 << 61) | ((uint64_t)1 << 46) | ((uint64_t)64 << 32) |
           ((uint64_t)1 << 16) | ((addr >> 4) & 0x3FFF);
}
__device__ __forceinline__ void mma_f16_ss(uint32_t d, uint64_t ad, uint64_t bd,
                                           uint32_t idesc, bool acc) {
    uint32_t en = acc ? 1u : 0u;
    asm volatile(
        "{\n\t.reg .pred p;\n\tsetp.ne.u32 p, %5, 0;\n\t"
        "tcgen05.mma.cta_group::1.kind::f16 [%0], %1, %2, %3, {%4,%4,%4,%4}, p;\n\t}"
        :: "r"(d), "l"(ad), "l"(bd), "r"(idesc), "r"(0u), "r"(en) : "memory");
}
__device__ __forceinline__ void mbar_init(uint32_t mb, uint32_t cnt) {
    asm volatile("mbarrier.init.shared.b64 [%0], %1;" :: "r"(mb), "r"(cnt) : "memory");
}
__device__ __forceinline__ void mbar_wait(uint32_t mb, int parity) {
    asm volatile(
        "{\n\t.reg .pred P1;\n\t"
        "WL_%=:\n\t"
        "mbarrier.try_wait.parity.acquire.cta.shared::cta.b64 P1, [%0], %1, 0x989680;\n\t"
        "@P1 bra.uni WD_%=;\n\t"
        "bra.uni WL_%=;\n\t"
        "WD_%=:\n\t}"
        :: "r"(mb), "r"(parity) : "memory");
}
#define LDTM_X32(r, a) \
    asm volatile( \
        "tcgen05.ld.sync.aligned.32x32b.x32.b32 " \
        "{%0, %1, %2, %3, %4, %5, %6, %7, " \
        " %8, %9, %10, %11, %12, %13, %14, %15, " \
        " %16, %17, %18, %19, %20, %21, %22, %23, " \
        " %24, %25, %26, %27, %28, %29, %30, %31}, [%32];" \
        : "=r"((r)[0]),  "=r"((r)[1]),  "=r"((r)[2]),  "=r"((r)[3]), \
          "=r"((r)[4]),  "=r"((r)[5]),  "=r"((r)[6]),  "=r"((r)[7]), \
          "=r"((r)[8]),  "=r"((r)[9]),  "=r"((r)[10]), "=r"((r)[11]), \
          "=r"((r)[12]), "=r"((r)[13]), "=r"((r)[14]), "=r"((r)[15]), \
          "=r"((r)[16]), "=r"((r)[17]), "=r"((r)[18]), "=r"((r)[19]), \
          "=r"((r)[20]), "=r"((r)[21]), "=r"((r)[22]), "=r"((r)[23]), \
          "=r"((r)[24]), "=r"((r)[25]), "=r"((r)[26]), "=r"((r)[27]), \
          "=r"((r)[28]), "=r"((r)[29]), "=r"((r)[30]), "=r"((r)[31]) \
        : "r"(a))
#else
__device__ __forceinline__ void hmma16816(float* c, const uint32_t* a, const uint32_t* b) {
    asm volatile(
        "mma.sync.aligned.m16n8k16.row.col.f32.bf16.bf16.f32 "
        "{%0,%1,%2,%3}, {%4,%5,%6,%7}, {%8,%9}, {%0,%1,%2,%3};"
        : "+f"(c[0]), "+f"(c[1]), "+f"(c[2]), "+f"(c[3])
        : "r"(a[0]), "r"(a[1]), "r"(a[2]), "r"(a[3]), "r"(b[0]), "r"(b[1]));
}
#define LDSM_X4(r, addr) \
    asm volatile("ldmatrix.sync.aligned.m8n8.x4.shared.b16 {%0,%1,%2,%3}, [%4];" \
        : "=r"((r)[0]), "=r"((r)[1]), "=r"((r)[2]), "=r"((r)[3]) : "r"(addr))
#endif

// ---------------- bf16x3 GEMM (z-batched) ----------------
// Block tile 128x128 at (m0, n0); z = blockIdx.z selects batch slice.
// C[m, coff+n] = act( sum_k (Ah+Al)[m,k]*(Bh+Bl)[n,k] + bias[n] )  via AhBh+AhBl+AlBh.
// STORE: 0 = fp32 C only; 1 = fp32 C + bf16 hi/lo; 2 = bf16 hi/lo only.
template <int ACT, int STORE>
__global__ __launch_bounds__(256)
void tcmm(const bf16* __restrict__ Ah, const bf16* __restrict__ Al, long az,
          const bf16* __restrict__ Bh, const bf16* __restrict__ Bl, long bz,
          const float* __restrict__ bias, int biasz,
          float* __restrict__ C, int ldc, int coff, long cz, int coffz,
          bf16* __restrict__ Ch, bf16* __restrict__ Cl, int ldh, int offh,
          long chz, int offhz,
          int M, int K) {
    extern __shared__ char smem[];
    const int tid = threadIdx.x, wid = tid >> 5, lid = tid & 31;
    const int m0 = blockIdx.y * 128;
    const int n0 = blockIdx.x * 128;
    const int z = blockIdx.z;
    Ah += (size_t)z * az;  Al += (size_t)z * az;
    Bh += (size_t)z * bz;  Bl += (size_t)z * bz;
    bias += (size_t)z * biasz;
    if (STORE != 2) { C += (size_t)z * cz; coff += z * coffz; }
    if (STORE != 0) { Ch += (size_t)z * chz; Cl += (size_t)z * chz; offh += z * offhz; }

#if HAS_TC05
    // ================= tcgen05 path =================
    const uint32_t sb = smem_u32(smem);
    const int ABYTES = 128 * 128;
    const int BUF = 2 * ABYTES;
    const uint32_t mbar0 = sb + 8, mbar1 = sb + 16;
    const uint32_t buf0 = sb + 1024;

    if (wid == 0) {
        asm volatile("tcgen05.alloc.cta_group::1.sync.aligned.shared::cta.b32 [%0], %1;"
                     :: "r"(sb), "r"(128u) : "memory");
        asm volatile("tcgen05.relinquish_alloc_permit.cta_group::1.sync.aligned;");
    }
    __syncthreads();
    uint32_t tmem;
    asm volatile("ld.shared.b32 %0, [%1];" : "=r"(tmem) : "r"(sb));
    if (tid == 0) { mbar_init(mbar0, 1); mbar_init(mbar1, 1); }
    __syncthreads();

    const int KC = K >> 6;
    const int T = KC * 3;
    const uint32_t idesc64 = (1u << 4) | (1u << 7) | (1u << 10) | (8u << 17) | (8u << 24);

    auto load_chunk = [&](int c, uint32_t bufbase) {
        int p = c / KC, kc = (c - p * KC) << 6;
        const bf16* Ap = (p == 2) ? Al : Ah;
        const bf16* Bp = (p == 1) ? Bl : Bh;
        for (int i = tid; i < 2048; i += 256) {
            uint32_t dst;
            const bf16* src;
            if (i < 1024) {
                int r = i >> 3, g = i & 7;
                dst = bufbase + SWZ128(r * 128 + g * 16);
                src = Ap + (size_t)(m0 + r) * K + kc + g * 8;
            } else {
                int j = i - 1024;
                int r = j >> 3, g = j & 7;
                dst = bufbase + ABYTES + SWZ128(r * 128 + g * 16);
                src = Bp + (size_t)(n0 + r) * K + kc + g * 8;
            }
            CP_ASYNC16(dst, src);
        }
        CP_COMMIT();
    };

    int ph0 = 0, ph1 = 0;
    load_chunk(0, buf0);
    for (int c = 0; c < T; c++) {
        int b = c & 1;
        if (c + 1 < T) {
            int nb = b ^ 1;
            if (c >= 1) {
                if (nb) { mbar_wait(mbar1, ph1); ph1 ^= 1; }
                else    { mbar_wait(mbar0, ph0); ph0 ^= 1; }
            }
            load_chunk(c + 1, buf0 + nb * BUF);
            CP_WAIT1();
        } else {
            CP_WAIT0();
        }
        __syncthreads();
        if (tid == 0) {
            asm volatile("fence.proxy.async.shared::cta;" ::: "memory");
            uint64_t ad = mkdesc(buf0 + b * BUF);
            uint64_t bd = mkdesc(buf0 + b * BUF + ABYTES);
#pragma unroll
            for (int ks = 0; ks < 4; ks++)
#pragma unroll
                for (int ns = 0; ns < 2; ns++)
                    mma_f16_ss(tmem + ns * 64, ad + ks * 2, bd + ns * 512 + ks * 2,
                               idesc64, (c > 0) || (ks > 0));
            asm volatile("tcgen05.commit.cta_group::1.mbarrier::arrive::one.shared::cluster.b64 [%0];"
                         :: "r"(b ? mbar1 : mbar0) : "memory");
        }
    }
    {
        int lb = (T - 1) & 1;
        if (lb) mbar_wait(mbar1, ph1); else mbar_wait(mbar0, ph0);
    }
    asm volatile("tcgen05.fence::after_thread_sync;" ::: "memory");

    {
        int row = m0 + (wid & 3) * 32 + lid;
        int colbase = (wid >> 2) * 64;
        for (int cb = 0; cb < 64; cb += 32) {
            uint32_t regs[32];
            LDTM_X32(regs, tmem + colbase + cb);
            asm volatile("tcgen05.wait::ld.sync.aligned;" ::: "memory");
            if (row < M) {
#pragma unroll
                for (int j = 0; j < 32; j++) {
                    int col = n0 + colbase + cb + j;
                    float v = __uint_as_float(regs[j]) + bias[col];
                    if (ACT == 1) v = gelu_exact(v);
                    else if (ACT == 2) v = tanhf(v);
                    if (STORE != 2) C[(size_t)row * ldc + coff + col] = v;
                    if (STORE != 0)
                        split_store(v, Ch + (size_t)row * ldh + offh + col,
                                       Cl + (size_t)row * ldh + offh + col);
                }
            }
        }
    }
    __syncthreads();
    if (wid == 0)
        asm volatile("tcgen05.dealloc.cta_group::1.sync.aligned.b32 %0, %1;"
                     :: "r"(tmem), "r"(128u));

#else
    // ================= ldmatrix + mma.sync path =================
    // 8 warps 2x4; warp tile 64x32; 64-K slabs; 3-stage cp.async pipeline.
    // Stage layout: [A 128x72bf16 (144B pitch) | B 128x72bf16] = 36864 B.
    const uint32_t sm_u = smem_u32(smem);
    const int STG = 36864;
    const int g = lid >> 2, tig = lid & 3;
    const int wr = wid >> 2, wc = wid & 3;
    const int rowbase = wr * 64, colbase = wc * 32;
    const int KC64 = K >> 6;
    const int S = KC64 * 3;

    // ldmatrix per-lane address components
    const uint32_t a_lane = (uint32_t)(rowbase + (lid & 15)) * 144 + ((lid >> 4) << 4);
    const uint32_t b_lane = (uint32_t)(colbase + (lid & 7) + (((lid >> 4) & 1) << 3)) * 144
                          + (((lid >> 3) & 1) << 4);

    auto load_stage = [&](int s, int buf) {
        int p = s / KC64, k0 = (s - p * KC64) << 6;
        const bf16* Ap = (p == 2) ? Al : Ah;
        const bf16* Bp = (p == 1) ? Bl : Bh;
        uint32_t ab = sm_u + buf * STG, bb = ab + 18432;
#pragma unroll
        for (int rep = 0; rep < 4; rep++) {
            int i = tid + 256 * rep;
            int r = i >> 3, sc = i & 7;
            CP_ASYNC16(ab + r * 144 + sc * 16, Ap + (size_t)(m0 + r) * K + k0 + sc * 8);
        }
#pragma unroll
        for (int rep = 0; rep < 4; rep++) {
            int i = tid + 256 * rep;
            int r = i >> 3, sc = i & 7;
            CP_ASYNC16(bb + r * 144 + sc * 16, Bp + (size_t)(n0 + r) * K + k0 + sc * 8);
        }
        CP_COMMIT();
    };

    float acc[4][4][4];
#pragma unroll
    for (int mf = 0; mf < 4; mf++)
#pragma unroll
        for (int nf = 0; nf < 4; nf++)
#pragma unroll
            for (int q = 0; q < 4; q++) acc[mf][nf][q] = 0.f;

    load_stage(0, 0);
    if (1 < S) load_stage(1, 1);
    for (int s = 0; s < S; s++) {
        if (s + 2 < S) { load_stage(s + 2, (s + 2) % 3); CP_WAIT2(); }
        else if (s + 1 < S) CP_WAIT1();
        else CP_WAIT0();
        __syncthreads();
        uint32_t ab = sm_u + (s % 3) * STG;
        uint32_t bb = ab + 18432;
#pragma unroll
        for (int kk = 0; kk < 64; kk += 16) {
            uint32_t afr[4][4], bfr[2][4];
#pragma unroll
            for (int mf = 0; mf < 4; mf++)
                LDSM_X4(afr[mf], ab + a_lane + mf * 2304 + kk * 2);
#pragma unroll
            for (int np = 0; np < 2; np++)
                LDSM_X4(bfr[np], bb + b_lane + np * 2304 + kk * 2);
#pragma unroll
            for (int mf = 0; mf < 4; mf++)
#pragma unroll
                for (int nf = 0; nf < 4; nf++)
                    hmma16816(acc[mf][nf], afr[mf], &bfr[nf >> 1][(nf & 1) * 2]);
        }
        __syncthreads();
    }

#pragma unroll
    for (int mf = 0; mf < 4; mf++)
#pragma unroll
        for (int nf = 0; nf < 4; nf++) {
            int col0 = n0 + colbase + nf * 8 + 2 * tig;
#pragma unroll
            for (int r8 = 0; r8 < 2; r8++) {
                int row = m0 + rowbase + mf * 16 + g + r8 * 8;
                if (row < M) {
#pragma unroll
                    for (int cc = 0; cc < 2; cc++) {
                        int col = col0 + cc;
                        float v = acc[mf][nf][r8 * 2 + cc] + bias[col];
                        if (ACT == 1) v = gelu_exact(v);
                        else if (ACT == 2) v = tanhf(v);
                        if (STORE != 2) C[(size_t)row * ldc + coff + col] = v;
                        if (STORE != 0)
                            split_store(v, Ch + (size_t)row * ldh + offh + col,
                                           Cl + (size_t)row * ldh + offh + col);
                    }
                }
            }
        }
#endif
}

// ---------------- conversion / small kernels ----------------
__global__ void tsplit(const float* __restrict__ W, long wz, bf16* __restrict__ oh,
                       bf16* __restrict__ ol, long oz, int Kin, int Ncol, int Kpad) {
    int idx = blockIdx.x * blockDim.x + threadIdx.x;
    if (idx >= Ncol * Kpad) return;
    int z = blockIdx.z;
    W += (size_t)z * wz; oh += (size_t)z * oz; ol += (size_t)z * oz;
    int n = idx / Kpad, k = idx - n * Kpad;
    float v = (k < Kin) ? W[(size_t)k * Ncol + n] : 0.f;
    split_store(v, oh + idx, ol + idx);
}

__global__ void fill_kernel(float* p, size_t n, float v) {
    size_t i = (size_t)blockIdx.x * blockDim.x + threadIdx.x;
    if (i < n) p[i] = v;
}

// batched over all 6 relations
__global__ void gather_split(const float* __restrict__ x, const int* __restrict__ ei,
                             const float* __restrict__ ea) {
    long idx = (long)blockIdx.x * blockDim.x + threadIdx.x;
    const long perR = (long)EE * (KVP + HH);
    if (idx >= RR * perR) return;
    int r = (int)(idx / perR);
    long rem = idx - (long)r * perR;
    if (rem < (long)EE * KVP) {
        int e = (int)(rem / KVP), c = (int)(rem - (long)e * KVP);
        int src = ei[(r * 2 + 0) * EE + e];
        float v = (c < HH) ? x[(size_t)src * HH + c]
                : ((c < KVO) ? ea[((size_t)r * EE + e) * FF + (c - HH)] : 0.f);
        size_t o = ((size_t)r * EE + e) * KVP + c;
        split_store(v, g_kvin_h + o, g_kvin_l + o);
    } else {
        long j = rem - (long)EE * KVP;
        int e = (int)(j >> 8), c = (int)(j & 255);
        int dst = ei[(r * 2 + 1) * EE + e];
        size_t o = ((size_t)r * EE + e) * HH + c;
        split_store(x[(size_t)dst * HH + c], g_xd_h + o, g_xd_l + o);
    }
}

__global__ void scores_kernel(const int* __restrict__ ei, const float* __restrict__ prior) {
    int idx = blockIdx.x * blockDim.x + threadIdx.x;
    if (idx >= RR * EE * NHD) return;
    int r = idx >> 18;                      // EE*NHD = 2^18
    int e = (idx >> 3) & (EE - 1), h = idx & 7;
    const float* qp = g_qe + ((size_t)r * EE + e) * HH + h * HDD;
    const float* kp = g_k  + ((size_t)r * EE + e) * HH + h * HDD;
    float s = 0.f;
#pragma unroll
    for (int d = 0; d < HDD; d++) s += qp[d] * kp[d];
    s *= 0.17677669529663687f * prior[r * NHD + h];
    g_sc[idx] = s;
    int dst = ei[(r * 2 + 1) * EE + e];
    atomicMaxF(&g_m[((size_t)r * NN + dst) * NHD + h], s);
}

__global__ void ex_kernel(const int* __restrict__ ei) {
    int idx = blockIdx.x * blockDim.x + threadIdx.x;
    if (idx >= RR * EE * NHD) return;
    int r = idx >> 18;
    int e = (idx >> 3) & (EE - 1), h = idx & 7;
    int dst = ei[(r * 2 + 1) * EE + e];
    float exv = expf(g_sc[idx] - g_m[((size_t)r * NN + dst) * NHD + h]);
    g_sc[idx] = exv;
    atomicAdd(&g_denom[((size_t)r * NN + dst) * NHD + h], exv);
}

__global__ void agg_kernel(const int* __restrict__ ei) {
    long idx = (long)blockIdx.x * blockDim.x + threadIdx.x;
    if (idx >= (long)RR * EE * HH) return;
    int r = (int)(idx >> 23);               // EE*HH = 2^23
    long w_ = idx & ((1L << 23) - 1);
    int e = (int)(w_ >> 8), c = (int)(w_ & 255);
    int h = c >> 5;
    int dst = ei[(r * 2 + 1) * EE + e];
    float w = g_sc[((size_t)r * EE + e) * NHD + h] /
              (g_denom[((size_t)r * NN + dst) * NHD + h] + 1e-16f);
    atomicAdd(&g_agg[((size_t)r * NN + dst) * HH + c], w * g_v[idx]);
}

__global__ void agg_split_kernel() {
    long idx = (long)blockIdx.x * blockDim.x + threadIdx.x;
    if (idx >= (long)RR * NN * HH) return;
    int r = (int)(idx / ((long)NN * HH));
    long w_ = idx - (long)r * NN * HH;
    int n = (int)(w_ >> 8), c = (int)(w_ & 255);
    size_t o = ((size_t)r * NP + n) * HH + c;
    split_store(g_agg[idx], g_agg_h + o, g_agg_l + o);
}

__global__ void interw_kernel(const float* __restrict__ Wir2, const float* __restrict__ bir2) {
    int gwarp = (blockIdx.x * blockDim.x + threadIdx.x) >> 5;
    int lane = threadIdx.x & 31;
    if (gwarp >= NN) return;
    float acc[RR] = {};
    for (int k = lane; k < HH; k += 32) {
        float hv = g_hbuf[gwarp * HH + k];
#pragma unroll
        for (int rr = 0; rr < RR; rr++) acc[rr] += hv * Wir2[k * RR + rr];
    }
#pragma unroll
    for (int rr = 0; rr < RR; rr++)
#pragma unroll
        for (int off = 16; off; off >>= 1)
            acc[rr] += __shfl_down_sync(0xffffffff, acc[rr], off);
    if (lane == 0) {
        float mx = -1e30f;
#pragma unroll
        for (int rr = 0; rr < RR; rr++) { acc[rr] += bir2[rr]; mx = fmaxf(mx, acc[rr]); }
        float s = 0.f;
#pragma unroll
        for (int rr = 0; rr < RR; rr++) { acc[rr] = expf(acc[rr] - mx); s += acc[rr]; }
        float inv = 1.f / s;
#pragma unroll
        for (int rr = 0; rr < RR; rr++) g_interw[gwarp * NHD + rr] = acc[rr] * inv;
    }
}

__global__ void interagg_kernel() {
    int idx = blockIdx.x * blockDim.x + threadIdx.x;
    if (idx >= NN * HH) return;
    int n = idx >> 8, c = idx & 255;
    float s = 0.f;
#pragma unroll
    for (int rr = 0; rr < RR; rr++) {
        size_t b = (size_t)n * RH + rr * HH + c;
        s += g_interw[n * NHD + rr] *
             (__bfloat162float(g_rel_h[b]) + __bfloat162float(g_rel_l[b]));
    }
    split_store(s, g_cat_h + (size_t)n * 2 * HH + c, g_cat_l + (size_t)n * 2 * HH + c);
}

__global__ void paths_kernel() {
    int idx = blockIdx.x * blockDim.x + threadIdx.x;
    if (idx >= NN * HH) return;
    int n = idx >> 8, c = idx & 255;
    float v[RR];
#pragma unroll
    for (int rr = 0; rr < RR; rr++) {
        size_t b = (size_t)n * RH + rr * HH + c;
        v[rr] = __bfloat162float(g_rel_h[b]) + __bfloat162float(g_rel_l[b]);
    }
    split_store(v[2] + v[3], g_pth_h + ((size_t)0 * NP + n) * HH + c, g_pth_l + ((size_t)0 * NP + n) * HH + c);
    split_store(v[4] + v[0], g_pth_h + ((size_t)1 * NP + n) * HH + c, g_pth_l + ((size_t)1 * NP + n) * HH + c);
    split_store(v[1] + v[5], g_pth_h + ((size_t)2 * NP + n) * HH + c, g_pth_l + ((size_t)2 * NP + n) * HH + c);
}

__global__ void attnmeta_kernel(const float* __restrict__ Wa2,
                                const float* __restrict__ gm, const float* __restrict__ bm_) {
    __shared__ float lg[3];
    __shared__ float rbuf[256];
    int n = blockIdx.x, t = threadIdx.x;
    int lane = t & 31, w = t >> 5;
    if (w < 3) {
        float a = 0.f;
        for (int j = lane; j < 128; j += 32)
            a += g_t[((size_t)n * 3 + w) * 128 + j] * Wa2[j];
#pragma unroll
        for (int off = 16; off; off >>= 1) a += __shfl_down_sync(0xffffffff, a, off);
        if (lane == 0) lg[w] = a;
    }
    __syncthreads();
    float l0 = lg[0], l1 = lg[1], l2 = lg[2];
    float mx = fmaxf(l0, fmaxf(l1, l2));
    float e0 = expf(l0 - mx), e1 = expf(l1 - mx), e2 = expf(l2 - mx);
    float inv = 1.f / (e0 + e1 + e2);
    const float* st = g_stacked + (size_t)n * 3 * HH;
    float s = (e0 * st[t] + e1 * st[HH + t] + e2 * st[2 * HH + t]) * inv;
    rbuf[t] = s;
    __syncthreads();
    for (int off = 128; off; off >>= 1) { if (t < off) rbuf[t] += rbuf[t + off]; __syncthreads(); }
    float mu = rbuf[0] * (1.f / 256.f);
    __syncthreads();
    float d = s - mu;
    rbuf[t] = d * d;
    __syncthreads();
    for (int off = 128; off; off >>= 1) { if (t < off) rbuf[t] += rbuf[t + off]; __syncthreads(); }
    float var = rbuf[0] * (1.f / 256.f);
    float o = d * rsqrtf(var + 1e-5f) * gm[t] + bm_[t];
    split_store(o, g_cat_h + (size_t)n * 2 * HH + HH + t, g_cat_l + (size_t)n * 2 * HH + HH + t);
}

__global__ void outln_kernel(const float* __restrict__ x, const float* __restrict__ gout,
                             const float* __restrict__ bout, float* __restrict__ out) {
    __shared__ float rbuf[256];
    int n = blockIdx.x, t = threadIdx.x;
    float v = x[(size_t)n * HH + t] + g_hbuf[(size_t)n * HH + t];
    rbuf[t] = v;
    __syncthreads();
    for (int off = 128; off; off >>= 1) { if (t < off) rbuf[t] += rbuf[t + off]; __syncthreads(); }
    float mu = rbuf[0] * (1.f / 256.f);
    __syncthreads();
    float d = v - mu;
    rbuf[t] = d * d;
    __syncthreads();
    for (int off = 128; off; off >>= 1) { if (t < off) rbuf[t] += rbuf[t + off]; __syncthreads(); }
    float var = rbuf[0] * (1.f / 256.f);
    out[(size_t)n * HH + t] = d * rsqrtf(var + 1e-5f) * gout[t] + bout[t];
}

// ---------------- host ----------------
extern "C" void kernel_launch(void* const* d_in, const int* in_sizes, int n_in,
                              void* d_out, int out_size) {
    const float* x     = (const float*)d_in[0];
    const int*   ei    = (const int*)d_in[1];
    const float* ea    = (const float*)d_in[2];
    const float* Wq    = (const float*)d_in[3];
    const float* bq    = (const float*)d_in[4];
    const float* Wk    = (const float*)d_in[5];
    const float* bk    = (const float*)d_in[6];
    const float* Wv    = (const float*)d_in[7];
    const float* bv    = (const float*)d_in[8];
    const float* prior = (const float*)d_in[9];
    const float* Wm    = (const float*)d_in[10];
    const float* bm    = (const float*)d_in[11];
    const float* W_ir1 = (const float*)d_in[12];
    const float* b_ir1 = (const float*)d_in[13];
    const float* W_ir2 = (const float*)d_in[14];
    const float* b_ir2 = (const float*)d_in[15];
    const float* Wmp   = (const float*)d_in[16];
    const float* bmp   = (const float*)d_in[17];
    const float* Wa1   = (const float*)d_in[18];
    const float* ba1   = (const float*)d_in[19];
    const float* Wa2   = (const float*)d_in[20];
    const float* gmeta = (const float*)d_in[21];
    const float* bmeta = (const float*)d_in[22];
    const float* Wc    = (const float*)d_in[23];
    const float* bc    = (const float*)d_in[24];
    const float* gout  = (const float*)d_in[25];
    const float* bout  = (const float*)d_in[26];
    float* out = (float*)d_out;

    void* p;
#define SYM(v, s) cudaGetSymbolAddress(&p, s); auto* v = (decltype(&s[0]))p
    SYM(p_kvin_h, g_kvin_h);  SYM(p_kvin_l, g_kvin_l);
    SYM(p_xd_h, g_xd_h);      SYM(p_xd_l, g_xd_l);
    SYM(p_qe, g_qe); SYM(p_k, g_k); SYM(p_v, g_v);
    SYM(p_m, g_m); SYM(p_denom, g_denom); SYM(p_agg, g_agg);
    SYM(p_agg_h, g_agg_h);    SYM(p_agg_l, g_agg_l);
    SYM(p_rel_h, g_rel_h);    SYM(p_rel_l, g_rel_l);
    SYM(p_hbuf, g_hbuf);
    SYM(p_cat_h, g_cat_h);    SYM(p_cat_l, g_cat_l);
    SYM(p_pth_h, g_pth_h);    SYM(p_pth_l, g_pth_l);
    SYM(p_stacked, g_stacked);
    SYM(p_stk_h, g_stk_h);    SYM(p_stk_l, g_stk_l);
    SYM(p_t, g_t);
    SYM(p_wqt_h, g_wqt_h);    SYM(p_wqt_l, g_wqt_l);
    SYM(p_wkt_h, g_wkt_h);    SYM(p_wkt_l, g_wkt_l);
    SYM(p_wvt_h, g_wvt_h);    SYM(p_wvt_l, g_wvt_l);
    SYM(p_wmt_h, g_wmt_h);    SYM(p_wmt_l, g_wmt_l);
    SYM(p_wir1t_h, g_wir1t_h); SYM(p_wir1t_l, g_wir1t_l);
    SYM(p_wmpt_h, g_wmpt_h);  SYM(p_wmpt_l, g_wmpt_l);
    SYM(p_wa1t_h, g_wa1t_h);  SYM(p_wa1t_l, g_wa1t_l);
    SYM(p_wct_h, g_wct_h);    SYM(p_wct_l, g_wct_l);
#undef SYM

    const int SMB = 110592;  // 3-stage HMMA pipeline; tcgen05 path needs 66560
    cudaFuncSetAttribute((const void*)&tcmm<0, 0>, cudaFuncAttributeMaxDynamicSharedMemorySize, SMB);
    cudaFuncSetAttribute((const void*)&tcmm<1, 2>, cudaFuncAttributeMaxDynamicSharedMemorySize, SMB);
    cudaFuncSetAttribute((const void*)&tcmm<1, 0>, cudaFuncAttributeMaxDynamicSharedMemorySize, SMB);
    cudaFuncSetAttribute((const void*)&tcmm<0, 1>, cudaFuncAttributeMaxDynamicSharedMemorySize, SMB);
    cudaFuncSetAttribute((const void*)&tcmm<2, 0>, cudaFuncAttributeMaxDynamicSharedMemorySize, SMB);

    const int TB = 256;
    bf16* nb16 = nullptr;
    float* nf32 = nullptr;

    // ---- weight transposes + splits (batched over z) ----
    tsplit<<<dim3((HH * HH + TB - 1) / TB, 1, RR), TB>>>(Wq, (long)HH * HH,
        p_wqt_h, p_wqt_l, (long)HH * HH, HH, HH, HH);
    tsplit<<<dim3((HH * KVP + TB - 1) / TB, 1, RR), TB>>>(Wk, (long)KVO * HH,
        p_wkt_h, p_wkt_l, (long)HH * KVP, KVO, HH, KVP);
    tsplit<<<dim3((HH * KVP + TB - 1) / TB, 1, RR), TB>>>(Wv, (long)KVO * HH,
        p_wvt_h, p_wvt_l, (long)HH * KVP, KVO, HH, KVP);
    tsplit<<<dim3((HH * HH + TB - 1) / TB, 1, RR), TB>>>(Wm, (long)HH * HH,
        p_wmt_h, p_wmt_l, (long)HH * HH, HH, HH, HH);
    tsplit<<<dim3((HH * RH + TB - 1) / TB, 1, 1), TB>>>(W_ir1, 0,
        p_wir1t_h, p_wir1t_l, 0, RH, HH, RH);
    tsplit<<<dim3((HH * HH + TB - 1) / TB, 1, 3), TB>>>(Wmp, (long)HH * HH,
        p_wmpt_h, p_wmpt_l, (long)HH * HH, HH, HH, HH);
    tsplit<<<dim3(((HH / 2) * HH + TB - 1) / TB, 1, 1), TB>>>(Wa1, 0,
        p_wa1t_h, p_wa1t_l, 0, HH, HH / 2, HH);
    tsplit<<<dim3((HH * 2 * HH + TB - 1) / TB, 1, 1), TB>>>(Wc, 0,
        p_wct_h, p_wct_l, 0, 2 * HH, HH, 2 * HH);

    // ---- message passing (fully batched over relations) ----
    fill_kernel<<<(RR * NN * NHD + TB - 1) / TB, TB>>>(p_m, (size_t)RR * NN * NHD, -INFINITY);
    fill_kernel<<<(RR * NN * NHD + TB - 1) / TB, TB>>>(p_denom, (size_t)RR * NN * NHD, 0.f);
    fill_kernel<<<(int)(((long)RR * NN * HH + TB - 1) / TB), TB>>>(p_agg, (size_t)RR * NN * HH, 0.f);
    gather_split<<<(int)(((long)RR * EE * (KVP + HH) + TB - 1) / TB), TB>>>(x, ei, ea);

    tcmm<0, 0><<<dim3(2, EE / 128, RR), 256, SMB>>>(
        p_xd_h, p_xd_l, (long)EE * HH,
        p_wqt_h, p_wqt_l, (long)HH * HH,
        bq, HH,
        p_qe, HH, 0, (long)EE * HH, 0,
        nb16, nb16, 0, 0, 0, 0, EE, HH);
    tcmm<0, 0><<<dim3(2, EE / 128, RR), 256, SMB>>>(
        p_kvin_h, p_kvin_l, (long)EE * KVP,
        p_wkt_h, p_wkt_l, (long)HH * KVP,
        bk, HH,
        p_k, HH, 0, (long)EE * HH, 0,
        nb16, nb16, 0, 0, 0, 0, EE, KVP);
    tcmm<0, 0><<<dim3(2, EE / 128, RR), 256, SMB>>>(
        p_kvin_h, p_kvin_l, (long)EE * KVP,
        p_wvt_h, p_wvt_l, (long)HH * KVP,
        bv, HH,
        p_v, HH, 0, (long)EE * HH, 0,
        nb16, nb16, 0, 0, 0, 0, EE, KVP);

    scores_kernel<<<RR * EE * NHD / TB, TB>>>(ei, prior);
    ex_kernel<<<RR * EE * NHD / TB, TB>>>(ei);
    agg_kernel<<<(int)(((long)RR * EE * HH) / TB), TB>>>(ei);
    agg_split_kernel<<<(int)(((long)RR * NN * HH + TB - 1) / TB), TB>>>();

    tcmm<1, 2><<<dim3(2, NP / 128, RR), 256, SMB>>>(
        p_agg_h, p_agg_l, (long)NP * HH,
        p_wmt_h, p_wmt_l, (long)HH * HH,
        bm, HH,
        nf32, 0, 0, 0, 0,
        p_rel_h, p_rel_l, RH, 0, 0, HH, NN, HH);

    // ---- inter-relation attention ----
    tcmm<1, 0><<<dim3(2, NP / 128, 1), 256, SMB>>>(
        p_rel_h, p_rel_l, 0,
        p_wir1t_h, p_wir1t_l, 0,
        b_ir1, 0,
        p_hbuf, HH, 0, 0, 0,
        nb16, nb16, 0, 0, 0, 0, NN, RH);
    interw_kernel<<<(NN * 32 + TB - 1) / TB, TB>>>(W_ir2, b_ir2);
    interagg_kernel<<<(NN * HH + TB - 1) / TB, TB>>>();

    // ---- meta paths ----
    paths_kernel<<<(NN * HH + TB - 1) / TB, TB>>>();
    tcmm<0, 1><<<dim3(2, NP / 128, 3), 256, SMB>>>(
        p_pth_h, p_pth_l, (long)NP * HH,
        p_wmpt_h, p_wmpt_l, (long)HH * HH,
        bmp, HH,
        p_stacked, 3 * HH, 0, 0, HH,
        p_stk_h, p_stk_l, 3 * HH, 0, 0, HH, NN, HH);
    tcmm<2, 0><<<dim3(1, (3 * NN + 127) / 128, 1), 256, SMB>>>(
        p_stk_h, p_stk_l, 0,
        p_wa1t_h, p_wa1t_l, 0,
        ba1, 0,
        p_t, HH / 2, 0, 0, 0,
        nb16, nb16, 0, 0, 0, 0, 3 * NN, HH);
    attnmeta_kernel<<<NN, TB>>>(Wa2, gmeta, bmeta);

    // ---- combine + output LN ----
    tcmm<1, 0><<<dim3(2, NP / 128, 1), 256, SMB>>>(
        p_cat_h, p_cat_l, 0,
        p_wct_h, p_wct_l, 0,
        bc, 0,
        p_hbuf, HH, 0, 0, 0,
        nb16, nb16, 0, 0, 0, 0, NN, 2 * HH);
    outln_kernel<<<NN, TB>>>(x, gout, bout, out);
}

// round 7
// speedup vs baseline: 1.3236x; 1.0749x over previous
#include <cuda_runtime.h>
#include <cuda_bf16.h>
#include <math.h>
#include <stdint.h>

#define NN 50000
#define NP 50048          // NN padded to 128
#define RR 6
#define EE 32768
#define HH 256
#define FF 16
#define KVO 272
#define KVP 320           // 272 padded to 64-multiple
#define NHD 8
#define HDD 32
#define RH 1536

typedef __nv_bfloat16 bf16;

#if defined(__CUDA_ARCH__) && (defined(__CUDA_ARCH_FEAT_SM103_ALL) \
    || (defined(__CUDA_ARCH_SPECIFIC__) && (__CUDA_ARCH_SPECIFIC__ == 1030)) \
    || (defined(__CUDA_ARCH_FAMILY_SPECIFIC__) && (__CUDA_ARCH_FAMILY_SPECIFIC__ == 1030)))
#define HAS_TC05 1
#else
#define HAS_TC05 0
#endif

// ---------------- scratch (device globals; zero-initialized at load) ----------------
__device__ __align__(1024) bf16 g_kvin_h[RR * EE * KVP], g_kvin_l[RR * EE * KVP];
__device__ __align__(1024) bf16 g_xd_h[RR * EE * HH],   g_xd_l[RR * EE * HH];
__device__ float g_qe[(size_t)RR * EE * HH], g_k[(size_t)RR * EE * HH], g_v[(size_t)RR * EE * HH];
__device__ float g_sc[RR * EE * NHD], g_m[RR * NN * NHD], g_denom[RR * NN * NHD];
__device__ float g_agg[(size_t)RR * NN * HH];
__device__ __align__(1024) bf16 g_agg_h[(size_t)RR * NP * HH], g_agg_l[(size_t)RR * NP * HH];
__device__ __align__(1024) bf16 g_rel_h[(size_t)NP * RH], g_rel_l[(size_t)NP * RH];
__device__ float g_hbuf[NP * HH];
__device__ float g_interw[NN * NHD];
__device__ __align__(1024) bf16 g_cat_h[NP * 2 * HH], g_cat_l[NP * 2 * HH];
__device__ __align__(1024) bf16 g_pth_h[3 * NP * HH], g_pth_l[3 * NP * HH];
__device__ float g_stacked[NP * 3 * HH];
__device__ __align__(1024) bf16 g_stk_h[NP * 3 * HH], g_stk_l[NP * 3 * HH];
__device__ float g_t[3 * NP * (HH / 2)];
// transposed + split weights: [Ncol][Kpad]
__device__ __align__(1024) bf16 g_wqt_h[RR * HH * HH],  g_wqt_l[RR * HH * HH];
__device__ __align__(1024) bf16 g_wkt_h[RR * HH * KVP], g_wkt_l[RR * HH * KVP];
__device__ __align__(1024) bf16 g_wvt_h[RR * HH * KVP], g_wvt_l[RR * HH * KVP];
__device__ __align__(1024) bf16 g_wmt_h[RR * HH * HH],  g_wmt_l[RR * HH * HH];
__device__ __align__(1024) bf16 g_wir1t_h[HH * RH],     g_wir1t_l[HH * RH];
__device__ __align__(1024) bf16 g_wmpt_h[3 * HH * HH],  g_wmpt_l[3 * HH * HH];
__device__ __align__(1024) bf16 g_wa1t_h[(HH/2) * HH],  g_wa1t_l[(HH/2) * HH];
__device__ __align__(1024) bf16 g_wct_h[HH * 2 * HH],   g_wct_l[HH * 2 * HH];

// ---------------- common helpers ----------------
__device__ __forceinline__ float gelu_exact(float x) {
    return 0.5f * x * (1.0f + erff(x * 0.7071067811865475f));
}
__device__ __forceinline__ void split_store(float v, bf16* ph, bf16* pl) {
    bf16 h = __float2bfloat16(v);
    *ph = h;
    *pl = __float2bfloat16(v - __bfloat162float(h));
}
__device__ __forceinline__ void atomicMaxF(float* addr, float v) {
    int* ai = (int*)addr;
    int old = *ai;
    while (__int_as_float(old) < v) {
        int assumed = old;
        old = atomicCAS(ai, assumed, __float_as_int(v));
        if (old == assumed) break;
    }
}
__device__ __forceinline__ uint32_t smem_u32(const void* p) {
    uint32_t a;
    asm("{ .reg .u64 t; cvta.to.shared.u64 t, %1; cvt.u32.u64 %0, t; }" : "=r"(a) : "l"(p));
    return a;
}
#define CP_ASYNC16(dst, src) \
    asm volatile("cp.async.cg.shared.global [%0], [%1], 16;" :: "r"(dst), "l"(src))
#define CP_COMMIT() asm volatile("cp.async.commit_group;")
#define CP_WAIT2()  asm volatile("cp.async.wait_group 2;")
#define CP_WAIT1()  asm volatile("cp.async.wait_group 1;")
#define CP_WAIT0()  asm volatile("cp.async.wait_group 0;")

#if HAS_TC05
#define SWZ128(o) ((o) ^ (((o) >> 3) & 0x70))
__device__ __forceinline__ uint64_t mkdesc(uint32_t addr) {
    return ((uint64_t)2 << 61) | ((uint64_t)1 << 46) | ((uint64_t)64 << 32) |
           ((uint64_t)1 << 16) | ((addr >> 4) & 0x3FFF);
}
__device__ __forceinline__ void mma_f16_ss(uint32_t d, uint64_t ad, uint64_t bd,
                                           uint32_t idesc, bool acc) {
    uint32_t en = acc ? 1u : 0u;
    asm volatile(
        "{\n\t.reg .pred p;\n\tsetp.ne.u32 p, %5, 0;\n\t"
        "tcgen05.mma.cta_group::1.kind::f16 [%0], %1, %2, %3, {%4,%4,%4,%4}, p;\n\t}"
        :: "r"(d), "l"(ad), "l"(bd), "r"(idesc), "r"(0u), "r"(en) : "memory");
}
__device__ __forceinline__ void mbar_init(uint32_t mb, uint32_t cnt) {
    asm volatile("mbarrier.init.shared.b64 [%0], %1;" :: "r"(mb), "r"(cnt) : "memory");
}
__device__ __forceinline__ void mbar_wait(uint32_t mb, int parity) {
    asm volatile(
        "{\n\t.reg .pred P1;\n\t"
        "WL_%=:\n\t"
        "mbarrier.try_wait.parity.acquire.cta.shared::cta.b64 P1, [%0], %1, 0x989680;\n\t"
        "@P1 bra.uni WD_%=;\n\t"
        "bra.uni WL_%=;\n\t"
        "WD_%=:\n\t}"
        :: "r"(mb), "r"(parity) : "memory");
}
#define LDTM_X32(r, a) \
    asm volatile( \
        "tcgen05.ld.sync.aligned.32x32b.x32.b32 " \
        "{%0, %1, %2, %3, %4, %5, %6, %7, " \
        " %8, %9, %10, %11, %12, %13, %14, %15, " \
        " %16, %17, %18, %19, %20, %21, %22, %23, " \
        " %24, %25, %26, %27, %28, %29, %30, %31}, [%32];" \
        : "=r"((r)[0]),  "=r"((r)[1]),  "=r"((r)[2]),  "=r"((r)[3]), \
          "=r"((r)[4]),  "=r"((r)[5]),  "=r"((r)[6]),  "=r"((r)[7]), \
          "=r"((r)[8]),  "=r"((r)[9]),  "=r"((r)[10]), "=r"((r)[11]), \
          "=r"((r)[12]), "=r"((r)[13]), "=r"((r)[14]), "=r"((r)[15]), \
          "=r"((r)[16]), "=r"((r)[17]), "=r"((r)[18]), "=r"((r)[19]), \
          "=r"((r)[20]), "=r"((r)[21]), "=r"((r)[22]), "=r"((r)[23]), \
          "=r"((r)[24]), "=r"((r)[25]), "=r"((r)[26]), "=r"((r)[27]), \
          "=r"((r)[28]), "=r"((r)[29]), "=r"((r)[30]), "=r"((r)[31]) \
        : "r"(a))
#else
__device__ __forceinline__ void hmma16816(float* c, const uint32_t* a, const uint32_t* b) {
    asm volatile(
        "mma.sync.aligned.m16n8k16.row.col.f32.bf16.bf16.f32 "
        "{%0,%1,%2,%3}, {%4,%5,%6,%7}, {%8,%9}, {%0,%1,%2,%3};"
        : "+f"(c[0]), "+f"(c[1]), "+f"(c[2]), "+f"(c[3])
        : "r"(a[0]), "r"(a[1]), "r"(a[2]), "r"(a[3]), "r"(b[0]), "r"(b[1]));
}
#define LDSM_X4(r, addr) \
    asm volatile("ldmatrix.sync.aligned.m8n8.x4.shared.b16 {%0,%1,%2,%3}, [%4];" \
        : "=r"((r)[0]), "=r"((r)[1]), "=r"((r)[2]), "=r"((r)[3]) : "r"(addr))
#endif

// ---------------- bf16x3 GEMM (z-batched) ----------------
template <int ACT, int STORE>
__global__ __launch_bounds__(256)
void tcmm(const bf16* __restrict__ Ah, const bf16* __restrict__ Al, long az,
          const bf16* __restrict__ Bh, const bf16* __restrict__ Bl, long bz,
          const float* __restrict__ bias, int biasz,
          float* __restrict__ C, int ldc, int coff, long cz, int coffz,
          bf16* __restrict__ Ch, bf16* __restrict__ Cl, int ldh, int offh,
          long chz, int offhz,
          int M, int K) {
    extern __shared__ char smem[];
    const int tid = threadIdx.x, wid = tid >> 5, lid = tid & 31;
    const int m0 = blockIdx.y * 128;
    const int n0 = blockIdx.x * 128;
    const int z = blockIdx.z;
    Ah += (size_t)z * az;  Al += (size_t)z * az;
    Bh += (size_t)z * bz;  Bl += (size_t)z * bz;
    bias += (size_t)z * biasz;
    if (STORE != 2) { C += (size_t)z * cz; coff += z * coffz; }
    if (STORE != 0) { Ch += (size_t)z * chz; Cl += (size_t)z * chz; offh += z * offhz; }

#if HAS_TC05
    // ================= tcgen05 path =================
    const uint32_t sb = smem_u32(smem);
    const int ABYTES = 128 * 128;
    const int BUF = 2 * ABYTES;
    const uint32_t mbar0 = sb + 8, mbar1 = sb + 16;
    const uint32_t buf0 = sb + 1024;

    if (wid == 0) {
        asm volatile("tcgen05.alloc.cta_group::1.sync.aligned.shared::cta.b32 [%0], %1;"
                     :: "r"(sb), "r"(128u) : "memory");
        asm volatile("tcgen05.relinquish_alloc_permit.cta_group::1.sync.aligned;");
    }
    __syncthreads();
    uint32_t tmem;
    asm volatile("ld.shared.b32 %0, [%1];" : "=r"(tmem) : "r"(sb));
    if (tid == 0) { mbar_init(mbar0, 1); mbar_init(mbar1, 1); }
    __syncthreads();

    const int KC = K >> 6;
    const int T = KC * 3;
    const uint32_t idesc64 = (1u << 4) | (1u << 7) | (1u << 10) | (8u << 17) | (8u << 24);

    auto load_chunk = [&](int c, uint32_t bufbase) {
        int p = c / KC, kc = (c - p * KC) << 6;
        const bf16* Ap = (p == 2) ? Al : Ah;
        const bf16* Bp = (p == 1) ? Bl : Bh;
        for (int i = tid; i < 2048; i += 256) {
            uint32_t dst;
            const bf16* src;
            if (i < 1024) {
                int r = i >> 3, g = i & 7;
                dst = bufbase + SWZ128(r * 128 + g * 16);
                src = Ap + (size_t)(m0 + r) * K + kc + g * 8;
            } else {
                int j = i - 1024;
                int r = j >> 3, g = j & 7;
                dst = bufbase + ABYTES + SWZ128(r * 128 + g * 16);
                src = Bp + (size_t)(n0 + r) * K + kc + g * 8;
            }
            CP_ASYNC16(dst, src);
        }
        CP_COMMIT();
    };

    int ph0 = 0, ph1 = 0;
    load_chunk(0, buf0);
    for (int c = 0; c < T; c++) {
        int b = c & 1;
        if (c + 1 < T) {
            int nb = b ^ 1;
            if (c >= 1) {
                if (nb) { mbar_wait(mbar1, ph1); ph1 ^= 1; }
                else    { mbar_wait(mbar0, ph0); ph0 ^= 1; }
            }
            load_chunk(c + 1, buf0 + nb * BUF);
            CP_WAIT1();
        } else {
            CP_WAIT0();
        }
        __syncthreads();
        if (tid == 0) {
            asm volatile("fence.proxy.async.shared::cta;" ::: "memory");
            uint64_t ad = mkdesc(buf0 + b * BUF);
            uint64_t bd = mkdesc(buf0 + b * BUF + ABYTES);
#pragma unroll
            for (int ks = 0; ks < 4; ks++)
#pragma unroll
                for (int ns = 0; ns < 2; ns++)
                    mma_f16_ss(tmem + ns * 64, ad + ks * 2, bd + ns * 512 + ks * 2,
                               idesc64, (c > 0) || (ks > 0));
            asm volatile("tcgen05.commit.cta_group::1.mbarrier::arrive::one.shared::cluster.b64 [%0];"
                         :: "r"(b ? mbar1 : mbar0) : "memory");
        }
    }
    {
        int lb = (T - 1) & 1;
        if (lb) mbar_wait(mbar1, ph1); else mbar_wait(mbar0, ph0);
    }
    asm volatile("tcgen05.fence::after_thread_sync;" ::: "memory");

    {
        int row = m0 + (wid & 3) * 32 + lid;
        int colbase = (wid >> 2) * 64;
        for (int cb = 0; cb < 64; cb += 32) {
            uint32_t regs[32];
            LDTM_X32(regs, tmem + colbase + cb);
            asm volatile("tcgen05.wait::ld.sync.aligned;" ::: "memory");
            if (row < M) {
#pragma unroll
                for (int j = 0; j < 32; j++) {
                    int col = n0 + colbase + cb + j;
                    float v = __uint_as_float(regs[j]) + bias[col];
                    if (ACT == 1) v = gelu_exact(v);
                    else if (ACT == 2) v = tanhf(v);
                    if (STORE != 2) C[(size_t)row * ldc + coff + col] = v;
                    if (STORE != 0)
                        split_store(v, Ch + (size_t)row * ldh + offh + col,
                                       Cl + (size_t)row * ldh + offh + col);
                }
            }
        }
    }
    __syncthreads();
    if (wid == 0)
        asm volatile("tcgen05.dealloc.cta_group::1.sync.aligned.b32 %0, %1;"
                     :: "r"(tmem), "r"(128u));

#else
    // ================= ldmatrix + mma.sync path =================
    const uint32_t sm_u = smem_u32(smem);
    const int STG = 36864;
    const int g = lid >> 2, tig = lid & 3;
    const int wr = wid >> 2, wc = wid & 3;
    const int rowbase = wr * 64, colbase = wc * 32;
    const int KC64 = K >> 6;
    const int S = KC64 * 3;

    const uint32_t a_lane = (uint32_t)(rowbase + (lid & 15)) * 144 + ((lid >> 4) << 4);
    const uint32_t b_lane = (uint32_t)(colbase + (lid & 7) + (((lid >> 4) & 1) << 3)) * 144
                          + (((lid >> 3) & 1) << 4);

    auto load_stage = [&](int s, int buf) {
        int p = s / KC64, k0 = (s - p * KC64) << 6;
        const bf16* Ap = (p == 2) ? Al : Ah;
        const bf16* Bp = (p == 1) ? Bl : Bh;
        uint32_t ab = sm_u + buf * STG, bb = ab + 18432;
#pragma unroll
        for (int rep = 0; rep < 4; rep++) {
            int i = tid + 256 * rep;
            int r = i >> 3, sc = i & 7;
            CP_ASYNC16(ab + r * 144 + sc * 16, Ap + (size_t)(m0 + r) * K + k0 + sc * 8);
        }
#pragma unroll
        for (int rep = 0; rep < 4; rep++) {
            int i = tid + 256 * rep;
            int r = i >> 3, sc = i & 7;
            CP_ASYNC16(bb + r * 144 + sc * 16, Bp + (size_t)(n0 + r) * K + k0 + sc * 8);
        }
        CP_COMMIT();
    };

    float acc[4][4][4];
#pragma unroll
    for (int mf = 0; mf < 4; mf++)
#pragma unroll
        for (int nf = 0; nf < 4; nf++)
#pragma unroll
            for (int q = 0; q < 4; q++) acc[mf][nf][q] = 0.f;

    load_stage(0, 0);
    if (1 < S) load_stage(1, 1);
    for (int s = 0; s < S; s++) {
        if (s + 2 < S) { load_stage(s + 2, (s + 2) % 3); CP_WAIT2(); }
        else if (s + 1 < S) CP_WAIT1();
        else CP_WAIT0();
        __syncthreads();
        uint32_t ab = sm_u + (s % 3) * STG;
        uint32_t bb = ab + 18432;
#pragma unroll
        for (int kk = 0; kk < 64; kk += 16) {
            uint32_t afr[4][4], bfr[2][4];
#pragma unroll
            for (int mf = 0; mf < 4; mf++)
                LDSM_X4(afr[mf], ab + a_lane + mf * 2304 + kk * 2);
#pragma unroll
            for (int np = 0; np < 2; np++)
                LDSM_X4(bfr[np], bb + b_lane + np * 2304 + kk * 2);
#pragma unroll
            for (int mf = 0; mf < 4; mf++)
#pragma unroll
                for (int nf = 0; nf < 4; nf++)
                    hmma16816(acc[mf][nf], afr[mf], &bfr[nf >> 1][(nf & 1) * 2]);
        }
        __syncthreads();
    }

#pragma unroll
    for (int mf = 0; mf < 4; mf++)
#pragma unroll
        for (int nf = 0; nf < 4; nf++) {
            int col0 = n0 + colbase + nf * 8 + 2 * tig;
#pragma unroll
            for (int r8 = 0; r8 < 2; r8++) {
                int row = m0 + rowbase + mf * 16 + g + r8 * 8;
                if (row < M) {
#pragma unroll
                    for (int cc = 0; cc < 2; cc++) {
                        int col = col0 + cc;
                        float v = acc[mf][nf][r8 * 2 + cc] + bias[col];
                        if (ACT == 1) v = gelu_exact(v);
                        else if (ACT == 2) v = tanhf(v);
                        if (STORE != 2) C[(size_t)row * ldc + coff + col] = v;
                        if (STORE != 0)
                            split_store(v, Ch + (size_t)row * ldh + offh + col,
                                           Cl + (size_t)row * ldh + offh + col);
                    }
                }
            }
        }
#endif
}

// ---------------- fused weight transpose+split (ALL weights, 1 launch) ----------------
__global__ void tsplit_all(const float* __restrict__ Wq, const float* __restrict__ Wk,
                           const float* __restrict__ Wv, const float* __restrict__ Wm,
                           const float* __restrict__ Wir1, const float* __restrict__ Wmp,
                           const float* __restrict__ Wa1, const float* __restrict__ Wc) {
    int idx = blockIdx.x * blockDim.x + threadIdx.x;
    int seg = blockIdx.y;
    float v;
    switch (seg) {
    case 0: {  // Wq -> wqt [RR][256][256]
        if (idx >= RR * HH * HH) return;
        int z = idx >> 16, w = idx & 65535, n = w >> 8, k = w & 255;
        v = Wq[(size_t)z * 65536 + k * HH + n];
        split_store(v, g_wqt_h + idx, g_wqt_l + idx);
        break; }
    case 1: {  // Wk -> wkt [RR][256][320]
        if (idx >= RR * HH * KVP) return;
        int z = idx / 81920, w = idx - z * 81920, n = w / KVP, k = w - n * KVP;
        v = (k < KVO) ? Wk[(size_t)z * KVO * HH + k * HH + n] : 0.f;
        split_store(v, g_wkt_h + idx, g_wkt_l + idx);
        break; }
    case 2: {  // Wv
        if (idx >= RR * HH * KVP) return;
        int z = idx / 81920, w = idx - z * 81920, n = w / KVP, k = w - n * KVP;
        v = (k < KVO) ? Wv[(size_t)z * KVO * HH + k * HH + n] : 0.f;
        split_store(v, g_wvt_h + idx, g_wvt_l + idx);
        break; }
    case 3: {  // Wm
        if (idx >= RR * HH * HH) return;
        int z = idx >> 16, w = idx & 65535, n = w >> 8, k = w & 255;
        v = Wm[(size_t)z * 65536 + k * HH + n];
        split_store(v, g_wmt_h + idx, g_wmt_l + idx);
        break; }
    case 4: {  // W_ir1 [1536,256] -> [256][1536]
        if (idx >= HH * RH) return;
        int n = idx / RH, k = idx - n * RH;
        v = Wir1[(size_t)k * HH + n];
        split_store(v, g_wir1t_h + idx, g_wir1t_l + idx);
        break; }
    case 5: {  // Wmp [3][256][256]
        if (idx >= 3 * HH * HH) return;
        int z = idx >> 16, w = idx & 65535, n = w >> 8, k = w & 255;
        v = Wmp[(size_t)z * 65536 + k * HH + n];
        split_store(v, g_wmpt_h + idx, g_wmpt_l + idx);
        break; }
    case 6: {  // Wa1 [256,128] -> [128][256]
        if (idx >= (HH / 2) * HH) return;
        int n = idx >> 8, k = idx & 255;
        v = Wa1[(size_t)k * (HH / 2) + n];
        split_store(v, g_wa1t_h + idx, g_wa1t_l + idx);
        break; }
    default: { // Wc [512,256] -> [256][512]
        if (idx >= HH * 2 * HH) return;
        int n = idx >> 9, k = idx & 511;
        v = Wc[(size_t)k * HH + n];
        split_store(v, g_wct_h + idx, g_wct_l + idx);
        break; }
    }
}

// ---------------- fused fills (m=-inf, denom=0, agg=0) ----------------
__global__ void fill_all() {
    const int T1 = RR * NN * NHD;                 // 2.4M
    const long T2 = (long)RR * NN * HH / 4;       // 19.2M float4
    long idx = (long)blockIdx.x * blockDim.x + threadIdx.x;
    if (idx < T1) {
        g_m[idx] = -INFINITY;
        g_denom[idx] = 0.f;
    } else {
        long j = idx - T1;
        if (j < T2) ((float4*)g_agg)[j] = make_float4(0.f, 0.f, 0.f, 0.f);
    }
}

// ---------------- gather (batched over all relations) ----------------
__global__ void gather_split(const float* __restrict__ x, const int* __restrict__ ei,
                             const float* __restrict__ ea) {
    long idx = (long)blockIdx.x * blockDim.x + threadIdx.x;
    const long perR = (long)EE * (KVP + HH);
    if (idx >= RR * perR) return;
    int r = (int)(idx / perR);
    long rem = idx - (long)r * perR;
    if (rem < (long)EE * KVP) {
        int e = (int)(rem / KVP), c = (int)(rem - (long)e * KVP);
        int src = ei[(r * 2 + 0) * EE + e];
        float v = (c < HH) ? x[(size_t)src * HH + c]
                : ((c < KVO) ? ea[((size_t)r * EE + e) * FF + (c - HH)] : 0.f);
        size_t o = ((size_t)r * EE + e) * KVP + c;
        split_store(v, g_kvin_h + o, g_kvin_l + o);
    } else {
        long j = rem - (long)EE * KVP;
        int e = (int)(j >> 8), c = (int)(j & 255);
        int dst = ei[(r * 2 + 1) * EE + e];
        size_t o = ((size_t)r * EE + e) * HH + c;
        split_store(x[(size_t)dst * HH + c], g_xd_h + o, g_xd_l + o);
    }
}

// ---------------- scores: one warp per (r, e), coalesced float4 loads ----------------
__global__ void scores_kernel(const int* __restrict__ ei, const float* __restrict__ prior) {
    int w = (blockIdx.x * blockDim.x + threadIdx.x) >> 5;
    int lane = threadIdx.x & 31;
    if (w >= RR * EE) return;
    int r = w >> 15, e = w & (EE - 1);
    const float4* q4 = (const float4*)g_qe + ((size_t)r * EE + e) * 64;
    const float4* k4 = (const float4*)g_k  + ((size_t)r * EE + e) * 64;
    float4 qa = q4[lane], ka = k4[lane];          // d in [4*lane, 4*lane+4)      head lane>>3
    float4 qb = q4[lane + 32], kb = k4[lane + 32];// d in [128+4*lane, ...)       head 4+(lane>>3)
    float p1 = qa.x * ka.x + qa.y * ka.y + qa.z * ka.z + qa.w * ka.w;
    float p2 = qb.x * kb.x + qb.y * kb.y + qb.z * kb.z + qb.w * kb.w;
#pragma unroll
    for (int off = 1; off < 8; off <<= 1) {
        p1 += __shfl_xor_sync(0xffffffff, p1, off);
        p2 += __shfl_xor_sync(0xffffffff, p2, off);
    }
    if ((lane & 7) == 0) {
        int dst = ei[(r * 2 + 1) * EE + e];
        int h1 = lane >> 3, h2 = h1 + 4;
        float s1 = p1 * 0.17677669529663687f * prior[r * NHD + h1];
        float s2 = p2 * 0.17677669529663687f * prior[r * NHD + h2];
        g_sc[((size_t)r * EE + e) * NHD + h1] = s1;
        g_sc[((size_t)r * EE + e) * NHD + h2] = s2;
        atomicMaxF(&g_m[((size_t)r * NN + dst) * NHD + h1], s1);
        atomicMaxF(&g_m[((size_t)r * NN + dst) * NHD + h2], s2);
    }
}

__global__ void ex_kernel(const int* __restrict__ ei) {
    int idx = blockIdx.x * blockDim.x + threadIdx.x;
    if (idx >= RR * EE * NHD) return;
    int r = idx >> 18;
    int e = (idx >> 3) & (EE - 1), h = idx & 7;
    int dst = ei[(r * 2 + 1) * EE + e];
    float exv = expf(g_sc[idx] - g_m[((size_t)r * NN + dst) * NHD + h]);
    g_sc[idx] = exv;
    atomicAdd(&g_denom[((size_t)r * NN + dst) * NHD + h], exv);
}

__global__ void agg_kernel(const int* __restrict__ ei) {
    long idx = (long)blockIdx.x * blockDim.x + threadIdx.x;
    if (idx >= (long)RR * EE * HH) return;
    int r = (int)(idx >> 23);
    long w_ = idx & ((1L << 23) - 1);
    int e = (int)(w_ >> 8), c = (int)(w_ & 255);
    int h = c >> 5;
    int dst = ei[(r * 2 + 1) * EE + e];
    float w = g_sc[((size_t)r * EE + e) * NHD + h] /
              (g_denom[((size_t)r * NN + dst) * NHD + h] + 1e-16f);
    atomicAdd(&g_agg[((size_t)r * NN + dst) * HH + c], w * g_v[idx]);
}

__global__ void agg_split_kernel() {
    long idx = (long)blockIdx.x * blockDim.x + threadIdx.x;
    if (idx >= (long)RR * NN * HH) return;
    int r = (int)(idx / ((long)NN * HH));
    long w_ = idx - (long)r * NN * HH;
    int n = (int)(w_ >> 8), c = (int)(w_ & 255);
    size_t o = ((size_t)r * NP + n) * HH + c;
    split_store(g_agg[idx], g_agg_h + o, g_agg_l + o);
}

__global__ void interw_kernel(const float* __restrict__ Wir2, const float* __restrict__ bir2) {
    int gwarp = (blockIdx.x * blockDim.x + threadIdx.x) >> 5;
    int lane = threadIdx.x & 31;
    if (gwarp >= NN) return;
    float acc[RR] = {};
    for (int k = lane; k < HH; k += 32) {
        float hv = g_hbuf[gwarp * HH + k];
#pragma unroll
        for (int rr = 0; rr < RR; rr++) acc[rr] += hv * Wir2[k * RR + rr];
    }
#pragma unroll
    for (int rr = 0; rr < RR; rr++)
#pragma unroll
        for (int off = 16; off; off >>= 1)
            acc[rr] += __shfl_down_sync(0xffffffff, acc[rr], off);
    if (lane == 0) {
        float mx = -1e30f;
#pragma unroll
        for (int rr = 0; rr < RR; rr++) { acc[rr] += bir2[rr]; mx = fmaxf(mx, acc[rr]); }
        float s = 0.f;
#pragma unroll
        for (int rr = 0; rr < RR; rr++) { acc[rr] = expf(acc[rr] - mx); s += acc[rr]; }
        float inv = 1.f / s;
#pragma unroll
        for (int rr = 0; rr < RR; rr++) g_interw[gwarp * NHD + rr] = acc[rr] * inv;
    }
}

// fused interagg + paths: one pass over rel_out
__global__ void postrel_kernel() {
    int idx = blockIdx.x * blockDim.x + threadIdx.x;
    if (idx >= NN * HH) return;
    int n = idx >> 8, c = idx & 255;
    float v[RR];
#pragma unroll
    for (int rr = 0; rr < RR; rr++) {
        size_t b = (size_t)n * RH + rr * HH + c;
        v[rr] = __bfloat162float(g_rel_h[b]) + __bfloat162float(g_rel_l[b]);
    }
    float s = 0.f;
#pragma unroll
    for (int rr = 0; rr < RR; rr++) s += g_interw[n * NHD + rr] * v[rr];
    split_store(s, g_cat_h + (size_t)n * 2 * HH + c, g_cat_l + (size_t)n * 2 * HH + c);
    split_store(v[2] + v[3], g_pth_h + ((size_t)0 * NP + n) * HH + c, g_pth_l + ((size_t)0 * NP + n) * HH + c);
    split_store(v[4] + v[0], g_pth_h + ((size_t)1 * NP + n) * HH + c, g_pth_l + ((size_t)1 * NP + n) * HH + c);
    split_store(v[1] + v[5], g_pth_h + ((size_t)2 * NP + n) * HH + c, g_pth_l + ((size_t)2 * NP + n) * HH + c);
}

__global__ void attnmeta_kernel(const float* __restrict__ Wa2,
                                const float* __restrict__ gm, const float* __restrict__ bm_) {
    __shared__ float lg[3];
    __shared__ float rbuf[256];
    int n = blockIdx.x, t = threadIdx.x;
    int lane = t & 31, w = t >> 5;
    if (w < 3) {
        float a = 0.f;
        for (int j = lane; j < 128; j += 32)
            a += g_t[((size_t)n * 3 + w) * 128 + j] * Wa2[j];
#pragma unroll
        for (int off = 16; off; off >>= 1) a += __shfl_down_sync(0xffffffff, a, off);
        if (lane == 0) lg[w] = a;
    }
    __syncthreads();
    float l0 = lg[0], l1 = lg[1], l2 = lg[2];
    float mx = fmaxf(l0, fmaxf(l1, l2));
    float e0 = expf(l0 - mx), e1 = expf(l1 - mx), e2 = expf(l2 - mx);
    float inv = 1.f / (e0 + e1 + e2);
    const float* st = g_stacked + (size_t)n * 3 * HH;
    float s = (e0 * st[t] + e1 * st[HH + t] + e2 * st[2 * HH + t]) * inv;
    rbuf[t] = s;
    __syncthreads();
    for (int off = 128; off; off >>= 1) { if (t < off) rbuf[t] += rbuf[t + off]; __syncthreads(); }
    float mu = rbuf[0] * (1.f / 256.f);
    __syncthreads();
    float d = s - mu;
    rbuf[t] = d * d;
    __syncthreads();
    for (int off = 128; off; off >>= 1) { if (t < off) rbuf[t] += rbuf[t + off]; __syncthreads(); }
    float var = rbuf[0] * (1.f / 256.f);
    float o = d * rsqrtf(var + 1e-5f) * gm[t] + bm_[t];
    split_store(o, g_cat_h + (size_t)n * 2 * HH + HH + t, g_cat_l + (size_t)n * 2 * HH + HH + t);
}

__global__ void outln_kernel(const float* __restrict__ x, const float* __restrict__ gout,
                             const float* __restrict__ bout, float* __restrict__ out) {
    __shared__ float rbuf[256];
    int n = blockIdx.x, t = threadIdx.x;
    float v = x[(size_t)n * HH + t] + g_hbuf[(size_t)n * HH + t];
    rbuf[t] = v;
    __syncthreads();
    for (int off = 128; off; off >>= 1) { if (t < off) rbuf[t] += rbuf[t + off]; __syncthreads(); }
    float mu = rbuf[0] * (1.f / 256.f);
    __syncthreads();
    float d = v - mu;
    rbuf[t] = d * d;
    __syncthreads();
    for (int off = 128; off; off >>= 1) { if (t < off) rbuf[t] += rbuf[t + off]; __syncthreads(); }
    float var = rbuf[0] * (1.f / 256.f);
    out[(size_t)n * HH + t] = d * rsqrtf(var + 1e-5f) * gout[t] + bout[t];
}

// ---------------- host ----------------
extern "C" void kernel_launch(void* const* d_in, const int* in_sizes, int n_in,
                              void* d_out, int out_size) {
    const float* x     = (const float*)d_in[0];
    const int*   ei    = (const int*)d_in[1];
    const float* ea    = (const float*)d_in[2];
    const float* Wq    = (const float*)d_in[3];
    const float* bq    = (const float*)d_in[4];
    const float* Wk    = (const float*)d_in[5];
    const float* bk    = (const float*)d_in[6];
    const float* Wv    = (const float*)d_in[7];
    const float* bv    = (const float*)d_in[8];
    const float* prior = (const float*)d_in[9];
    const float* Wm    = (const float*)d_in[10];
    const float* bm    = (const float*)d_in[11];
    const float* W_ir1 = (const float*)d_in[12];
    const float* b_ir1 = (const float*)d_in[13];
    const float* W_ir2 = (const float*)d_in[14];
    const float* b_ir2 = (const float*)d_in[15];
    const float* Wmp   = (const float*)d_in[16];
    const float* bmp   = (const float*)d_in[17];
    const float* Wa1   = (const float*)d_in[18];
    const float* ba1   = (const float*)d_in[19];
    const float* Wa2   = (const float*)d_in[20];
    const float* gmeta = (const float*)d_in[21];
    const float* bmeta = (const float*)d_in[22];
    const float* Wc    = (const float*)d_in[23];
    const float* bc    = (const float*)d_in[24];
    const float* gout  = (const float*)d_in[25];
    const float* bout  = (const float*)d_in[26];
    float* out = (float*)d_out;

    void* p;
#define SYM(v, s) cudaGetSymbolAddress(&p, s); auto* v = (decltype(&s[0]))p
    SYM(p_kvin_h, g_kvin_h);  SYM(p_kvin_l, g_kvin_l);
    SYM(p_xd_h, g_xd_h);      SYM(p_xd_l, g_xd_l);
    SYM(p_qe, g_qe); SYM(p_k, g_k); SYM(p_v, g_v);
    SYM(p_agg_h, g_agg_h);    SYM(p_agg_l, g_agg_l);
    SYM(p_rel_h, g_rel_h);    SYM(p_rel_l, g_rel_l);
    SYM(p_hbuf, g_hbuf);
    SYM(p_cat_h, g_cat_h);    SYM(p_cat_l, g_cat_l);
    SYM(p_pth_h, g_pth_h);    SYM(p_pth_l, g_pth_l);
    SYM(p_stacked, g_stacked);
    SYM(p_stk_h, g_stk_h);    SYM(p_stk_l, g_stk_l);
    SYM(p_t, g_t);
    SYM(p_wqt_h, g_wqt_h);    SYM(p_wqt_l, g_wqt_l);
    SYM(p_wkt_h, g_wkt_h);    SYM(p_wkt_l, g_wkt_l);
    SYM(p_wvt_h, g_wvt_h);    SYM(p_wvt_l, g_wvt_l);
    SYM(p_wmt_h, g_wmt_h);    SYM(p_wmt_l, g_wmt_l);
    SYM(p_wir1t_h, g_wir1t_h); SYM(p_wir1t_l, g_wir1t_l);
    SYM(p_wmpt_h, g_wmpt_h);  SYM(p_wmpt_l, g_wmpt_l);
    SYM(p_wa1t_h, g_wa1t_h);  SYM(p_wa1t_l, g_wa1t_l);
    SYM(p_wct_h, g_wct_h);    SYM(p_wct_l, g_wct_l);
#undef SYM

    const int SMB = 110592;
    cudaFuncSetAttribute((const void*)&tcmm<0, 0>, cudaFuncAttributeMaxDynamicSharedMemorySize, SMB);
    cudaFuncSetAttribute((const void*)&tcmm<1, 2>, cudaFuncAttributeMaxDynamicSharedMemorySize, SMB);
    cudaFuncSetAttribute((const void*)&tcmm<1, 0>, cudaFuncAttributeMaxDynamicSharedMemorySize, SMB);
    cudaFuncSetAttribute((const void*)&tcmm<0, 1>, cudaFuncAttributeMaxDynamicSharedMemorySize, SMB);
    cudaFuncSetAttribute((const void*)&tcmm<2, 0>, cudaFuncAttributeMaxDynamicSharedMemorySize, SMB);

    const int TB = 256;
    bf16* nb16 = nullptr;
    float* nf32 = nullptr;

    // 0: all weight transposes+splits in ONE launch
    tsplit_all<<<dim3((RR * HH * KVP + TB - 1) / TB, 8), TB>>>(Wq, Wk, Wv, Wm, W_ir1, Wmp, Wa1, Wc);
    // 1: all fills
    {
        long tot = (long)RR * NN * NHD + (long)RR * NN * HH / 4;
        fill_all<<<(int)((tot + TB - 1) / TB), TB>>>();
    }
    // 2: gather
    gather_split<<<(int)(((long)RR * EE * (KVP + HH) + TB - 1) / TB), TB>>>(x, ei, ea);

    // 3,4,5: q/k/v GEMMs (launch #5 = v — the ncu-profiled one)
    tcmm<0, 0><<<dim3(2, EE / 128, RR), 256, SMB>>>(
        p_xd_h, p_xd_l, (long)EE * HH,
        p_wqt_h, p_wqt_l, (long)HH * HH,
        bq, HH,
        p_qe, HH, 0, (long)EE * HH, 0,
        nb16, nb16, 0, 0, 0, 0, EE, HH);
    tcmm<0, 0><<<dim3(2, EE / 128, RR), 256, SMB>>>(
        p_kvin_h, p_kvin_l, (long)EE * KVP,
        p_wkt_h, p_wkt_l, (long)HH * KVP,
        bk, HH,
        p_k, HH, 0, (long)EE * HH, 0,
        nb16, nb16, 0, 0, 0, 0, EE, KVP);
    tcmm<0, 0><<<dim3(2, EE / 128, RR), 256, SMB>>>(
        p_kvin_h, p_kvin_l, (long)EE * KVP,
        p_wvt_h, p_wvt_l, (long)HH * KVP,
        bv, HH,
        p_v, HH, 0, (long)EE * HH, 0,
        nb16, nb16, 0, 0, 0, 0, EE, KVP);

    // 6-9: attention softmax + aggregation
    scores_kernel<<<RR * EE / 8, TB>>>(ei, prior);
    ex_kernel<<<RR * EE * NHD / TB, TB>>>(ei);
    agg_kernel<<<(int)(((long)RR * EE * HH) / TB), TB>>>(ei);
    agg_split_kernel<<<(int)(((long)RR * NN * HH + TB - 1) / TB), TB>>>();

    // 10: Wm GEMM -> rel_out
    tcmm<1, 2><<<dim3(2, NP / 128, RR), 256, SMB>>>(
        p_agg_h, p_agg_l, (long)NP * HH,
        p_wmt_h, p_wmt_l, (long)HH * HH,
        bm, HH,
        nf32, 0, 0, 0, 0,
        p_rel_h, p_rel_l, RH, 0, 0, HH, NN, HH);

    // 11-13: inter-relation attention + fused post-rel
    tcmm<1, 0><<<dim3(2, NP / 128, 1), 256, SMB>>>(
        p_rel_h, p_rel_l, 0,
        p_wir1t_h, p_wir1t_l, 0,
        b_ir1, 0,
        p_hbuf, HH, 0, 0, 0,
        nb16, nb16, 0, 0, 0, 0, NN, RH);
    interw_kernel<<<(NN * 32 + TB - 1) / TB, TB>>>(W_ir2, b_ir2);
    postrel_kernel<<<(NN * HH + TB - 1) / TB, TB>>>();

    // 14-16: meta paths
    tcmm<0, 1><<<dim3(2, NP / 128, 3), 256, SMB>>>(
        p_pth_h, p_pth_l, (long)NP * HH,
        p_wmpt_h, p_wmpt_l, (long)HH * HH,
        bmp, HH,
        p_stacked, 3 * HH, 0, 0, HH,
        p_stk_h, p_stk_l, 3 * HH, 0, 0, HH, NN, HH);
    tcmm<2, 0><<<dim3(1, (3 * NN + 127) / 128, 1), 256, SMB>>>(
        p_stk_h, p_stk_l, 0,
        p_wa1t_h, p_wa1t_l, 0,
        ba1, 0,
        p_t, HH / 2, 0, 0, 0,
        nb16, nb16, 0, 0, 0, 0, 3 * NN, HH);
    attnmeta_kernel<<<NN, TB>>>(Wa2, gmeta, bmeta);

    // 17-18: combine + output LN
    tcmm<1, 0><<<dim3(2, NP / 128, 1), 256, SMB>>>(
        p_cat_h, p_cat_l, 0,
        p_wct_h, p_wct_l, 0,
        bc, 0,
        p_hbuf, HH, 0, 0, 0,
        nb16, nb16, 0, 0, 0, 0, NN, 2 * HH);
    outln_kernel<<<NN, TB>>>(x, gout, bout, out);
}

// round 8
// speedup vs baseline: 1.3511x; 1.0208x over previous
#include <cuda_runtime.h>
#include <cuda_bf16.h>
#include <math.h>
#include <stdint.h>

#define NN 50000
#define NP 50048          // NN padded to 128
#define RR 6
#define EE 32768
#define HH 256
#define FF 16
#define KVO 272
#define KVP 320           // 272 padded to 64-multiple
#define NHD 8
#define HDD 32
#define RH 1536

typedef __nv_bfloat16 bf16;

#if defined(__CUDA_ARCH__) && (defined(__CUDA_ARCH_FEAT_SM103_ALL) \
    || (defined(__CUDA_ARCH_SPECIFIC__) && (__CUDA_ARCH_SPECIFIC__ == 1030)) \
    || (defined(__CUDA_ARCH_FAMILY_SPECIFIC__) && (__CUDA_ARCH_FAMILY_SPECIFIC__ == 1030)))
#define HAS_TC05 1
#else
#define HAS_TC05 0
#endif

// ---------------- scratch (device globals; zero-initialized at load) ----------------
__device__ __align__(1024) bf16 g_kvin_h[RR * EE * KVP], g_kvin_l[RR * EE * KVP];
__device__ __align__(1024) bf16 g_xd_h[RR * EE * HH],   g_xd_l[RR * EE * HH];
__device__ float g_qe[(size_t)RR * EE * HH], g_k[(size_t)RR * EE * HH], g_v[(size_t)RR * EE * HH];
__device__ float g_sc[RR * EE * NHD], g_m[RR * NN * NHD], g_denom[RR * NN * NHD];
__device__ float g_agg[(size_t)RR * NN * HH];
__device__ __align__(1024) bf16 g_agg_h[(size_t)RR * NP * HH], g_agg_l[(size_t)RR * NP * HH];
__device__ __align__(1024) bf16 g_rel_h[(size_t)NP * RH], g_rel_l[(size_t)NP * RH];
__device__ float g_hbuf[NP * HH];
__device__ float g_interw[NN * NHD];
__device__ __align__(1024) bf16 g_cat_h[NP * 2 * HH], g_cat_l[NP * 2 * HH];
__device__ __align__(1024) bf16 g_pth_h[3 * NP * HH], g_pth_l[3 * NP * HH];
__device__ float g_stacked[NP * 3 * HH];
__device__ __align__(1024) bf16 g_stk_h[NP * 3 * HH], g_stk_l[NP * 3 * HH];
__device__ float g_t[3 * NP * (HH / 2)];
// transposed + split weights: [Ncol][Kpad]
__device__ __align__(1024) bf16 g_wqt_h[RR * HH * HH],  g_wqt_l[RR * HH * HH];
__device__ __align__(1024) bf16 g_wkt_h[RR * HH * KVP], g_wkt_l[RR * HH * KVP];
__device__ __align__(1024) bf16 g_wvt_h[RR * HH * KVP], g_wvt_l[RR * HH * KVP];
__device__ __align__(1024) bf16 g_wmt_h[RR * HH * HH],  g_wmt_l[RR * HH * HH];
__device__ __align__(1024) bf16 g_wir1t_h[HH * RH],     g_wir1t_l[HH * RH];
__device__ __align__(1024) bf16 g_wmpt_h[3 * HH * HH],  g_wmpt_l[3 * HH * HH];
__device__ __align__(1024) bf16 g_wa1t_h[(HH/2) * HH],  g_wa1t_l[(HH/2) * HH];
__device__ __align__(1024) bf16 g_wct_h[HH * 2 * HH],   g_wct_l[HH * 2 * HH];

// ---------------- common helpers ----------------
__device__ __forceinline__ float gelu_exact(float x) {
    return 0.5f * x * (1.0f + erff(x * 0.7071067811865475f));
}
__device__ __forceinline__ void split_store(float v, bf16* ph, bf16* pl) {
    bf16 h = __float2bfloat16(v);
    *ph = h;
    *pl = __float2bfloat16(v - __bfloat162float(h));
}
__device__ __forceinline__ void atomicMaxF(float* addr, float v) {
    int* ai = (int*)addr;
    int old = *ai;
    while (__int_as_float(old) < v) {
        int assumed = old;
        old = atomicCAS(ai, assumed, __float_as_int(v));
        if (old == assumed) break;
    }
}
__device__ __forceinline__ uint32_t smem_u32(const void* p) {
    uint32_t a;
    asm("{ .reg .u64 t; cvta.to.shared.u64 t, %1; cvt.u32.u64 %0, t; }" : "=r"(a) : "l"(p));
    return a;
}
#define CP_ASYNC16(dst, src) \
    asm volatile("cp.async.cg.shared.global [%0], [%1], 16;" :: "r"(dst), "l"(src))
#define CP_COMMIT() asm volatile("cp.async.commit_group;")
#define CP_WAIT1()  asm volatile("cp.async.wait_group 1;")
#define CP_WAIT0()  asm volatile("cp.async.wait_group 0;")

#if HAS_TC05
#define SWZ128(o) ((o) ^ (((o) >> 3) & 0x70))
__device__ __forceinline__ uint64_t mkdesc(uint32_t addr) {
    return ((uint64_t)2 << 61) | ((uint64_t)1 << 46) | ((uint64_t)64 << 32) |
           ((uint64_t)1 << 16) | ((addr >> 4) & 0x3FFF);
}
__device__ __forceinline__ void mma_f16_ss(uint32_t d, uint64_t ad, uint64_t bd,
                                           uint32_t idesc, bool acc) {
    uint32_t en = acc ? 1u : 0u;
    asm volatile(
        "{\n\t.reg .pred p;\n\tsetp.ne.u32 p, %5, 0;\n\t"
        "tcgen05.mma.cta_group::1.kind::f16 [%0], %1, %2, %3, {%4,%4,%4,%4}, p;\n\t}"
        :: "r"(d), "l"(ad), "l"(bd), "r"(idesc), "r"(0u), "r"(en) : "memory");
}
__device__ __forceinline__ void mbar_init(uint32_t mb, uint32_t cnt) {
    asm volatile("mbarrier.init.shared.b64 [%0], %1;" :: "r"(mb), "r"(cnt) : "memory");
}
__device__ __forceinline__ void mbar_wait(uint32_t mb, int parity) {
    asm volatile(
        "{\n\t.reg .pred P1;\n\t"
        "WL_%=:\n\t"
        "mbarrier.try_wait.parity.acquire.cta.shared::cta.b64 P1, [%0], %1, 0x989680;\n\t"
        "@P1 bra.uni WD_%=;\n\t"
        "bra.uni WL_%=;\n\t"
        "WD_%=:\n\t}"
        :: "r"(mb), "r"(parity) : "memory");
}
#define LDTM_X32(r, a) \
    asm volatile( \
        "tcgen05.ld.sync.aligned.32x32b.x32.b32 " \
        "{%0, %1, %2, %3, %4, %5, %6, %7, " \
        " %8, %9, %10, %11, %12, %13, %14, %15, " \
        " %16, %17, %18, %19, %20, %21, %22, %23, " \
        " %24, %25, %26, %27, %28, %29, %30, %31}, [%32];" \
        : "=r"((r)[0]),  "=r"((r)[1]),  "=r"((r)[2]),  "=r"((r)[3]), \
          "=r"((r)[4]),  "=r"((r)[5]),  "=r"((r)[6]),  "=r"((r)[7]), \
          "=r"((r)[8]),  "=r"((r)[9]),  "=r"((r)[10]), "=r"((r)[11]), \
          "=r"((r)[12]), "=r"((r)[13]), "=r"((r)[14]), "=r"((r)[15]), \
          "=r"((r)[16]), "=r"((r)[17]), "=r"((r)[18]), "=r"((r)[19]), \
          "=r"((r)[20]), "=r"((r)[21]), "=r"((r)[22]), "=r"((r)[23]), \
          "=r"((r)[24]), "=r"((r)[25]), "=r"((r)[26]), "=r"((r)[27]), \
          "=r"((r)[28]), "=r"((r)[29]), "=r"((r)[30]), "=r"((r)[31]) \
        : "r"(a))
#else
__device__ __forceinline__ void hmma16816(float* c, const uint32_t* a, const uint32_t* b) {
    asm volatile(
        "mma.sync.aligned.m16n8k16.row.col.f32.bf16.bf16.f32 "
        "{%0,%1,%2,%3}, {%4,%5,%6,%7}, {%8,%9}, {%0,%1,%2,%3};"
        : "+f"(c[0]), "+f"(c[1]), "+f"(c[2]), "+f"(c[3])
        : "r"(a[0]), "r"(a[1]), "r"(a[2]), "r"(a[3]), "r"(b[0]), "r"(b[1]));
}
#define LDSM_X4(r, addr) \
    asm volatile("ldmatrix.sync.aligned.m8n8.x4.shared.b16 {%0,%1,%2,%3}, [%4];" \
        : "=r"((r)[0]), "=r"((r)[1]), "=r"((r)[2]), "=r"((r)[3]) : "r"(addr))
#endif

// ---------------- bf16x3 GEMM (z-batched) ----------------
// Block tile 128x128; 2-stage cp.async pipeline sized for 2 CTAs/SM.
template <int ACT, int STORE>
__global__ __launch_bounds__(256, 2)
void tcmm(const bf16* __restrict__ Ah, const bf16* __restrict__ Al, long az,
          const bf16* __restrict__ Bh, const bf16* __restrict__ Bl, long bz,
          const float* __restrict__ bias, int biasz,
          float* __restrict__ C, int ldc, int coff, long cz, int coffz,
          bf16* __restrict__ Ch, bf16* __restrict__ Cl, int ldh, int offh,
          long chz, int offhz,
          int M, int K) {
    extern __shared__ char smem[];
    const int tid = threadIdx.x, wid = tid >> 5, lid = tid & 31;
    const int m0 = blockIdx.y * 128;
    const int n0 = blockIdx.x * 128;
    const int z = blockIdx.z;
    Ah += (size_t)z * az;  Al += (size_t)z * az;
    Bh += (size_t)z * bz;  Bl += (size_t)z * bz;
    bias += (size_t)z * biasz;
    if (STORE != 2) { C += (size_t)z * cz; coff += z * coffz; }
    if (STORE != 0) { Ch += (size_t)z * chz; Cl += (size_t)z * chz; offh += z * offhz; }

#if HAS_TC05
    // ================= tcgen05 path =================
    const uint32_t sb = smem_u32(smem);
    const int ABYTES = 128 * 128;
    const int BUF = 2 * ABYTES;
    const uint32_t mbar0 = sb + 8, mbar1 = sb + 16;
    const uint32_t buf0 = sb + 1024;

    if (wid == 0) {
        asm volatile("tcgen05.alloc.cta_group::1.sync.aligned.shared::cta.b32 [%0], %1;"
                     :: "r"(sb), "r"(128u) : "memory");
        asm volatile("tcgen05.relinquish_alloc_permit.cta_group::1.sync.aligned;");
    }
    __syncthreads();
    uint32_t tmem;
    asm volatile("ld.shared.b32 %0, [%1];" : "=r"(tmem) : "r"(sb));
    if (tid == 0) { mbar_init(mbar0, 1); mbar_init(mbar1, 1); }
    __syncthreads();

    const int KC = K >> 6;
    const int T = KC * 3;
    const uint32_t idesc64 = (1u << 4) | (1u << 7) | (1u << 10) | (8u << 17) | (8u << 24);

    auto load_chunk = [&](int c, uint32_t bufbase) {
        int p = c / KC, kc = (c - p * KC) << 6;
        const bf16* Ap = (p == 2) ? Al : Ah;
        const bf16* Bp = (p == 1) ? Bl : Bh;
        for (int i = tid; i < 2048; i += 256) {
            uint32_t dst;
            const bf16* src;
            if (i < 1024) {
                int r = i >> 3, g = i & 7;
                dst = bufbase + SWZ128(r * 128 + g * 16);
                src = Ap + (size_t)(m0 + r) * K + kc + g * 8;
            } else {
                int j = i - 1024;
                int r = j >> 3, g = j & 7;
                dst = bufbase + ABYTES + SWZ128(r * 128 + g * 16);
                src = Bp + (size_t)(n0 + r) * K + kc + g * 8;
            }
            CP_ASYNC16(dst, src);
        }
        CP_COMMIT();
    };

    int ph0 = 0, ph1 = 0;
    load_chunk(0, buf0);
    for (int c = 0; c < T; c++) {
        int b = c & 1;
        if (c + 1 < T) {
            int nb = b ^ 1;
            if (c >= 1) {
                if (nb) { mbar_wait(mbar1, ph1); ph1 ^= 1; }
                else    { mbar_wait(mbar0, ph0); ph0 ^= 1; }
            }
            load_chunk(c + 1, buf0 + nb * BUF);
            CP_WAIT1();
        } else {
            CP_WAIT0();
        }
        __syncthreads();
        if (tid == 0) {
            asm volatile("fence.proxy.async.shared::cta;" ::: "memory");
            uint64_t ad = mkdesc(buf0 + b * BUF);
            uint64_t bd = mkdesc(buf0 + b * BUF + ABYTES);
#pragma unroll
            for (int ks = 0; ks < 4; ks++)
#pragma unroll
                for (int ns = 0; ns < 2; ns++)
                    mma_f16_ss(tmem + ns * 64, ad + ks * 2, bd + ns * 512 + ks * 2,
                               idesc64, (c > 0) || (ks > 0));
            asm volatile("tcgen05.commit.cta_group::1.mbarrier::arrive::one.shared::cluster.b64 [%0];"
                         :: "r"(b ? mbar1 : mbar0) : "memory");
        }
    }
    {
        int lb = (T - 1) & 1;
        if (lb) mbar_wait(mbar1, ph1); else mbar_wait(mbar0, ph0);
    }
    asm volatile("tcgen05.fence::after_thread_sync;" ::: "memory");

    {
        int row = m0 + (wid & 3) * 32 + lid;
        int colbase = (wid >> 2) * 64;
        for (int cb = 0; cb < 64; cb += 32) {
            uint32_t regs[32];
            LDTM_X32(regs, tmem + colbase + cb);
            asm volatile("tcgen05.wait::ld.sync.aligned;" ::: "memory");
            if (row < M) {
#pragma unroll
                for (int j = 0; j < 32; j++) {
                    int col = n0 + colbase + cb + j;
                    float v = __uint_as_float(regs[j]) + bias[col];
                    if (ACT == 1) v = gelu_exact(v);
                    else if (ACT == 2) v = tanhf(v);
                    if (STORE != 2) C[(size_t)row * ldc + coff + col] = v;
                    if (STORE != 0)
                        split_store(v, Ch + (size_t)row * ldh + offh + col,
                                       Cl + (size_t)row * ldh + offh + col);
                }
            }
        }
    }
    __syncthreads();
    if (wid == 0)
        asm volatile("tcgen05.dealloc.cta_group::1.sync.aligned.b32 %0, %1;"
                     :: "r"(tmem), "r"(128u));

#else
    // ================= ldmatrix + mma.sync path (2-stage, 2 CTAs/SM) =================
    const uint32_t sm_u = smem_u32(smem);
    const int STG = 36864;               // A 128x144B + B 128x144B
    const int g = lid >> 2, tig = lid & 3;
    const int wr = wid >> 2, wc = wid & 3;
    const int rowbase = wr * 64, colbase = wc * 32;
    const int KC64 = K >> 6;
    const int S = KC64 * 3;

    const uint32_t a_lane = (uint32_t)(rowbase + (lid & 15)) * 144 + ((lid >> 4) << 4);
    const uint32_t b_lane = (uint32_t)(colbase + (lid & 7) + (((lid >> 4) & 1) << 3)) * 144
                          + (((lid >> 3) & 1) << 4);

    auto load_stage = [&](int s, int buf) {
        int p = s / KC64, k0 = (s - p * KC64) << 6;
        const bf16* Ap = (p == 2) ? Al : Ah;
        const bf16* Bp = (p == 1) ? Bl : Bh;
        uint32_t ab = sm_u + buf * STG, bb = ab + 18432;
#pragma unroll
        for (int rep = 0; rep < 4; rep++) {
            int i = tid + 256 * rep;
            int r = i >> 3, sc = i & 7;
            CP_ASYNC16(ab + r * 144 + sc * 16, Ap + (size_t)(m0 + r) * K + k0 + sc * 8);
        }
#pragma unroll
        for (int rep = 0; rep < 4; rep++) {
            int i = tid + 256 * rep;
            int r = i >> 3, sc = i & 7;
            CP_ASYNC16(bb + r * 144 + sc * 16, Bp + (size_t)(n0 + r) * K + k0 + sc * 8);
        }
        CP_COMMIT();
    };

    float acc[4][4][4];
#pragma unroll
    for (int mf = 0; mf < 4; mf++)
#pragma unroll
        for (int nf = 0; nf < 4; nf++)
#pragma unroll
            for (int q = 0; q < 4; q++) acc[mf][nf][q] = 0.f;

    load_stage(0, 0);
    for (int s = 0; s < S; s++) {
        if (s + 1 < S) { load_stage(s + 1, (s + 1) & 1); CP_WAIT1(); }
        else CP_WAIT0();
        __syncthreads();
        uint32_t ab = sm_u + (s & 1) * STG;
        uint32_t bb = ab + 18432;
#pragma unroll
        for (int kk = 0; kk < 64; kk += 16) {
            uint32_t afr[4][4], bfr[2][4];
#pragma unroll
            for (int mf = 0; mf < 4; mf++)
                LDSM_X4(afr[mf], ab + a_lane + mf * 2304 + kk * 2);
#pragma unroll
            for (int np = 0; np < 2; np++)
                LDSM_X4(bfr[np], bb + b_lane + np * 2304 + kk * 2);
#pragma unroll
            for (int mf = 0; mf < 4; mf++)
#pragma unroll
                for (int nf = 0; nf < 4; nf++)
                    hmma16816(acc[mf][nf], afr[mf], &bfr[nf >> 1][(nf & 1) * 2]);
        }
        __syncthreads();
    }

#pragma unroll
    for (int mf = 0; mf < 4; mf++)
#pragma unroll
        for (int nf = 0; nf < 4; nf++) {
            int col0 = n0 + colbase + nf * 8 + 2 * tig;
#pragma unroll
            for (int r8 = 0; r8 < 2; r8++) {
                int row = m0 + rowbase + mf * 16 + g + r8 * 8;
                if (row < M) {
#pragma unroll
                    for (int cc = 0; cc < 2; cc++) {
                        int col = col0 + cc;
                        float v = acc[mf][nf][r8 * 2 + cc] + bias[col];
                        if (ACT == 1) v = gelu_exact(v);
                        else if (ACT == 2) v = tanhf(v);
                        if (STORE != 2) C[(size_t)row * ldc + coff + col] = v;
                        if (STORE != 0)
                            split_store(v, Ch + (size_t)row * ldh + offh + col,
                                           Cl + (size_t)row * ldh + offh + col);
                    }
                }
            }
        }
#endif
}

// ---------------- fused weight transpose+split (ALL weights, 1 launch) ----------------
__global__ void tsplit_all(const float* __restrict__ Wq, const float* __restrict__ Wk,
                           const float* __restrict__ Wv, const float* __restrict__ Wm,
                           const float* __restrict__ Wir1, const float* __restrict__ Wmp,
                           const float* __restrict__ Wa1, const float* __restrict__ Wc) {
    int idx = blockIdx.x * blockDim.x + threadIdx.x;
    int seg = blockIdx.y;
    float v;
    switch (seg) {
    case 0: {
        if (idx >= RR * HH * HH) return;
        int z = idx >> 16, w = idx & 65535, n = w >> 8, k = w & 255;
        v = Wq[(size_t)z * 65536 + k * HH + n];
        split_store(v, g_wqt_h + idx, g_wqt_l + idx);
        break; }
    case 1: {
        if (idx >= RR * HH * KVP) return;
        int z = idx / 81920, w = idx - z * 81920, n = w / KVP, k = w - n * KVP;
        v = (k < KVO) ? Wk[(size_t)z * KVO * HH + k * HH + n] : 0.f;
        split_store(v, g_wkt_h + idx, g_wkt_l + idx);
        break; }
    case 2: {
        if (idx >= RR * HH * KVP) return;
        int z = idx / 81920, w = idx - z * 81920, n = w / KVP, k = w - n * KVP;
        v = (k < KVO) ? Wv[(size_t)z * KVO * HH + k * HH + n] : 0.f;
        split_store(v, g_wvt_h + idx, g_wvt_l + idx);
        break; }
    case 3: {
        if (idx >= RR * HH * HH) return;
        int z = idx >> 16, w = idx & 65535, n = w >> 8, k = w & 255;
        v = Wm[(size_t)z * 65536 + k * HH + n];
        split_store(v, g_wmt_h + idx, g_wmt_l + idx);
        break; }
    case 4: {
        if (idx >= HH * RH) return;
        int n = idx / RH, k = idx - n * RH;
        v = Wir1[(size_t)k * HH + n];
        split_store(v, g_wir1t_h + idx, g_wir1t_l + idx);
        break; }
    case 5: {
        if (idx >= 3 * HH * HH) return;
        int z = idx >> 16, w = idx & 65535, n = w >> 8, k = w & 255;
        v = Wmp[(size_t)z * 65536 + k * HH + n];
        split_store(v, g_wmpt_h + idx, g_wmpt_l + idx);
        break; }
    case 6: {
        if (idx >= (HH / 2) * HH) return;
        int n = idx >> 8, k = idx & 255;
        v = Wa1[(size_t)k * (HH / 2) + n];
        split_store(v, g_wa1t_h + idx, g_wa1t_l + idx);
        break; }
    default: {
        if (idx >= HH * 2 * HH) return;
        int n = idx >> 9, k = idx & 511;
        v = Wc[(size_t)k * HH + n];
        split_store(v, g_wct_h + idx, g_wct_l + idx);
        break; }
    }
}

// ---------------- fused fills ----------------
__global__ void fill_all() {
    const int T1 = RR * NN * NHD;
    const long T2 = (long)RR * NN * HH / 4;
    long idx = (long)blockIdx.x * blockDim.x + threadIdx.x;
    if (idx < T1) {
        g_m[idx] = -INFINITY;
        g_denom[idx] = 0.f;
    } else {
        long j = idx - T1;
        if (j < T2) ((float4*)g_agg)[j] = make_float4(0.f, 0.f, 0.f, 0.f);
    }
}

// ---------------- gather (batched over all relations) ----------------
__global__ void gather_split(const float* __restrict__ x, const int* __restrict__ ei,
                             const float* __restrict__ ea) {
    long idx = (long)blockIdx.x * blockDim.x + threadIdx.x;
    const long perR = (long)EE * (KVP + HH);
    if (idx >= RR * perR) return;
    int r = (int)(idx / perR);
    long rem = idx - (long)r * perR;
    if (rem < (long)EE * KVP) {
        int e = (int)(rem / KVP), c = (int)(rem - (long)e * KVP);
        int src = ei[(r * 2 + 0) * EE + e];
        float v = (c < HH) ? x[(size_t)src * HH + c]
                : ((c < KVO) ? ea[((size_t)r * EE + e) * FF + (c - HH)] : 0.f);
        size_t o = ((size_t)r * EE + e) * KVP + c;
        split_store(v, g_kvin_h + o, g_kvin_l + o);
    } else {
        long j = rem - (long)EE * KVP;
        int e = (int)(j >> 8), c = (int)(j & 255);
        int dst = ei[(r * 2 + 1) * EE + e];
        size_t o = ((size_t)r * EE + e) * HH + c;
        split_store(x[(size_t)dst * HH + c], g_xd_h + o, g_xd_l + o);
    }
}

// ---------------- scores: warp per (r, e), coalesced float4 ----------------
__global__ void scores_kernel(const int* __restrict__ ei, const float* __restrict__ prior) {
    int w = (blockIdx.x * blockDim.x + threadIdx.x) >> 5;
    int lane = threadIdx.x & 31;
    if (w >= RR * EE) return;
    int r = w >> 15, e = w & (EE - 1);
    const float4* q4 = (const float4*)g_qe + ((size_t)r * EE + e) * 64;
    const float4* k4 = (const float4*)g_k  + ((size_t)r * EE + e) * 64;
    float4 qa = q4[lane], ka = k4[lane];
    float4 qb = q4[lane + 32], kb = k4[lane + 32];
    float p1 = qa.x * ka.x + qa.y * ka.y + qa.z * ka.z + qa.w * ka.w;
    float p2 = qb.x * kb.x + qb.y * kb.y + qb.z * kb.z + qb.w * kb.w;
#pragma unroll
    for (int off = 1; off < 8; off <<= 1) {
        p1 += __shfl_xor_sync(0xffffffff, p1, off);
        p2 += __shfl_xor_sync(0xffffffff, p2, off);
    }
    if ((lane & 7) == 0) {
        int dst = ei[(r * 2 + 1) * EE + e];
        int h1 = lane >> 3, h2 = h1 + 4;
        float s1 = p1 * 0.17677669529663687f * prior[r * NHD + h1];
        float s2 = p2 * 0.17677669529663687f * prior[r * NHD + h2];
        g_sc[((size_t)r * EE + e) * NHD + h1] = s1;
        g_sc[((size_t)r * EE + e) * NHD + h2] = s2;
        atomicMaxF(&g_m[((size_t)r * NN + dst) * NHD + h1], s1);
        atomicMaxF(&g_m[((size_t)r * NN + dst) * NHD + h2], s2);
    }
}

__global__ void ex_kernel(const int* __restrict__ ei) {
    int idx = blockIdx.x * blockDim.x + threadIdx.x;
    if (idx >= RR * EE * NHD) return;
    int r = idx >> 18;
    int e = (idx >> 3) & (EE - 1), h = idx & 7;
    int dst = ei[(r * 2 + 1) * EE + e];
    float exv = expf(g_sc[idx] - g_m[((size_t)r * NN + dst) * NHD + h]);
    g_sc[idx] = exv;
    atomicAdd(&g_denom[((size_t)r * NN + dst) * NHD + h], exv);
}

__global__ void agg_kernel(const int* __restrict__ ei) {
    long idx = (long)blockIdx.x * blockDim.x + threadIdx.x;
    if (idx >= (long)RR * EE * HH) return;
    int r = (int)(idx >> 23);
    long w_ = idx & ((1L << 23) - 1);
    int e = (int)(w_ >> 8), c = (int)(w_ & 255);
    int h = c >> 5;
    int dst = ei[(r * 2 + 1) * EE + e];
    float w = g_sc[((size_t)r * EE + e) * NHD + h] /
              (g_denom[((size_t)r * NN + dst) * NHD + h] + 1e-16f);
    atomicAdd(&g_agg[((size_t)r * NN + dst) * HH + c], w * g_v[idx]);
}

__global__ void agg_split_kernel() {
    long idx = (long)blockIdx.x * blockDim.x + threadIdx.x;
    if (idx >= (long)RR * NN * HH) return;
    int r = (int)(idx / ((long)NN * HH));
    long w_ = idx - (long)r * NN * HH;
    int n = (int)(w_ >> 8), c = (int)(w_ & 255);
    size_t o = ((size_t)r * NP + n) * HH + c;
    split_store(g_agg[idx], g_agg_h + o, g_agg_l + o);
}

__global__ void interw_kernel(const float* __restrict__ Wir2, const float* __restrict__ bir2) {
    int gwarp = (blockIdx.x * blockDim.x + threadIdx.x) >> 5;
    int lane = threadIdx.x & 31;
    if (gwarp >= NN) return;
    float acc[RR] = {};
    for (int k = lane; k < HH; k += 32) {
        float hv = g_hbuf[gwarp * HH + k];
#pragma unroll
        for (int rr = 0; rr < RR; rr++) acc[rr] += hv * Wir2[k * RR + rr];
    }
#pragma unroll
    for (int rr = 0; rr < RR; rr++)
#pragma unroll
        for (int off = 16; off; off >>= 1)
            acc[rr] += __shfl_down_sync(0xffffffff, acc[rr], off);
    if (lane == 0) {
        float mx = -1e30f;
#pragma unroll
        for (int rr = 0; rr < RR; rr++) { acc[rr] += bir2[rr]; mx = fmaxf(mx, acc[rr]); }
        float s = 0.f;
#pragma unroll
        for (int rr = 0; rr < RR; rr++) { acc[rr] = expf(acc[rr] - mx); s += acc[rr]; }
        float inv = 1.f / s;
#pragma unroll
        for (int rr = 0; rr < RR; rr++) g_interw[gwarp * NHD + rr] = acc[rr] * inv;
    }
}

// fused interagg + paths
__global__ void postrel_kernel() {
    int idx = blockIdx.x * blockDim.x + threadIdx.x;
    if (idx >= NN * HH) return;
    int n = idx >> 8, c = idx & 255;
    float v[RR];
#pragma unroll
    for (int rr = 0; rr < RR; rr++) {
        size_t b = (size_t)n * RH + rr * HH + c;
        v[rr] = __bfloat162float(g_rel_h[b]) + __bfloat162float(g_rel_l[b]);
    }
    float s = 0.f;
#pragma unroll
    for (int rr = 0; rr < RR; rr++) s += g_interw[n * NHD + rr] * v[rr];
    split_store(s, g_cat_h + (size_t)n * 2 * HH + c, g_cat_l + (size_t)n * 2 * HH + c);
    split_store(v[2] + v[3], g_pth_h + ((size_t)0 * NP + n) * HH + c, g_pth_l + ((size_t)0 * NP + n) * HH + c);
    split_store(v[4] + v[0], g_pth_h + ((size_t)1 * NP + n) * HH + c, g_pth_l + ((size_t)1 * NP + n) * HH + c);
    split_store(v[1] + v[5], g_pth_h + ((size_t)2 * NP + n) * HH + c, g_pth_l + ((size_t)2 * NP + n) * HH + c);
}

__global__ void attnmeta_kernel(const float* __restrict__ Wa2,
                                const float* __restrict__ gm, const float* __restrict__ bm_) {
    __shared__ float lg[3];
    __shared__ float rbuf[256];
    int n = blockIdx.x, t = threadIdx.x;
    int lane = t & 31, w = t >> 5;
    if (w < 3) {
        float a = 0.f;
        for (int j = lane; j < 128; j += 32)
            a += g_t[((size_t)n * 3 + w) * 128 + j] * Wa2[j];
#pragma unroll
        for (int off = 16; off; off >>= 1) a += __shfl_down_sync(0xffffffff, a, off);
        if (lane == 0) lg[w] = a;
    }
    __syncthreads();
    float l0 = lg[0], l1 = lg[1], l2 = lg[2];
    float mx = fmaxf(l0, fmaxf(l1, l2));
    float e0 = expf(l0 - mx), e1 = expf(l1 - mx), e2 = expf(l2 - mx);
    float inv = 1.f / (e0 + e1 + e2);
    const float* st = g_stacked + (size_t)n * 3 * HH;
    float s = (e0 * st[t] + e1 * st[HH + t] + e2 * st[2 * HH + t]) * inv;
    rbuf[t] = s;
    __syncthreads();
    for (int off = 128; off; off >>= 1) { if (t < off) rbuf[t] += rbuf[t + off]; __syncthreads(); }
    float mu = rbuf[0] * (1.f / 256.f);
    __syncthreads();
    float d = s - mu;
    rbuf[t] = d * d;
    __syncthreads();
    for (int off = 128; off; off >>= 1) { if (t < off) rbuf[t] += rbuf[t + off]; __syncthreads(); }
    float var = rbuf[0] * (1.f / 256.f);
    float o = d * rsqrtf(var + 1e-5f) * gm[t] + bm_[t];
    split_store(o, g_cat_h + (size_t)n * 2 * HH + HH + t, g_cat_l + (size_t)n * 2 * HH + HH + t);
}

__global__ void outln_kernel(const float* __restrict__ x, const float* __restrict__ gout,
                             const float* __restrict__ bout, float* __restrict__ out) {
    __shared__ float rbuf[256];
    int n = blockIdx.x, t = threadIdx.x;
    float v = x[(size_t)n * HH + t] + g_hbuf[(size_t)n * HH + t];
    rbuf[t] = v;
    __syncthreads();
    for (int off = 128; off; off >>= 1) { if (t < off) rbuf[t] += rbuf[t + off]; __syncthreads(); }
    float mu = rbuf[0] * (1.f / 256.f);
    __syncthreads();
    float d = v - mu;
    rbuf[t] = d * d;
    __syncthreads();
    for (int off = 128; off; off >>= 1) { if (t < off) rbuf[t] += rbuf[t + off]; __syncthreads(); }
    float var = rbuf[0] * (1.f / 256.f);
    out[(size_t)n * HH + t] = d * rsqrtf(var + 1e-5f) * gout[t] + bout[t];
}

// ---------------- host ----------------
extern "C" void kernel_launch(void* const* d_in, const int* in_sizes, int n_in,
                              void* d_out, int out_size) {
    const float* x     = (const float*)d_in[0];
    const int*   ei    = (const int*)d_in[1];
    const float* ea    = (const float*)d_in[2];
    const float* Wq    = (const float*)d_in[3];
    const float* bq    = (const float*)d_in[4];
    const float* Wk    = (const float*)d_in[5];
    const float* bk    = (const float*)d_in[6];
    const float* Wv    = (const float*)d_in[7];
    const float* bv    = (const float*)d_in[8];
    const float* prior = (const float*)d_in[9];
    const float* Wm    = (const float*)d_in[10];
    const float* bm    = (const float*)d_in[11];
    const float* W_ir1 = (const float*)d_in[12];
    const float* b_ir1 = (const float*)d_in[13];
    const float* W_ir2 = (const float*)d_in[14];
    const float* b_ir2 = (const float*)d_in[15];
    const float* Wmp   = (const float*)d_in[16];
    const float* bmp   = (const float*)d_in[17];
    const float* Wa1   = (const float*)d_in[18];
    const float* ba1   = (const float*)d_in[19];
    const float* Wa2   = (const float*)d_in[20];
    const float* gmeta = (const float*)d_in[21];
    const float* bmeta = (const float*)d_in[22];
    const float* Wc    = (const float*)d_in[23];
    const float* bc    = (const float*)d_in[24];
    const float* gout  = (const float*)d_in[25];
    const float* bout  = (const float*)d_in[26];
    float* out = (float*)d_out;

    void* p;
#define SYM(v, s) cudaGetSymbolAddress(&p, s); auto* v = (decltype(&s[0]))p
    SYM(p_kvin_h, g_kvin_h);  SYM(p_kvin_l, g_kvin_l);
    SYM(p_xd_h, g_xd_h);      SYM(p_xd_l, g_xd_l);
    SYM(p_qe, g_qe); SYM(p_k, g_k); SYM(p_v, g_v);
    SYM(p_agg_h, g_agg_h);    SYM(p_agg_l, g_agg_l);
    SYM(p_rel_h, g_rel_h);    SYM(p_rel_l, g_rel_l);
    SYM(p_hbuf, g_hbuf);
    SYM(p_cat_h, g_cat_h);    SYM(p_cat_l, g_cat_l);
    SYM(p_pth_h, g_pth_h);    SYM(p_pth_l, g_pth_l);
    SYM(p_stacked, g_stacked);
    SYM(p_stk_h, g_stk_h);    SYM(p_stk_l, g_stk_l);
    SYM(p_t, g_t);
    SYM(p_wqt_h, g_wqt_h);    SYM(p_wqt_l, g_wqt_l);
    SYM(p_wkt_h, g_wkt_h);    SYM(p_wkt_l, g_wkt_l);
    SYM(p_wvt_h, g_wvt_h);    SYM(p_wvt_l, g_wvt_l);
    SYM(p_wmt_h, g_wmt_h);    SYM(p_wmt_l, g_wmt_l);
    SYM(p_wir1t_h, g_wir1t_h); SYM(p_wir1t_l, g_wir1t_l);
    SYM(p_wmpt_h, g_wmpt_h);  SYM(p_wmpt_l, g_wmpt_l);
    SYM(p_wa1t_h, g_wa1t_h);  SYM(p_wa1t_l, g_wa1t_l);
    SYM(p_wct_h, g_wct_h);    SYM(p_wct_l, g_wct_l);
#undef SYM

    const int SMB = 73728;   // 2-stage pipeline -> 2 CTAs/SM (tcgen05 path uses 66560)
    cudaFuncSetAttribute((const void*)&tcmm<0, 0>, cudaFuncAttributeMaxDynamicSharedMemorySize, SMB);
    cudaFuncSetAttribute((const void*)&tcmm<1, 2>, cudaFuncAttributeMaxDynamicSharedMemorySize, SMB);
    cudaFuncSetAttribute((const void*)&tcmm<1, 0>, cudaFuncAttributeMaxDynamicSharedMemorySize, SMB);
    cudaFuncSetAttribute((const void*)&tcmm<0, 1>, cudaFuncAttributeMaxDynamicSharedMemorySize, SMB);
    cudaFuncSetAttribute((const void*)&tcmm<2, 0>, cudaFuncAttributeMaxDynamicSharedMemorySize, SMB);

    const int TB = 256;
    bf16* nb16 = nullptr;
    float* nf32 = nullptr;

    // 0: all weight transposes+splits
    tsplit_all<<<dim3((RR * HH * KVP + TB - 1) / TB, 8), TB>>>(Wq, Wk, Wv, Wm, W_ir1, Wmp, Wa1, Wc);
    // 1: all fills
    {
        long tot = (long)RR * NN * NHD + (long)RR * NN * HH / 4;
        fill_all<<<(int)((tot + TB - 1) / TB), TB>>>();
    }
    // 2: gather
    gather_split<<<(int)(((long)RR * EE * (KVP + HH) + TB - 1) / TB), TB>>>(x, ei, ea);

    // 3,4,5: q/k/v GEMMs
    tcmm<0, 0><<<dim3(2, EE / 128, RR), 256, SMB>>>(
        p_xd_h, p_xd_l, (long)EE * HH,
        p_wqt_h, p_wqt_l, (long)HH * HH,
        bq, HH,
        p_qe, HH, 0, (long)EE * HH, 0,
        nb16, nb16, 0, 0, 0, 0, EE, HH);
    tcmm<0, 0><<<dim3(2, EE / 128, RR), 256, SMB>>>(
        p_kvin_h, p_kvin_l, (long)EE * KVP,
        p_wkt_h, p_wkt_l, (long)HH * KVP,
        bk, HH,
        p_k, HH, 0, (long)EE * HH, 0,
        nb16, nb16, 0, 0, 0, 0, EE, KVP);
    tcmm<0, 0><<<dim3(2, EE / 128, RR), 256, SMB>>>(
        p_kvin_h, p_kvin_l, (long)EE * KVP,
        p_wvt_h, p_wvt_l, (long)HH * KVP,
        bv, HH,
        p_v, HH, 0, (long)EE * HH, 0,
        nb16, nb16, 0, 0, 0, 0, EE, KVP);

    // 6-9: attention softmax + aggregation
    scores_kernel<<<RR * EE / 8, TB>>>(ei, prior);
    ex_kernel<<<RR * EE * NHD / TB, TB>>>(ei);
    agg_kernel<<<(int)(((long)RR * EE * HH) / TB), TB>>>(ei);
    agg_split_kernel<<<(int)(((long)RR * NN * HH + TB - 1) / TB), TB>>>();

    // 10: Wm GEMM -> rel_out
    tcmm<1, 2><<<dim3(2, NP / 128, RR), 256, SMB>>>(
        p_agg_h, p_agg_l, (long)NP * HH,
        p_wmt_h, p_wmt_l, (long)HH * HH,
        bm, HH,
        nf32, 0, 0, 0, 0,
        p_rel_h, p_rel_l, RH, 0, 0, HH, NN, HH);

    // 11-13: inter-relation attention + fused post-rel
    tcmm<1, 0><<<dim3(2, NP / 128, 1), 256, SMB>>>(
        p_rel_h, p_rel_l, 0,
        p_wir1t_h, p_wir1t_l, 0,
        b_ir1, 0,
        p_hbuf, HH, 0, 0, 0,
        nb16, nb16, 0, 0, 0, 0, NN, RH);
    interw_kernel<<<(NN * 32 + TB - 1) / TB, TB>>>(W_ir2, b_ir2);
    postrel_kernel<<<(NN * HH + TB - 1) / TB, TB>>>();

    // 14-16: meta paths
    tcmm<0, 1><<<dim3(2, NP / 128, 3), 256, SMB>>>(
        p_pth_h, p_pth_l, (long)NP * HH,
        p_wmpt_h, p_wmpt_l, (long)HH * HH,
        bmp, HH,
        p_stacked, 3 * HH, 0, 0, HH,
        p_stk_h, p_stk_l, 3 * HH, 0, 0, HH, NN, HH);
    tcmm<2, 0><<<dim3(1, (3 * NN + 127) / 128, 1), 256, SMB>>>(
        p_stk_h, p_stk_l, 0,
        p_wa1t_h, p_wa1t_l, 0,
        ba1, 0,
        p_t, HH / 2, 0, 0, 0,
        nb16, nb16, 0, 0, 0, 0, 3 * NN, HH);
    attnmeta_kernel<<<NN, TB>>>(Wa2, gmeta, bmeta);

    // 17-18: combine + output LN
    tcmm<1, 0><<<dim3(2, NP / 128, 1), 256, SMB>>>(
        p_cat_h, p_cat_l, 0,
        p_wct_h, p_wct_l, 0,
        bc, 0,
        p_hbuf, HH, 0, 0, 0,
        nb16, nb16, 0, 0, 0, 0, NN, 2 * HH);
    outln_kernel<<<NN, TB>>>(x, gout, bout, out);
}

// round 9
// speedup vs baseline: 1.3717x; 1.0152x over previous
#include <cuda_runtime.h>
#include <cuda_bf16.h>
#include <math.h>
#include <stdint.h>

#define NN 50000
#define NP 50048          // NN padded to 128
#define RR 6
#define EE 32768
#define HH 256
#define FF 16
#define KVO 272
#define KVP 320           // 272 padded to 64-multiple
#define NHD 8
#define HDD 32
#define RH 1536

typedef __nv_bfloat16 bf16;

#if defined(__CUDA_ARCH__) && (defined(__CUDA_ARCH_FEAT_SM103_ALL) \
    || (defined(__CUDA_ARCH_SPECIFIC__) && (__CUDA_ARCH_SPECIFIC__ == 1030)) \
    || (defined(__CUDA_ARCH_FAMILY_SPECIFIC__) && (__CUDA_ARCH_FAMILY_SPECIFIC__ == 1030)))
#define HAS_TC05 1
#else
#define HAS_TC05 0
#endif

// ---------------- scratch (device globals; zero-initialized at load) ----------------
__device__ __align__(1024) bf16 g_kvin_h[RR * EE * KVP], g_kvin_l[RR * EE * KVP];
__device__ __align__(1024) bf16 g_xd_h[RR * EE * HH],   g_xd_l[RR * EE * HH];
__device__ float g_qe[(size_t)RR * EE * HH], g_k[(size_t)RR * EE * HH], g_v[(size_t)RR * EE * HH];
__device__ float g_sc[RR * EE * NHD], g_m[RR * NN * NHD], g_denom[RR * NN * NHD];
__device__ float g_agg[(size_t)RR * NN * HH];
__device__ __align__(1024) bf16 g_agg_h[(size_t)RR * NP * HH], g_agg_l[(size_t)RR * NP * HH];
__device__ __align__(1024) bf16 g_rel_h[(size_t)NP * RH], g_rel_l[(size_t)NP * RH];
__device__ float g_hbuf[NP * HH];
__device__ float g_interw[NN * NHD];
__device__ __align__(1024) bf16 g_cat_h[NP * 2 * HH], g_cat_l[NP * 2 * HH];
__device__ __align__(1024) bf16 g_pth_h[3 * NP * HH], g_pth_l[3 * NP * HH];
__device__ float g_stacked[NP * 3 * HH];
__device__ __align__(1024) bf16 g_stk_h[NP * 3 * HH], g_stk_l[NP * 3 * HH];
__device__ float g_t[3 * NP * (HH / 2)];
// transposed + split weights: [Ncol][Kpad]
__device__ __align__(1024) bf16 g_wqt_h[RR * HH * HH],  g_wqt_l[RR * HH * HH];
__device__ __align__(1024) bf16 g_wkt_h[RR * HH * KVP], g_wkt_l[RR * HH * KVP];
__device__ __align__(1024) bf16 g_wvt_h[RR * HH * KVP], g_wvt_l[RR * HH * KVP];
__device__ __align__(1024) bf16 g_wmt_h[RR * HH * HH],  g_wmt_l[RR * HH * HH];
__device__ __align__(1024) bf16 g_wir1t_h[HH * RH],     g_wir1t_l[HH * RH];
__device__ __align__(1024) bf16 g_wmpt_h[3 * HH * HH],  g_wmpt_l[3 * HH * HH];
__device__ __align__(1024) bf16 g_wa1t_h[(HH/2) * HH],  g_wa1t_l[(HH/2) * HH];
__device__ __align__(1024) bf16 g_wct_h[HH * 2 * HH],   g_wct_l[HH * 2 * HH];

// ---------------- common helpers ----------------
__device__ __forceinline__ float gelu_exact(float x) {
    return 0.5f * x * (1.0f + erff(x * 0.7071067811865475f));
}
__device__ __forceinline__ void split_store(float v, bf16* ph, bf16* pl) {
    bf16 h = __float2bfloat16(v);
    *ph = h;
    *pl = __float2bfloat16(v - __bfloat162float(h));
}
__device__ __forceinline__ void atomicMaxF(float* addr, float v) {
    int* ai = (int*)addr;
    int old = *ai;
    while (__int_as_float(old) < v) {
        int assumed = old;
        old = atomicCAS(ai, assumed, __float_as_int(v));
        if (old == assumed) break;
    }
}
__device__ __forceinline__ uint32_t smem_u32(const void* p) {
    uint32_t a;
    asm("{ .reg .u64 t; cvta.to.shared.u64 t, %1; cvt.u32.u64 %0, t; }" : "=r"(a) : "l"(p));
    return a;
}
#define CP_ASYNC16(dst, src) \
    asm volatile("cp.async.cg.shared.global [%0], [%1], 16;" :: "r"(dst), "l"(src))
#define CP_COMMIT() asm volatile("cp.async.commit_group;")
#define CP_WAIT1()  asm volatile("cp.async.wait_group 1;")
#define CP_WAIT0()  asm volatile("cp.async.wait_group 0;")

#if HAS_TC05
#define SWZ128(o) ((o) ^ (((o) >> 3) & 0x70))
__device__ __forceinline__ uint64_t mkdesc(uint32_t addr) {
    return ((uint64_t)2 << 61) | ((uint64_t)1 << 46) | ((uint64_t)64 << 32) |
           ((uint64_t)1 << 16) | ((addr >> 4) & 0x3FFF);
}
__device__ __forceinline__ void mma_f16_ss(uint32_t d, uint64_t ad, uint64_t bd,
                                           uint32_t idesc, bool acc) {
    uint32_t en = acc ? 1u : 0u;
    asm volatile(
        "{\n\t.reg .pred p;\n\tsetp.ne.u32 p, %5, 0;\n\t"
        "tcgen05.mma.cta_group::1.kind::f16 [%0], %1, %2, %3, {%4,%4,%4,%4}, p;\n\t}"
        :: "r"(d), "l"(ad), "l"(bd), "r"(idesc), "r"(0u), "r"(en) : "memory");
}
__device__ __forceinline__ void mbar_init(uint32_t mb, uint32_t cnt) {
    asm volatile("mbarrier.init.shared.b64 [%0], %1;" :: "r"(mb), "r"(cnt) : "memory");
}
__device__ __forceinline__ void mbar_wait(uint32_t mb, int parity) {
    asm volatile(
        "{\n\t.reg .pred P1;\n\t"
        "WL_%=:\n\t"
        "mbarrier.try_wait.parity.acquire.cta.shared::cta.b64 P1, [%0], %1, 0x989680;\n\t"
        "@P1 bra.uni WD_%=;\n\t"
        "bra.uni WL_%=;\n\t"
        "WD_%=:\n\t}"
        :: "r"(mb), "r"(parity) : "memory");
}
#define LDTM_X32(r, a) \
    asm volatile( \
        "tcgen05.ld.sync.aligned.32x32b.x32.b32 " \
        "{%0, %1, %2, %3, %4, %5, %6, %7, " \
        " %8, %9, %10, %11, %12, %13, %14, %15, " \
        " %16, %17, %18, %19, %20, %21, %22, %23, " \
        " %24, %25, %26, %27, %28, %29, %30, %31}, [%32];" \
        : "=r"((r)[0]),  "=r"((r)[1]),  "=r"((r)[2]),  "=r"((r)[3]), \
          "=r"((r)[4]),  "=r"((r)[5]),  "=r"((r)[6]),  "=r"((r)[7]), \
          "=r"((r)[8]),  "=r"((r)[9]),  "=r"((r)[10]), "=r"((r)[11]), \
          "=r"((r)[12]), "=r"((r)[13]), "=r"((r)[14]), "=r"((r)[15]), \
          "=r"((r)[16]), "=r"((r)[17]), "=r"((r)[18]), "=r"((r)[19]), \
          "=r"((r)[20]), "=r"((r)[21]), "=r"((r)[22]), "=r"((r)[23]), \
          "=r"((r)[24]), "=r"((r)[25]), "=r"((r)[26]), "=r"((r)[27]), \
          "=r"((r)[28]), "=r"((r)[29]), "=r"((r)[30]), "=r"((r)[31]) \
        : "r"(a))
#else
__device__ __forceinline__ void hmma16816(float* c, const uint32_t* a, const uint32_t* b) {
    asm volatile(
        "mma.sync.aligned.m16n8k16.row.col.f32.bf16.bf16.f32 "
        "{%0,%1,%2,%3}, {%4,%5,%6,%7}, {%8,%9}, {%0,%1,%2,%3};"
        : "+f"(c[0]), "+f"(c[1]), "+f"(c[2]), "+f"(c[3])
        : "r"(a[0]), "r"(a[1]), "r"(a[2]), "r"(a[3]), "r"(b[0]), "r"(b[1]));
}
#define LDSM_X4(r, addr) \
    asm volatile("ldmatrix.sync.aligned.m8n8.x4.shared.b16 {%0,%1,%2,%3}, [%4];" \
        : "=r"((r)[0]), "=r"((r)[1]), "=r"((r)[2]), "=r"((r)[3]) : "r"(addr))
#endif

// ---------------- bf16x3 GEMM (z-batched) ----------------
// Block tile 128x128; single-pass hi/lo: per K-slab load Ah,Al,Bh,Bl once,
// accumulate AhBh + AhBl + AlBh from registers. 2-stage cp.async, 2 CTAs/SM.
template <int ACT, int STORE>
__global__ __launch_bounds__(256, 2)
void tcmm(const bf16* __restrict__ Ah, const bf16* __restrict__ Al, long az,
          const bf16* __restrict__ Bh, const bf16* __restrict__ Bl, long bz,
          const float* __restrict__ bias, int biasz,
          float* __restrict__ C, int ldc, int coff, long cz, int coffz,
          bf16* __restrict__ Ch, bf16* __restrict__ Cl, int ldh, int offh,
          long chz, int offhz,
          int M, int K) {
    extern __shared__ char smem[];
    const int tid = threadIdx.x, wid = tid >> 5, lid = tid & 31;
    const int m0 = blockIdx.y * 128;
    const int n0 = blockIdx.x * 128;
    const int z = blockIdx.z;
    Ah += (size_t)z * az;  Al += (size_t)z * az;
    Bh += (size_t)z * bz;  Bl += (size_t)z * bz;
    bias += (size_t)z * biasz;
    if (STORE != 2) { C += (size_t)z * cz; coff += z * coffz; }
    if (STORE != 0) { Ch += (size_t)z * chz; Cl += (size_t)z * chz; offh += z * offhz; }

#if HAS_TC05
    // ================= tcgen05 path =================
    const uint32_t sb = smem_u32(smem);
    const int ABYTES = 128 * 128;
    const int BUF = 2 * ABYTES;
    const uint32_t mbar0 = sb + 8, mbar1 = sb + 16;
    const uint32_t buf0 = sb + 1024;

    if (wid == 0) {
        asm volatile("tcgen05.alloc.cta_group::1.sync.aligned.shared::cta.b32 [%0], %1;"
                     :: "r"(sb), "r"(128u) : "memory");
        asm volatile("tcgen05.relinquish_alloc_permit.cta_group::1.sync.aligned;");
    }
    __syncthreads();
    uint32_t tmem;
    asm volatile("ld.shared.b32 %0, [%1];" : "=r"(tmem) : "r"(sb));
    if (tid == 0) { mbar_init(mbar0, 1); mbar_init(mbar1, 1); }
    __syncthreads();

    const int KC = K >> 6;
    const int T = KC * 3;
    const uint32_t idesc64 = (1u << 4) | (1u << 7) | (1u << 10) | (8u << 17) | (8u << 24);

    auto load_chunk = [&](int c, uint32_t bufbase) {
        int p = c / KC, kc = (c - p * KC) << 6;
        const bf16* Ap = (p == 2) ? Al : Ah;
        const bf16* Bp = (p == 1) ? Bl : Bh;
        for (int i = tid; i < 2048; i += 256) {
            uint32_t dst;
            const bf16* src;
            if (i < 1024) {
                int r = i >> 3, g = i & 7;
                dst = bufbase + SWZ128(r * 128 + g * 16);
                src = Ap + (size_t)(m0 + r) * K + kc + g * 8;
            } else {
                int j = i - 1024;
                int r = j >> 3, g = j & 7;
                dst = bufbase + ABYTES + SWZ128(r * 128 + g * 16);
                src = Bp + (size_t)(n0 + r) * K + kc + g * 8;
            }
            CP_ASYNC16(dst, src);
        }
        CP_COMMIT();
    };

    int ph0 = 0, ph1 = 0;
    load_chunk(0, buf0);
    for (int c = 0; c < T; c++) {
        int b = c & 1;
        if (c + 1 < T) {
            int nb = b ^ 1;
            if (c >= 1) {
                if (nb) { mbar_wait(mbar1, ph1); ph1 ^= 1; }
                else    { mbar_wait(mbar0, ph0); ph0 ^= 1; }
            }
            load_chunk(c + 1, buf0 + nb * BUF);
            CP_WAIT1();
        } else {
            CP_WAIT0();
        }
        __syncthreads();
        if (tid == 0) {
            asm volatile("fence.proxy.async.shared::cta;" ::: "memory");
            uint64_t ad = mkdesc(buf0 + b * BUF);
            uint64_t bd = mkdesc(buf0 + b * BUF + ABYTES);
#pragma unroll
            for (int ks = 0; ks < 4; ks++)
#pragma unroll
                for (int ns = 0; ns < 2; ns++)
                    mma_f16_ss(tmem + ns * 64, ad + ks * 2, bd + ns * 512 + ks * 2,
                               idesc64, (c > 0) || (ks > 0));
            asm volatile("tcgen05.commit.cta_group::1.mbarrier::arrive::one.shared::cluster.b64 [%0];"
                         :: "r"(b ? mbar1 : mbar0) : "memory");
        }
    }
    {
        int lb = (T - 1) & 1;
        if (lb) mbar_wait(mbar1, ph1); else mbar_wait(mbar0, ph0);
    }
    asm volatile("tcgen05.fence::after_thread_sync;" ::: "memory");

    {
        int row = m0 + (wid & 3) * 32 + lid;
        int colbase = (wid >> 2) * 64;
        for (int cb = 0; cb < 64; cb += 32) {
            uint32_t regs[32];
            LDTM_X32(regs, tmem + colbase + cb);
            asm volatile("tcgen05.wait::ld.sync.aligned;" ::: "memory");
            if (row < M) {
#pragma unroll
                for (int j = 0; j < 32; j++) {
                    int col = n0 + colbase + cb + j;
                    float v = __uint_as_float(regs[j]) + bias[col];
                    if (ACT == 1) v = gelu_exact(v);
                    else if (ACT == 2) v = tanhf(v);
                    if (STORE != 2) C[(size_t)row * ldc + coff + col] = v;
                    if (STORE != 0)
                        split_store(v, Ch + (size_t)row * ldh + offh + col,
                                       Cl + (size_t)row * ldh + offh + col);
                }
            }
        }
    }
    __syncthreads();
    if (wid == 0)
        asm volatile("tcgen05.dealloc.cta_group::1.sync.aligned.b32 %0, %1;"
                     :: "r"(tmem), "r"(128u));

#else
    // ================= single-pass ldmatrix + mma.sync path =================
    // Stage: [Ah | Al | Bh | Bl], each 128 rows x 80 B (32 bf16 K-slab).
    const uint32_t sm_u = smem_u32(smem);
    const int OPB = 128 * 80;            // 10240 B per operand slab
    const int STG = 4 * OPB;             // 40960 B per stage
    const int g = lid >> 2, tig = lid & 3;
    const int wr = wid >> 2, wc = wid & 3;
    const int rowbase = wr * 64, colbase = wc * 32;
    const int S = K >> 5;

    const uint32_t a_lane = (uint32_t)(rowbase + (lid & 15)) * 80 + ((lid >> 4) << 4);
    const uint32_t b_lane = (uint32_t)(colbase + (lid & 7) + (((lid >> 4) & 1) << 3)) * 80
                          + (((lid >> 3) & 1) << 4);

    auto load_stage = [&](int s, int buf) {
        int k0 = s << 5;
        uint32_t base = sm_u + buf * STG;
#pragma unroll
        for (int rep = 0; rep < 2; rep++) {
            int i = tid + 256 * rep;
            int r = i >> 2, sc = i & 3;
            uint32_t off = r * 80 + sc * 16;
            size_t ga = (size_t)(m0 + r) * K + k0 + sc * 8;
            size_t gb = (size_t)(n0 + r) * K + k0 + sc * 8;
            CP_ASYNC16(base + off,            Ah + ga);
            CP_ASYNC16(base + OPB + off,      Al + ga);
            CP_ASYNC16(base + 2 * OPB + off,  Bh + gb);
            CP_ASYNC16(base + 3 * OPB + off,  Bl + gb);
        }
        CP_COMMIT();
    };

    float acc[4][4][4];
#pragma unroll
    for (int mf = 0; mf < 4; mf++)
#pragma unroll
        for (int nf = 0; nf < 4; nf++)
#pragma unroll
            for (int q = 0; q < 4; q++) acc[mf][nf][q] = 0.f;

    load_stage(0, 0);
    for (int s = 0; s < S; s++) {
        if (s + 1 < S) { load_stage(s + 1, (s + 1) & 1); CP_WAIT1(); }
        else CP_WAIT0();
        __syncthreads();
        uint32_t base = sm_u + (s & 1) * STG;
#pragma unroll
        for (int kk = 0; kk < 2; kk++) {
            uint32_t ko = kk << 5;   // 32 bytes per 16-K chunk
            uint32_t afh[4][4], afl[4][4], bfh[2][4], bfl[2][4];
#pragma unroll
            for (int mf = 0; mf < 4; mf++) {
                LDSM_X4(afh[mf], base + a_lane + mf * 1280 + ko);
                LDSM_X4(afl[mf], base + OPB + a_lane + mf * 1280 + ko);
            }
#pragma unroll
            for (int np = 0; np < 2; np++) {
                LDSM_X4(bfh[np], base + 2 * OPB + b_lane + np * 1280 + ko);
                LDSM_X4(bfl[np], base + 3 * OPB + b_lane + np * 1280 + ko);
            }
#pragma unroll
            for (int mf = 0; mf < 4; mf++)
#pragma unroll
                for (int nf = 0; nf < 4; nf++) {
                    const uint32_t* bh = &bfh[nf >> 1][(nf & 1) * 2];
                    const uint32_t* bl = &bfl[nf >> 1][(nf & 1) * 2];
                    hmma16816(acc[mf][nf], afh[mf], bh);
                    hmma16816(acc[mf][nf], afh[mf], bl);
                    hmma16816(acc[mf][nf], afl[mf], bh);
                }
        }
        __syncthreads();
    }

#pragma unroll
    for (int mf = 0; mf < 4; mf++)
#pragma unroll
        for (int nf = 0; nf < 4; nf++) {
            int col0 = n0 + colbase + nf * 8 + 2 * tig;
#pragma unroll
            for (int r8 = 0; r8 < 2; r8++) {
                int row = m0 + rowbase + mf * 16 + g + r8 * 8;
                if (row < M) {
#pragma unroll
                    for (int cc = 0; cc < 2; cc++) {
                        int col = col0 + cc;
                        float v = acc[mf][nf][r8 * 2 + cc] + bias[col];
                        if (ACT == 1) v = gelu_exact(v);
                        else if (ACT == 2) v = tanhf(v);
                        if (STORE != 2) C[(size_t)row * ldc + coff + col] = v;
                        if (STORE != 0)
                            split_store(v, Ch + (size_t)row * ldh + offh + col,
                                           Cl + (size_t)row * ldh + offh + col);
                    }
                }
            }
        }
#endif
}

// ---------------- fused weight transpose+split (ALL weights, 1 launch) ----------------
__global__ void tsplit_all(const float* __restrict__ Wq, const float* __restrict__ Wk,
                           const float* __restrict__ Wv, const float* __restrict__ Wm,
                           const float* __restrict__ Wir1, const float* __restrict__ Wmp,
                           const float* __restrict__ Wa1, const float* __restrict__ Wc) {
    int idx = blockIdx.x * blockDim.x + threadIdx.x;
    int seg = blockIdx.y;
    float v;
    switch (seg) {
    case 0: {
        if (idx >= RR * HH * HH) return;
        int z = idx >> 16, w = idx & 65535, n = w >> 8, k = w & 255;
        v = Wq[(size_t)z * 65536 + k * HH + n];
        split_store(v, g_wqt_h + idx, g_wqt_l + idx);
        break; }
    case 1: {
        if (idx >= RR * HH * KVP) return;
        int z = idx / 81920, w = idx - z * 81920, n = w / KVP, k = w - n * KVP;
        v = (k < KVO) ? Wk[(size_t)z * KVO * HH + k * HH + n] : 0.f;
        split_store(v, g_wkt_h + idx, g_wkt_l + idx);
        break; }
    case 2: {
        if (idx >= RR * HH * KVP) return;
        int z = idx / 81920, w = idx - z * 81920, n = w / KVP, k = w - n * KVP;
        v = (k < KVO) ? Wv[(size_t)z * KVO * HH + k * HH + n] : 0.f;
        split_store(v, g_wvt_h + idx, g_wvt_l + idx);
        break; }
    case 3: {
        if (idx >= RR * HH * HH) return;
        int z = idx >> 16, w = idx & 65535, n = w >> 8, k = w & 255;
        v = Wm[(size_t)z * 65536 + k * HH + n];
        split_store(v, g_wmt_h + idx, g_wmt_l + idx);
        break; }
    case 4: {
        if (idx >= HH * RH) return;
        int n = idx / RH, k = idx - n * RH;
        v = Wir1[(size_t)k * HH + n];
        split_store(v, g_wir1t_h + idx, g_wir1t_l + idx);
        break; }
    case 5: {
        if (idx >= 3 * HH * HH) return;
        int z = idx >> 16, w = idx & 65535, n = w >> 8, k = w & 255;
        v = Wmp[(size_t)z * 65536 + k * HH + n];
        split_store(v, g_wmpt_h + idx, g_wmpt_l + idx);
        break; }
    case 6: {
        if (idx >= (HH / 2) * HH) return;
        int n = idx >> 8, k = idx & 255;
        v = Wa1[(size_t)k * (HH / 2) + n];
        split_store(v, g_wa1t_h + idx, g_wa1t_l + idx);
        break; }
    default: {
        if (idx >= HH * 2 * HH) return;
        int n = idx >> 9, k = idx & 511;
        v = Wc[(size_t)k * HH + n];
        split_store(v, g_wct_h + idx, g_wct_l + idx);
        break; }
    }
}

// ---------------- fused fills ----------------
__global__ void fill_all() {
    const int T1 = RR * NN * NHD;
    const long T2 = (long)RR * NN * HH / 4;
    long idx = (long)blockIdx.x * blockDim.x + threadIdx.x;
    if (idx < T1) {
        g_m[idx] = -INFINITY;
        g_denom[idx] = 0.f;
    } else {
        long j = idx - T1;
        if (j < T2) ((float4*)g_agg)[j] = make_float4(0.f, 0.f, 0.f, 0.f);
    }
}

// ---------------- gather (batched over all relations) ----------------
__global__ void gather_split(const float* __restrict__ x, const int* __restrict__ ei,
                             const float* __restrict__ ea) {
    long idx = (long)blockIdx.x * blockDim.x + threadIdx.x;
    const long perR = (long)EE * (KVP + HH);
    if (idx >= RR * perR) return;
    int r = (int)(idx / perR);
    long rem = idx - (long)r * perR;
    if (rem < (long)EE * KVP) {
        int e = (int)(rem / KVP), c = (int)(rem - (long)e * KVP);
        int src = ei[(r * 2 + 0) * EE + e];
        float v = (c < HH) ? x[(size_t)src * HH + c]
                : ((c < KVO) ? ea[((size_t)r * EE + e) * FF + (c - HH)] : 0.f);
        size_t o = ((size_t)r * EE + e) * KVP + c;
        split_store(v, g_kvin_h + o, g_kvin_l + o);
    } else {
        long j = rem - (long)EE * KVP;
        int e = (int)(j >> 8), c = (int)(j & 255);
        int dst = ei[(r * 2 + 1) * EE + e];
        size_t o = ((size_t)r * EE + e) * HH + c;
        split_store(x[(size_t)dst * HH + c], g_xd_h + o, g_xd_l + o);
    }
}

// ---------------- scores: warp per (r, e), coalesced float4 ----------------
__global__ void scores_kernel(const int* __restrict__ ei, const float* __restrict__ prior) {
    int w = (blockIdx.x * blockDim.x + threadIdx.x) >> 5;
    int lane = threadIdx.x & 31;
    if (w >= RR * EE) return;
    int r = w >> 15, e = w & (EE - 1);
    const float4* q4 = (const float4*)g_qe + ((size_t)r * EE + e) * 64;
    const float4* k4 = (const float4*)g_k  + ((size_t)r * EE + e) * 64;
    float4 qa = q4[lane], ka = k4[lane];
    float4 qb = q4[lane + 32], kb = k4[lane + 32];
    float p1 = qa.x * ka.x + qa.y * ka.y + qa.z * ka.z + qa.w * ka.w;
    float p2 = qb.x * kb.x + qb.y * kb.y + qb.z * kb.z + qb.w * kb.w;
#pragma unroll
    for (int off = 1; off < 8; off <<= 1) {
        p1 += __shfl_xor_sync(0xffffffff, p1, off);
        p2 += __shfl_xor_sync(0xffffffff, p2, off);
    }
    if ((lane & 7) == 0) {
        int dst = ei[(r * 2 + 1) * EE + e];
        int h1 = lane >> 3, h2 = h1 + 4;
        float s1 = p1 * 0.17677669529663687f * prior[r * NHD + h1];
        float s2 = p2 * 0.17677669529663687f * prior[r * NHD + h2];
        g_sc[((size_t)r * EE + e) * NHD + h1] = s1;
        g_sc[((size_t)r * EE + e) * NHD + h2] = s2;
        atomicMaxF(&g_m[((size_t)r * NN + dst) * NHD + h1], s1);
        atomicMaxF(&g_m[((size_t)r * NN + dst) * NHD + h2], s2);
    }
}

__global__ void ex_kernel(const int* __restrict__ ei) {
    int idx = blockIdx.x * blockDim.x + threadIdx.x;
    if (idx >= RR * EE * NHD) return;
    int r = idx >> 18;
    int e = (idx >> 3) & (EE - 1), h = idx & 7;
    int dst = ei[(r * 2 + 1) * EE + e];
    float exv = expf(g_sc[idx] - g_m[((size_t)r * NN + dst) * NHD + h]);
    g_sc[idx] = exv;
    atomicAdd(&g_denom[((size_t)r * NN + dst) * NHD + h], exv);
}

__global__ void agg_kernel(const int* __restrict__ ei) {
    long idx = (long)blockIdx.x * blockDim.x + threadIdx.x;
    if (idx >= (long)RR * EE * HH) return;
    int r = (int)(idx >> 23);
    long w_ = idx & ((1L << 23) - 1);
    int e = (int)(w_ >> 8), c = (int)(w_ & 255);
    int h = c >> 5;
    int dst = ei[(r * 2 + 1) * EE + e];
    float w = g_sc[((size_t)r * EE + e) * NHD + h] /
              (g_denom[((size_t)r * NN + dst) * NHD + h] + 1e-16f);
    atomicAdd(&g_agg[((size_t)r * NN + dst) * HH + c], w * g_v[idx]);
}

__global__ void agg_split_kernel() {
    long idx = (long)blockIdx.x * blockDim.x + threadIdx.x;
    if (idx >= (long)RR * NN * HH) return;
    int r = (int)(idx / ((long)NN * HH));
    long w_ = idx - (long)r * NN * HH;
    int n = (int)(w_ >> 8), c = (int)(w_ & 255);
    size_t o = ((size_t)r * NP + n) * HH + c;
    split_store(g_agg[idx], g_agg_h + o, g_agg_l + o);
}

__global__ void interw_kernel(const float* __restrict__ Wir2, const float* __restrict__ bir2) {
    int gwarp = (blockIdx.x * blockDim.x + threadIdx.x) >> 5;
    int lane = threadIdx.x & 31;
    if (gwarp >= NN) return;
    float acc[RR] = {};
    for (int k = lane; k < HH; k += 32) {
        float hv = g_hbuf[gwarp * HH + k];
#pragma unroll
        for (int rr = 0; rr < RR; rr++) acc[rr] += hv * Wir2[k * RR + rr];
    }
#pragma unroll
    for (int rr = 0; rr < RR; rr++)
#pragma unroll
        for (int off = 16; off; off >>= 1)
            acc[rr] += __shfl_down_sync(0xffffffff, acc[rr], off);
    if (lane == 0) {
        float mx = -1e30f;
#pragma unroll
        for (int rr = 0; rr < RR; rr++) { acc[rr] += bir2[rr]; mx = fmaxf(mx, acc[rr]); }
        float s = 0.f;
#pragma unroll
        for (int rr = 0; rr < RR; rr++) { acc[rr] = expf(acc[rr] - mx); s += acc[rr]; }
        float inv = 1.f / s;
#pragma unroll
        for (int rr = 0; rr < RR; rr++) g_interw[gwarp * NHD + rr] = acc[rr] * inv;
    }
}

// fused interagg + paths
__global__ void postrel_kernel() {
    int idx = blockIdx.x * blockDim.x + threadIdx.x;
    if (idx >= NN * HH) return;
    int n = idx >> 8, c = idx & 255;
    float v[RR];
#pragma unroll
    for (int rr = 0; rr < RR; rr++) {
        size_t b = (size_t)n * RH + rr * HH + c;
        v[rr] = __bfloat162float(g_rel_h[b]) + __bfloat162float(g_rel_l[b]);
    }
    float s = 0.f;
#pragma unroll
    for (int rr = 0; rr < RR; rr++) s += g_interw[n * NHD + rr] * v[rr];
    split_store(s, g_cat_h + (size_t)n * 2 * HH + c, g_cat_l + (size_t)n * 2 * HH + c);
    split_store(v[2] + v[3], g_pth_h + ((size_t)0 * NP + n) * HH + c, g_pth_l + ((size_t)0 * NP + n) * HH + c);
    split_store(v[4] + v[0], g_pth_h + ((size_t)1 * NP + n) * HH + c, g_pth_l + ((size_t)1 * NP + n) * HH + c);
    split_store(v[1] + v[5], g_pth_h + ((size_t)2 * NP + n) * HH + c, g_pth_l + ((size_t)2 * NP + n) * HH + c);
}

__global__ void attnmeta_kernel(const float* __restrict__ Wa2,
                                const float* __restrict__ gm, const float* __restrict__ bm_) {
    __shared__ float lg[3];
    __shared__ float rbuf[256];
    int n = blockIdx.x, t = threadIdx.x;
    int lane = t & 31, w = t >> 5;
    if (w < 3) {
        float a = 0.f;
        for (int j = lane; j < 128; j += 32)
            a += g_t[((size_t)n * 3 + w) * 128 + j] * Wa2[j];
#pragma unroll
        for (int off = 16; off; off >>= 1) a += __shfl_down_sync(0xffffffff, a, off);
        if (lane == 0) lg[w] = a;
    }
    __syncthreads();
    float l0 = lg[0], l1 = lg[1], l2 = lg[2];
    float mx = fmaxf(l0, fmaxf(l1, l2));
    float e0 = expf(l0 - mx), e1 = expf(l1 - mx), e2 = expf(l2 - mx);
    float inv = 1.f / (e0 + e1 + e2);
    const float* st = g_stacked + (size_t)n * 3 * HH;
    float s = (e0 * st[t] + e1 * st[HH + t] + e2 * st[2 * HH + t]) * inv;
    rbuf[t] = s;
    __syncthreads();
    for (int off = 128; off; off >>= 1) { if (t < off) rbuf[t] += rbuf[t + off]; __syncthreads(); }
    float mu = rbuf[0] * (1.f / 256.f);
    __syncthreads();
    float d = s - mu;
    rbuf[t] = d * d;
    __syncthreads();
    for (int off = 128; off; off >>= 1) { if (t < off) rbuf[t] += rbuf[t + off]; __syncthreads(); }
    float var = rbuf[0] * (1.f / 256.f);
    float o = d * rsqrtf(var + 1e-5f) * gm[t] + bm_[t];
    split_store(o, g_cat_h + (size_t)n * 2 * HH + HH + t, g_cat_l + (size_t)n * 2 * HH + HH + t);
}

__global__ void outln_kernel(const float* __restrict__ x, const float* __restrict__ gout,
                             const float* __restrict__ bout, float* __restrict__ out) {
    __shared__ float rbuf[256];
    int n = blockIdx.x, t = threadIdx.x;
    float v = x[(size_t)n * HH + t] + g_hbuf[(size_t)n * HH + t];
    rbuf[t] = v;
    __syncthreads();
    for (int off = 128; off; off >>= 1) { if (t < off) rbuf[t] += rbuf[t + off]; __syncthreads(); }
    float mu = rbuf[0] * (1.f / 256.f);
    __syncthreads();
    float d = v - mu;
    rbuf[t] = d * d;
    __syncthreads();
    for (int off = 128; off; off >>= 1) { if (t < off) rbuf[t] += rbuf[t + off]; __syncthreads(); }
    float var = rbuf[0] * (1.f / 256.f);
    out[(size_t)n * HH + t] = d * rsqrtf(var + 1e-5f) * gout[t] + bout[t];
}

// ---------------- host ----------------
extern "C" void kernel_launch(void* const* d_in, const int* in_sizes, int n_in,
                              void* d_out, int out_size) {
    const float* x     = (const float*)d_in[0];
    const int*   ei    = (const int*)d_in[1];
    const float* ea    = (const float*)d_in[2];
    const float* Wq    = (const float*)d_in[3];
    const float* bq    = (const float*)d_in[4];
    const float* Wk    = (const float*)d_in[5];
    const float* bk    = (const float*)d_in[6];
    const float* Wv    = (const float*)d_in[7];
    const float* bv    = (const float*)d_in[8];
    const float* prior = (const float*)d_in[9];
    const float* Wm    = (const float*)d_in[10];
    const float* bm    = (const float*)d_in[11];
    const float* W_ir1 = (const float*)d_in[12];
    const float* b_ir1 = (const float*)d_in[13];
    const float* W_ir2 = (const float*)d_in[14];
    const float* b_ir2 = (const float*)d_in[15];
    const float* Wmp   = (const float*)d_in[16];
    const float* bmp   = (const float*)d_in[17];
    const float* Wa1   = (const float*)d_in[18];
    const float* ba1   = (const float*)d_in[19];
    const float* Wa2   = (const float*)d_in[20];
    const float* gmeta = (const float*)d_in[21];
    const float* bmeta = (const float*)d_in[22];
    const float* Wc    = (const float*)d_in[23];
    const float* bc    = (const float*)d_in[24];
    const float* gout  = (const float*)d_in[25];
    const float* bout  = (const float*)d_in[26];
    float* out = (float*)d_out;

    void* p;
#define SYM(v, s) cudaGetSymbolAddress(&p, s); auto* v = (decltype(&s[0]))p
    SYM(p_kvin_h, g_kvin_h);  SYM(p_kvin_l, g_kvin_l);
    SYM(p_xd_h, g_xd_h);      SYM(p_xd_l, g_xd_l);
    SYM(p_qe, g_qe); SYM(p_k, g_k); SYM(p_v, g_v);
    SYM(p_agg_h, g_agg_h);    SYM(p_agg_l, g_agg_l);
    SYM(p_rel_h, g_rel_h);    SYM(p_rel_l, g_rel_l);
    SYM(p_hbuf, g_hbuf);
    SYM(p_cat_h, g_cat_h);    SYM(p_cat_l, g_cat_l);
    SYM(p_pth_h, g_pth_h);    SYM(p_pth_l, g_pth_l);
    SYM(p_stacked, g_stacked);
    SYM(p_stk_h, g_stk_h);    SYM(p_stk_l, g_stk_l);
    SYM(p_t, g_t);
    SYM(p_wqt_h, g_wqt_h);    SYM(p_wqt_l, g_wqt_l);
    SYM(p_wkt_h, g_wkt_h);    SYM(p_wkt_l, g_wkt_l);
    SYM(p_wvt_h, g_wvt_h);    SYM(p_wvt_l, g_wvt_l);
    SYM(p_wmt_h, g_wmt_h);    SYM(p_wmt_l, g_wmt_l);
    SYM(p_wir1t_h, g_wir1t_h); SYM(p_wir1t_l, g_wir1t_l);
    SYM(p_wmpt_h, g_wmpt_h);  SYM(p_wmpt_l, g_wmpt_l);
    SYM(p_wa1t_h, g_wa1t_h);  SYM(p_wa1t_l, g_wa1t_l);
    SYM(p_wct_h, g_wct_h);    SYM(p_wct_l, g_wct_l);
#undef SYM

    const int SMB = 81920;   // 2 stages x 40960 B; tcgen05 path uses 66560
    cudaFuncSetAttribute((const void*)&tcmm<0, 0>, cudaFuncAttributeMaxDynamicSharedMemorySize, SMB);
    cudaFuncSetAttribute((const void*)&tcmm<1, 2>, cudaFuncAttributeMaxDynamicSharedMemorySize, SMB);
    cudaFuncSetAttribute((const void*)&tcmm<1, 0>, cudaFuncAttributeMaxDynamicSharedMemorySize, SMB);
    cudaFuncSetAttribute((const void*)&tcmm<0, 1>, cudaFuncAttributeMaxDynamicSharedMemorySize, SMB);
    cudaFuncSetAttribute((const void*)&tcmm<2, 0>, cudaFuncAttributeMaxDynamicSharedMemorySize, SMB);

    const int TB = 256;
    bf16* nb16 = nullptr;
    float* nf32 = nullptr;

    // 0: all weight transposes+splits
    tsplit_all<<<dim3((RR * HH * KVP + TB - 1) / TB, 8), TB>>>(Wq, Wk, Wv, Wm, W_ir1, Wmp, Wa1, Wc);
    // 1: all fills
    {
        long tot = (long)RR * NN * NHD + (long)RR * NN * HH / 4;
        fill_all<<<(int)((tot + TB - 1) / TB), TB>>>();
    }
    // 2: gather
    gather_split<<<(int)(((long)RR * EE * (KVP + HH) + TB - 1) / TB), TB>>>(x, ei, ea);

    // 3,4,5: q/k/v GEMMs
    tcmm<0, 0><<<dim3(2, EE / 128, RR), 256, SMB>>>(
        p_xd_h, p_xd_l, (long)EE * HH,
        p_wqt_h, p_wqt_l, (long)HH * HH,
        bq, HH,
        p_qe, HH, 0, (long)EE * HH, 0,
        nb16, nb16, 0, 0, 0, 0, EE, HH);
    tcmm<0, 0><<<dim3(2, EE / 128, RR), 256, SMB>>>(
        p_kvin_h, p_kvin_l, (long)EE * KVP,
        p_wkt_h, p_wkt_l, (long)HH * KVP,
        bk, HH,
        p_k, HH, 0, (long)EE * HH, 0,
        nb16, nb16, 0, 0, 0, 0, EE, KVP);
    tcmm<0, 0><<<dim3(2, EE / 128, RR), 256, SMB>>>(
        p_kvin_h, p_kvin_l, (long)EE * KVP,
        p_wvt_h, p_wvt_l, (long)HH * KVP,
        bv, HH,
        p_v, HH, 0, (long)EE * HH, 0,
        nb16, nb16, 0, 0, 0, 0, EE, KVP);

    // 6-9: attention softmax + aggregation
    scores_kernel<<<RR * EE / 8, TB>>>(ei, prior);
    ex_kernel<<<RR * EE * NHD / TB, TB>>>(ei);
    agg_kernel<<<(int)(((long)RR * EE * HH) / TB), TB>>>(ei);
    agg_split_kernel<<<(int)(((long)RR * NN * HH + TB - 1) / TB), TB>>>();

    // 10: Wm GEMM -> rel_out
    tcmm<1, 2><<<dim3(2, NP / 128, RR), 256, SMB>>>(
        p_agg_h, p_agg_l, (long)NP * HH,
        p_wmt_h, p_wmt_l, (long)HH * HH,
        bm, HH,
        nf32, 0, 0, 0, 0,
        p_rel_h, p_rel_l, RH, 0, 0, HH, NN, HH);

    // 11-13: inter-relation attention + fused post-rel
    tcmm<1, 0><<<dim3(2, NP / 128, 1), 256, SMB>>>(
        p_rel_h, p_rel_l, 0,
        p_wir1t_h, p_wir1t_l, 0,
        b_ir1, 0,
        p_hbuf, HH, 0, 0, 0,
        nb16, nb16, 0, 0, 0, 0, NN, RH);
    interw_kernel<<<(NN * 32 + TB - 1) / TB, TB>>>(W_ir2, b_ir2);
    postrel_kernel<<<(NN * HH + TB - 1) / TB, TB>>>();

    // 14-16: meta paths
    tcmm<0, 1><<<dim3(2, NP / 128, 3), 256, SMB>>>(
        p_pth_h, p_pth_l, (long)NP * HH,
        p_wmpt_h, p_wmpt_l, (long)HH * HH,
        bmp, HH,
        p_stacked, 3 * HH, 0, 0, HH,
        p_stk_h, p_stk_l, 3 * HH, 0, 0, HH, NN, HH);
    tcmm<2, 0><<<dim3(1, (3 * NN + 127) / 128, 1), 256, SMB>>>(
        p_stk_h, p_stk_l, 0,
        p_wa1t_h, p_wa1t_l, 0,
        ba1, 0,
        p_t, HH / 2, 0, 0, 0,
        nb16, nb16, 0, 0, 0, 0, 3 * NN, HH);
    attnmeta_kernel<<<NN, TB>>>(Wa2, gmeta, bmeta);

    // 17-18: combine + output LN
    tcmm<1, 0><<<dim3(2, NP / 128, 1), 256, SMB>>>(
        p_cat_h, p_cat_l, 0,
        p_wct_h, p_wct_l, 0,
        bc, 0,
        p_hbuf, HH, 0, 0, 0,
        nb16, nb16, 0, 0, 0, 0, NN, 2 * HH);
    outln_kernel<<<NN, TB>>>(x, gout, bout, out);
}

// round 10
// speedup vs baseline: 1.5076x; 1.0991x over previous
#include <cuda_runtime.h>
#include <cuda_bf16.h>
#include <math.h>
#include <stdint.h>

#define NN 50000
#define NP 50048          // NN padded to 128
#define RR 6
#define EE 32768
#define HH 256
#define FF 16
#define KVO 272
#define KVP 320           // 272 padded to 64-multiple
#define NHD 8
#define HDD 32
#define RH 1536

typedef __nv_bfloat16 bf16;
typedef __nv_bfloat162 bf162;

#if defined(__CUDA_ARCH__) && (defined(__CUDA_ARCH_FEAT_SM103_ALL) \
    || (defined(__CUDA_ARCH_SPECIFIC__) && (__CUDA_ARCH_SPECIFIC__ == 1030)) \
    || (defined(__CUDA_ARCH_FAMILY_SPECIFIC__) && (__CUDA_ARCH_FAMILY_SPECIFIC__ == 1030)))
#define HAS_TC05 1
#else
#define HAS_TC05 0
#endif

// ---------------- scratch (device globals; zero-initialized at load) ----------------
__device__ __align__(1024) bf16 g_kvin_h[RR * EE * KVP], g_kvin_l[RR * EE * KVP];
__device__ __align__(1024) bf16 g_xd_h[RR * EE * HH],   g_xd_l[RR * EE * HH];
__device__ float g_qe[(size_t)RR * EE * HH], g_k[(size_t)RR * EE * HH], g_v[(size_t)RR * EE * HH];
__device__ float g_sc[RR * EE * NHD], g_m[RR * NN * NHD], g_denom[RR * NN * NHD];
__device__ float g_agg[(size_t)RR * NN * HH];
__device__ __align__(1024) bf16 g_agg_h[(size_t)RR * NP * HH], g_agg_l[(size_t)RR * NP * HH];
__device__ __align__(1024) bf16 g_rel_h[(size_t)NP * RH], g_rel_l[(size_t)NP * RH];
__device__ float g_hbuf[NP * HH];
__device__ float g_interw[NN * NHD];
__device__ __align__(1024) bf16 g_cat_h[NP * 2 * HH], g_cat_l[NP * 2 * HH];
__device__ __align__(1024) bf16 g_pth_h[3 * NP * HH], g_pth_l[3 * NP * HH];
__device__ float g_stacked[NP * 3 * HH];
__device__ __align__(1024) bf16 g_stk_h[NP * 3 * HH], g_stk_l[NP * 3 * HH];
__device__ float g_t[3 * NP * (HH / 2)];
// transposed + split weights: [Ncol][Kpad]
__device__ __align__(1024) bf16 g_wqt_h[RR * HH * HH],  g_wqt_l[RR * HH * HH];
__device__ __align__(1024) bf16 g_wkt_h[RR * HH * KVP], g_wkt_l[RR * HH * KVP];
__device__ __align__(1024) bf16 g_wvt_h[RR * HH * KVP], g_wvt_l[RR * HH * KVP];
__device__ __align__(1024) bf16 g_wmt_h[RR * HH * HH],  g_wmt_l[RR * HH * HH];
__device__ __align__(1024) bf16 g_wir1t_h[HH * RH],     g_wir1t_l[HH * RH];
__device__ __align__(1024) bf16 g_wmpt_h[3 * HH * HH],  g_wmpt_l[3 * HH * HH];
__device__ __align__(1024) bf16 g_wa1t_h[(HH/2) * HH],  g_wa1t_l[(HH/2) * HH];
__device__ __align__(1024) bf16 g_wct_h[HH * 2 * HH],   g_wct_l[HH * 2 * HH];

// ---------------- common helpers ----------------
__device__ __forceinline__ float gelu_exact(float x) {
    return 0.5f * x * (1.0f + erff(x * 0.7071067811865475f));
}
__device__ __forceinline__ void split_store(float v, bf16* ph, bf16* pl) {
    bf16 h = __float2bfloat16(v);
    *ph = h;
    *pl = __float2bfloat16(v - __bfloat162float(h));
}
// packed 4-wide split store (8B aligned destinations)
__device__ __forceinline__ void split_store4(float4 v, bf16* ph, bf16* pl) {
    bf16 h0 = __float2bfloat16(v.x), h1 = __float2bfloat16(v.y);
    bf16 h2 = __float2bfloat16(v.z), h3 = __float2bfloat16(v.w);
    bf16 l0 = __float2bfloat16(v.x - __bfloat162float(h0));
    bf16 l1 = __float2bfloat16(v.y - __bfloat162float(h1));
    bf16 l2 = __float2bfloat16(v.z - __bfloat162float(h2));
    bf16 l3 = __float2bfloat16(v.w - __bfloat162float(h3));
    union { bf162 b[2]; uint2 u; } H, L;
    H.b[0] = bf162(h0, h1); H.b[1] = bf162(h2, h3);
    L.b[0] = bf162(l0, l1); L.b[1] = bf162(l2, l3);
    *(uint2*)ph = H.u;
    *(uint2*)pl = L.u;
}
__device__ __forceinline__ float4 load_hl4(const bf16* ph, const bf16* pl) {
    union { uint2 u; bf162 b[2]; } H, L;
    H.u = *(const uint2*)ph;
    L.u = *(const uint2*)pl;
    float4 r;
    r.x = __bfloat162float(H.b[0].x) + __bfloat162float(L.b[0].x);
    r.y = __bfloat162float(H.b[0].y) + __bfloat162float(L.b[0].y);
    r.z = __bfloat162float(H.b[1].x) + __bfloat162float(L.b[1].x);
    r.w = __bfloat162float(H.b[1].y) + __bfloat162float(L.b[1].y);
    return r;
}
__device__ __forceinline__ void atomicMaxF(float* addr, float v) {
    int* ai = (int*)addr;
    int old = *ai;
    while (__int_as_float(old) < v) {
        int assumed = old;
        old = atomicCAS(ai, assumed, __float_as_int(v));
        if (old == assumed) break;
    }
}
// block-wide sum over 256 threads via warp shuffles (sm must hold >= 8 floats)
__device__ __forceinline__ float block_sum256(float v, float* sm) {
    int lane = threadIdx.x & 31, w = threadIdx.x >> 5;
#pragma unroll
    for (int o = 16; o; o >>= 1) v += __shfl_xor_sync(0xffffffffu, v, o);
    if (lane == 0) sm[w] = v;
    __syncthreads();
    float r;
    if (threadIdx.x < 8) {
        float s = sm[threadIdx.x];
#pragma unroll
        for (int o = 4; o; o >>= 1) s += __shfl_xor_sync(0xffu, s, o);
        if (threadIdx.x == 0) sm[0] = s;
    }
    __syncthreads();
    r = sm[0];
    __syncthreads();
    return r;
}
__device__ __forceinline__ uint32_t smem_u32(const void* p) {
    uint32_t a;
    asm("{ .reg .u64 t; cvta.to.shared.u64 t, %1; cvt.u32.u64 %0, t; }" : "=r"(a) : "l"(p));
    return a;
}
#define CP_ASYNC16(dst, src) \
    asm volatile("cp.async.cg.shared.global [%0], [%1], 16;" :: "r"(dst), "l"(src))
#define CP_COMMIT() asm volatile("cp.async.commit_group;")
#define CP_WAIT1()  asm volatile("cp.async.wait_group 1;")
#define CP_WAIT0()  asm volatile("cp.async.wait_group 0;")

#if HAS_TC05
#define SWZ128(o) ((o) ^ (((o) >> 3) & 0x70))
__device__ __forceinline__ uint64_t mkdesc(uint32_t addr) {
    return ((uint64_t)2 << 61) | ((uint64_t)1 << 46) | ((uint64_t)64 << 32) |
           ((uint64_t)1 << 16) | ((addr >> 4) & 0x3FFF);
}
__device__ __forceinline__ void mma_f16_ss(uint32_t d, uint64_t ad, uint64_t bd,
                                           uint32_t idesc, bool acc) {
    uint32_t en = acc ? 1u : 0u;
    asm volatile(
        "{\n\t.reg .pred p;\n\tsetp.ne.u32 p, %5, 0;\n\t"
        "tcgen05.mma.cta_group::1.kind::f16 [%0], %1, %2, %3, {%4,%4,%4,%4}, p;\n\t}"
        :: "r"(d), "l"(ad), "l"(bd), "r"(idesc), "r"(0u), "r"(en) : "memory");
}
__device__ __forceinline__ void mbar_init(uint32_t mb, uint32_t cnt) {
    asm volatile("mbarrier.init.shared.b64 [%0], %1;" :: "r"(mb), "r"(cnt) : "memory");
}
__device__ __forceinline__ void mbar_wait(uint32_t mb, int parity) {
    asm volatile(
        "{\n\t.reg .pred P1;\n\t"
        "WL_%=:\n\t"
        "mbarrier.try_wait.parity.acquire.cta.shared::cta.b64 P1, [%0], %1, 0x989680;\n\t"
        "@P1 bra.uni WD_%=;\n\t"
        "bra.uni WL_%=;\n\t"
        "WD_%=:\n\t}"
        :: "r"(mb), "r"(parity) : "memory");
}
#define LDTM_X32(r, a) \
    asm volatile( \
        "tcgen05.ld.sync.aligned.32x32b.x32.b32 " \
        "{%0, %1, %2, %3, %4, %5, %6, %7, " \
        " %8, %9, %10, %11, %12, %13, %14, %15, " \
        " %16, %17, %18, %19, %20, %21, %22, %23, " \
        " %24, %25, %26, %27, %28, %29, %30, %31}, [%32];" \
        : "=r"((r)[0]),  "=r"((r)[1]),  "=r"((r)[2]),  "=r"((r)[3]), \
          "=r"((r)[4]),  "=r"((r)[5]),  "=r"((r)[6]),  "=r"((r)[7]), \
          "=r"((r)[8]),  "=r"((r)[9]),  "=r"((r)[10]), "=r"((r)[11]), \
          "=r"((r)[12]), "=r"((r)[13]), "=r"((r)[14]), "=r"((r)[15]), \
          "=r"((r)[16]), "=r"((r)[17]), "=r"((r)[18]), "=r"((r)[19]), \
          "=r"((r)[20]), "=r"((r)[21]), "=r"((r)[22]), "=r"((r)[23]), \
          "=r"((r)[24]), "=r"((r)[25]), "=r"((r)[26]), "=r"((r)[27]), \
          "=r"((r)[28]), "=r"((r)[29]), "=r"((r)[30]), "=r"((r)[31]) \
        : "r"(a))
#else
__device__ __forceinline__ void hmma16816(float* c, const uint32_t* a, const uint32_t* b) {
    asm volatile(
        "mma.sync.aligned.m16n8k16.row.col.f32.bf16.bf16.f32 "
        "{%0,%1,%2,%3}, {%4,%5,%6,%7}, {%8,%9}, {%0,%1,%2,%3};"
        : "+f"(c[0]), "+f"(c[1]), "+f"(c[2]), "+f"(c[3])
        : "r"(a[0]), "r"(a[1]), "r"(a[2]), "r"(a[3]), "r"(b[0]), "r"(b[1]));
}
#define LDSM_X4(r, addr) \
    asm volatile("ldmatrix.sync.aligned.m8n8.x4.shared.b16 {%0,%1,%2,%3}, [%4];" \
        : "=r"((r)[0]), "=r"((r)[1]), "=r"((r)[2]), "=r"((r)[3]) : "r"(addr))
#endif

// ---------------- bf16x3 GEMM (z-batched) ----------------
template <int ACT, int STORE>
__global__ __launch_bounds__(256, 2)
void tcmm(const bf16* __restrict__ Ah, const bf16* __restrict__ Al, long az,
          const bf16* __restrict__ Bh, const bf16* __restrict__ Bl, long bz,
          const float* __restrict__ bias, int biasz,
          float* __restrict__ C, int ldc, int coff, long cz, int coffz,
          bf16* __restrict__ Ch, bf16* __restrict__ Cl, int ldh, int offh,
          long chz, int offhz,
          int M, int K) {
    extern __shared__ char smem[];
    const int tid = threadIdx.x, wid = tid >> 5, lid = tid & 31;
    const int m0 = blockIdx.y * 128;
    const int n0 = blockIdx.x * 128;
    const int z = blockIdx.z;
    Ah += (size_t)z * az;  Al += (size_t)z * az;
    Bh += (size_t)z * bz;  Bl += (size_t)z * bz;
    bias += (size_t)z * biasz;
    if (STORE != 2) { C += (size_t)z * cz; coff += z * coffz; }
    if (STORE != 0) { Ch += (size_t)z * chz; Cl += (size_t)z * chz; offh += z * offhz; }

#if HAS_TC05
    // ================= tcgen05 path =================
    const uint32_t sb = smem_u32(smem);
    const int ABYTES = 128 * 128;
    const int BUF = 2 * ABYTES;
    const uint32_t mbar0 = sb + 8, mbar1 = sb + 16;
    const uint32_t buf0 = sb + 1024;

    if (wid == 0) {
        asm volatile("tcgen05.alloc.cta_group::1.sync.aligned.shared::cta.b32 [%0], %1;"
                     :: "r"(sb), "r"(128u) : "memory");
        asm volatile("tcgen05.relinquish_alloc_permit.cta_group::1.sync.aligned;");
    }
    __syncthreads();
    uint32_t tmem;
    asm volatile("ld.shared.b32 %0, [%1];" : "=r"(tmem) : "r"(sb));
    if (tid == 0) { mbar_init(mbar0, 1); mbar_init(mbar1, 1); }
    __syncthreads();

    const int KC = K >> 6;
    const int T = KC * 3;
    const uint32_t idesc64 = (1u << 4) | (1u << 7) | (1u << 10) | (8u << 17) | (8u << 24);

    auto load_chunk = [&](int c, uint32_t bufbase) {
        int p = c / KC, kc = (c - p * KC) << 6;
        const bf16* Ap = (p == 2) ? Al : Ah;
        const bf16* Bp = (p == 1) ? Bl : Bh;
        for (int i = tid; i < 2048; i += 256) {
            uint32_t dst;
            const bf16* src;
            if (i < 1024) {
                int r = i >> 3, g = i & 7;
                dst = bufbase + SWZ128(r * 128 + g * 16);
                src = Ap + (size_t)(m0 + r) * K + kc + g * 8;
            } else {
                int j = i - 1024;
                int r = j >> 3, g = j & 7;
                dst = bufbase + ABYTES + SWZ128(r * 128 + g * 16);
                src = Bp + (size_t)(n0 + r) * K + kc + g * 8;
            }
            CP_ASYNC16(dst, src);
        }
        CP_COMMIT();
    };

    int ph0 = 0, ph1 = 0;
    load_chunk(0, buf0);
    for (int c = 0; c < T; c++) {
        int b = c & 1;
        if (c + 1 < T) {
            int nb = b ^ 1;
            if (c >= 1) {
                if (nb) { mbar_wait(mbar1, ph1); ph1 ^= 1; }
                else    { mbar_wait(mbar0, ph0); ph0 ^= 1; }
            }
            load_chunk(c + 1, buf0 + nb * BUF);
            CP_WAIT1();
        } else {
            CP_WAIT0();
        }
        __syncthreads();
        if (tid == 0) {
            asm volatile("fence.proxy.async.shared::cta;" ::: "memory");
            uint64_t ad = mkdesc(buf0 + b * BUF);
            uint64_t bd = mkdesc(buf0 + b * BUF + ABYTES);
#pragma unroll
            for (int ks = 0; ks < 4; ks++)
#pragma unroll
                for (int ns = 0; ns < 2; ns++)
                    mma_f16_ss(tmem + ns * 64, ad + ks * 2, bd + ns * 512 + ks * 2,
                               idesc64, (c > 0) || (ks > 0));
            asm volatile("tcgen05.commit.cta_group::1.mbarrier::arrive::one.shared::cluster.b64 [%0];"
                         :: "r"(b ? mbar1 : mbar0) : "memory");
        }
    }
    {
        int lb = (T - 1) & 1;
        if (lb) mbar_wait(mbar1, ph1); else mbar_wait(mbar0, ph0);
    }
    asm volatile("tcgen05.fence::after_thread_sync;" ::: "memory");

    {
        int row = m0 + (wid & 3) * 32 + lid;
        int colbase = (wid >> 2) * 64;
        for (int cb = 0; cb < 64; cb += 32) {
            uint32_t regs[32];
            LDTM_X32(regs, tmem + colbase + cb);
            asm volatile("tcgen05.wait::ld.sync.aligned;" ::: "memory");
            if (row < M) {
#pragma unroll
                for (int j = 0; j < 32; j++) {
                    int col = n0 + colbase + cb + j;
                    float v = __uint_as_float(regs[j]) + bias[col];
                    if (ACT == 1) v = gelu_exact(v);
                    else if (ACT == 2) v = tanhf(v);
                    if (STORE != 2) C[(size_t)row * ldc + coff + col] = v;
                    if (STORE != 0)
                        split_store(v, Ch + (size_t)row * ldh + offh + col,
                                       Cl + (size_t)row * ldh + offh + col);
                }
            }
        }
    }
    __syncthreads();
    if (wid == 0)
        asm volatile("tcgen05.dealloc.cta_group::1.sync.aligned.b32 %0, %1;"
                     :: "r"(tmem), "r"(128u));

#else
    // ================= single-pass ldmatrix + mma.sync path =================
    const uint32_t sm_u = smem_u32(smem);
    const int OPB = 128 * 80;
    const int STG = 4 * OPB;
    const int g = lid >> 2, tig = lid & 3;
    const int wr = wid >> 2, wc = wid & 3;
    const int rowbase = wr * 64, colbase = wc * 32;
    const int S = K >> 5;

    const uint32_t a_lane = (uint32_t)(rowbase + (lid & 15)) * 80 + ((lid >> 4) << 4);
    const uint32_t b_lane = (uint32_t)(colbase + (lid & 7) + (((lid >> 4) & 1) << 3)) * 80
                          + (((lid >> 3) & 1) << 4);

    auto load_stage = [&](int s, int buf) {
        int k0 = s << 5;
        uint32_t base = sm_u + buf * STG;
#pragma unroll
        for (int rep = 0; rep < 2; rep++) {
            int i = tid + 256 * rep;
            int r = i >> 2, sc = i & 3;
            uint32_t off = r * 80 + sc * 16;
            size_t ga = (size_t)(m0 + r) * K + k0 + sc * 8;
            size_t gb = (size_t)(n0 + r) * K + k0 + sc * 8;
            CP_ASYNC16(base + off,            Ah + ga);
            CP_ASYNC16(base + OPB + off,      Al + ga);
            CP_ASYNC16(base + 2 * OPB + off,  Bh + gb);
            CP_ASYNC16(base + 3 * OPB + off,  Bl + gb);
        }
        CP_COMMIT();
    };

    float acc[4][4][4];
#pragma unroll
    for (int mf = 0; mf < 4; mf++)
#pragma unroll
        for (int nf = 0; nf < 4; nf++)
#pragma unroll
            for (int q = 0; q < 4; q++) acc[mf][nf][q] = 0.f;

    load_stage(0, 0);
    for (int s = 0; s < S; s++) {
        if (s + 1 < S) { load_stage(s + 1, (s + 1) & 1); CP_WAIT1(); }
        else CP_WAIT0();
        __syncthreads();
        uint32_t base = sm_u + (s & 1) * STG;
#pragma unroll
        for (int kk = 0; kk < 2; kk++) {
            uint32_t ko = kk << 5;
            uint32_t afh[4][4], afl[4][4], bfh[2][4], bfl[2][4];
#pragma unroll
            for (int mf = 0; mf < 4; mf++) {
                LDSM_X4(afh[mf], base + a_lane + mf * 1280 + ko);
                LDSM_X4(afl[mf], base + OPB + a_lane + mf * 1280 + ko);
            }
#pragma unroll
            for (int np = 0; np < 2; np++) {
                LDSM_X4(bfh[np], base + 2 * OPB + b_lane + np * 1280 + ko);
                LDSM_X4(bfl[np], base + 3 * OPB + b_lane + np * 1280 + ko);
            }
#pragma unroll
            for (int mf = 0; mf < 4; mf++)
#pragma unroll
                for (int nf = 0; nf < 4; nf++) {
                    const uint32_t* bh = &bfh[nf >> 1][(nf & 1) * 2];
                    const uint32_t* bl = &bfl[nf >> 1][(nf & 1) * 2];
                    hmma16816(acc[mf][nf], afh[mf], bh);
                    hmma16816(acc[mf][nf], afh[mf], bl);
                    hmma16816(acc[mf][nf], afl[mf], bh);
                }
        }
        __syncthreads();
    }

#pragma unroll
    for (int mf = 0; mf < 4; mf++)
#pragma unroll
        for (int nf = 0; nf < 4; nf++) {
            int col0 = n0 + colbase + nf * 8 + 2 * tig;
#pragma unroll
            for (int r8 = 0; r8 < 2; r8++) {
                int row = m0 + rowbase + mf * 16 + g + r8 * 8;
                if (row < M) {
#pragma unroll
                    for (int cc = 0; cc < 2; cc++) {
                        int col = col0 + cc;
                        float v = acc[mf][nf][r8 * 2 + cc] + bias[col];
                        if (ACT == 1) v = gelu_exact(v);
                        else if (ACT == 2) v = tanhf(v);
                        if (STORE != 2) C[(size_t)row * ldc + coff + col] = v;
                        if (STORE != 0)
                            split_store(v, Ch + (size_t)row * ldh + offh + col,
                                           Cl + (size_t)row * ldh + offh + col);
                    }
                }
            }
        }
#endif
}

// ---------------- fused weight transpose+split ----------------
__global__ void tsplit_all(const float* __restrict__ Wq, const float* __restrict__ Wk,
                           const float* __restrict__ Wv, const float* __restrict__ Wm,
                           const float* __restrict__ Wir1, const float* __restrict__ Wmp,
                           const float* __restrict__ Wa1, const float* __restrict__ Wc) {
    int idx = blockIdx.x * blockDim.x + threadIdx.x;
    int seg = blockIdx.y;
    float v;
    switch (seg) {
    case 0: {
        if (idx >= RR * HH * HH) return;
        int z = idx >> 16, w = idx & 65535, n = w >> 8, k = w & 255;
        v = Wq[(size_t)z * 65536 + k * HH + n];
        split_store(v, g_wqt_h + idx, g_wqt_l + idx);
        break; }
    case 1: {
        if (idx >= RR * HH * KVP) return;
        int z = idx / 81920, w = idx - z * 81920, n = w / KVP, k = w - n * KVP;
        v = (k < KVO) ? Wk[(size_t)z * KVO * HH + k * HH + n] : 0.f;
        split_store(v, g_wkt_h + idx, g_wkt_l + idx);
        break; }
    case 2: {
        if (idx >= RR * HH * KVP) return;
        int z = idx / 81920, w = idx - z * 81920, n = w / KVP, k = w - n * KVP;
        v = (k < KVO) ? Wv[(size_t)z * KVO * HH + k * HH + n] : 0.f;
        split_store(v, g_wvt_h + idx, g_wvt_l + idx);
        break; }
    case 3: {
        if (idx >= RR * HH * HH) return;
        int z = idx >> 16, w = idx & 65535, n = w >> 8, k = w & 255;
        v = Wm[(size_t)z * 65536 + k * HH + n];
        split_store(v, g_wmt_h + idx, g_wmt_l + idx);
        break; }
    case 4: {
        if (idx >= HH * RH) return;
        int n = idx / RH, k = idx - n * RH;
        v = Wir1[(size_t)k * HH + n];
        split_store(v, g_wir1t_h + idx, g_wir1t_l + idx);
        break; }
    case 5: {
        if (idx >= 3 * HH * HH) return;
        int z = idx >> 16, w = idx & 65535, n = w >> 8, k = w & 255;
        v = Wmp[(size_t)z * 65536 + k * HH + n];
        split_store(v, g_wmpt_h + idx, g_wmpt_l + idx);
        break; }
    case 6: {
        if (idx >= (HH / 2) * HH) return;
        int n = idx >> 8, k = idx & 255;
        v = Wa1[(size_t)k * (HH / 2) + n];
        split_store(v, g_wa1t_h + idx, g_wa1t_l + idx);
        break; }
    default: {
        if (idx >= HH * 2 * HH) return;
        int n = idx >> 9, k = idx & 511;
        v = Wc[(size_t)k * HH + n];
        split_store(v, g_wct_h + idx, g_wct_l + idx);
        break; }
    }
}

// ---------------- fused fills (vectorized) ----------------
__global__ void fill_all() {
    const int T14 = RR * NN * NHD / 4;            // 600,000 float4
    const long T24 = (long)RR * NN * HH / 4;      // 19.2M float4
    long idx = (long)blockIdx.x * blockDim.x + threadIdx.x;
    if (idx < T14) {
        ((float4*)g_m)[idx] = make_float4(-INFINITY, -INFINITY, -INFINITY, -INFINITY);
        ((float4*)g_denom)[idx] = make_float4(0.f, 0.f, 0.f, 0.f);
    } else {
        long j = idx - T14;
        if (j < T24) ((float4*)g_agg)[j] = make_float4(0.f, 0.f, 0.f, 0.f);
    }
}

// ---------------- gather (vectorized float4) ----------------
__global__ void gather_split(const float* __restrict__ x, const int* __restrict__ ei,
                             const float* __restrict__ ea) {
    long idx = (long)blockIdx.x * blockDim.x + threadIdx.x;
    const long perR = (long)EE * (KVP / 4 + HH / 4);   // 80 + 64 c4 units
    if (idx >= RR * perR) return;
    int r = (int)(idx / perR);
    long rem = idx - (long)r * perR;
    if (rem < (long)EE * (KVP / 4)) {
        int e = (int)(rem / (KVP / 4)), c4 = (int)(rem - (long)e * (KVP / 4));
        int src = ei[(r * 2 + 0) * EE + e];
        float4 v;
        if (c4 < 64)      v = ((const float4*)(x + (size_t)src * HH))[c4];
        else if (c4 < 68) v = ((const float4*)(ea + ((size_t)r * EE + e) * FF))[c4 - 64];
        else              v = make_float4(0.f, 0.f, 0.f, 0.f);
        size_t o = ((size_t)r * EE + e) * KVP + 4 * c4;
        split_store4(v, g_kvin_h + o, g_kvin_l + o);
    } else {
        long j = rem - (long)EE * (KVP / 4);
        int e = (int)(j >> 6), c4 = (int)(j & 63);
        int dst = ei[(r * 2 + 1) * EE + e];
        float4 v = ((const float4*)(x + (size_t)dst * HH))[c4];
        size_t o = ((size_t)r * EE + e) * HH + 4 * c4;
        split_store4(v, g_xd_h + o, g_xd_l + o);
    }
}

// ---------------- scores: warp per (r, e), coalesced float4 ----------------
__global__ void scores_kernel(const int* __restrict__ ei, const float* __restrict__ prior) {
    int w = (blockIdx.x * blockDim.x + threadIdx.x) >> 5;
    int lane = threadIdx.x & 31;
    if (w >= RR * EE) return;
    int r = w >> 15, e = w & (EE - 1);
    const float4* q4 = (const float4*)g_qe + ((size_t)r * EE + e) * 64;
    const float4* k4 = (const float4*)g_k  + ((size_t)r * EE + e) * 64;
    float4 qa = q4[lane], ka = k4[lane];
    float4 qb = q4[lane + 32], kb = k4[lane + 32];
    float p1 = qa.x * ka.x + qa.y * ka.y + qa.z * ka.z + qa.w * ka.w;
    float p2 = qb.x * kb.x + qb.y * kb.y + qb.z * kb.z + qb.w * kb.w;
#pragma unroll
    for (int off = 1; off < 8; off <<= 1) {
        p1 += __shfl_xor_sync(0xffffffff, p1, off);
        p2 += __shfl_xor_sync(0xffffffff, p2, off);
    }
    if ((lane & 7) == 0) {
        int dst = ei[(r * 2 + 1) * EE + e];
        int h1 = lane >> 3, h2 = h1 + 4;
        float s1 = p1 * 0.17677669529663687f * prior[r * NHD + h1];
        float s2 = p2 * 0.17677669529663687f * prior[r * NHD + h2];
        g_sc[((size_t)r * EE + e) * NHD + h1] = s1;
        g_sc[((size_t)r * EE + e) * NHD + h2] = s2;
        atomicMaxF(&g_m[((size_t)r * NN + dst) * NHD + h1], s1);
        atomicMaxF(&g_m[((size_t)r * NN + dst) * NHD + h2], s2);
    }
}

__global__ void ex_kernel(const int* __restrict__ ei) {
    int idx = blockIdx.x * blockDim.x + threadIdx.x;
    if (idx >= RR * EE * NHD) return;
    int r = idx >> 18;
    int e = (idx >> 3) & (EE - 1), h = idx & 7;
    int dst = ei[(r * 2 + 1) * EE + e];
    float exv = expf(g_sc[idx] - g_m[((size_t)r * NN + dst) * NHD + h]);
    g_sc[idx] = exv;
    atomicAdd(&g_denom[((size_t)r * NN + dst) * NHD + h], exv);
}

// ---------------- aggregation (vectorized: float4 v + 4 atomics) ----------------
__global__ void agg_kernel(const int* __restrict__ ei) {
    long idx = (long)blockIdx.x * blockDim.x + threadIdx.x;
    if (idx >= (long)RR * EE * (HH / 4)) return;
    int r = (int)(idx >> 21);                 // EE * 64 = 2^21
    long w_ = idx & ((1L << 21) - 1);
    int e = (int)(w_ >> 6), c4 = (int)(w_ & 63);
    int h = c4 >> 3;
    int dst = ei[(r * 2 + 1) * EE + e];
    float w = g_sc[((size_t)r * EE + e) * NHD + h] /
              (g_denom[((size_t)r * NN + dst) * NHD + h] + 1e-16f);
    float4 vv = ((const float4*)g_v)[idx];
    float* base = &g_agg[((size_t)r * NN + dst) * HH + 4 * c4];
    atomicAdd(base + 0, w * vv.x);
    atomicAdd(base + 1, w * vv.y);
    atomicAdd(base + 2, w * vv.z);
    atomicAdd(base + 3, w * vv.w);
}

__global__ void agg_split_kernel() {
    long idx = (long)blockIdx.x * blockDim.x + threadIdx.x;
    if (idx >= (long)RR * NN * (HH / 4)) return;
    int r = (int)(idx / ((long)NN * 64));
    long w_ = idx - (long)r * NN * 64;
    int n = (int)(w_ >> 6), c4 = (int)(w_ & 63);
    float4 v = ((const float4*)g_agg)[idx];
    size_t o = ((size_t)r * NP + n) * HH + 4 * c4;
    split_store4(v, g_agg_h + o, g_agg_l + o);
}

__global__ void interw_kernel(const float* __restrict__ Wir2, const float* __restrict__ bir2) {
    int gwarp = (blockIdx.x * blockDim.x + threadIdx.x) >> 5;
    int lane = threadIdx.x & 31;
    if (gwarp >= NN) return;
    float acc[RR] = {};
    for (int k = lane; k < HH; k += 32) {
        float hv = g_hbuf[gwarp * HH + k];
#pragma unroll
        for (int rr = 0; rr < RR; rr++) acc[rr] += hv * Wir2[k * RR + rr];
    }
#pragma unroll
    for (int rr = 0; rr < RR; rr++)
#pragma unroll
        for (int off = 16; off; off >>= 1)
            acc[rr] += __shfl_down_sync(0xffffffff, acc[rr], off);
    if (lane == 0) {
        float mx = -1e30f;
#pragma unroll
        for (int rr = 0; rr < RR; rr++) { acc[rr] += bir2[rr]; mx = fmaxf(mx, acc[rr]); }
        float s = 0.f;
#pragma unroll
        for (int rr = 0; rr < RR; rr++) { acc[rr] = expf(acc[rr] - mx); s += acc[rr]; }
        float inv = 1.f / s;
#pragma unroll
        for (int rr = 0; rr < RR; rr++) g_interw[gwarp * NHD + rr] = acc[rr] * inv;
    }
}

// fused interagg + paths (vectorized float4 per thread)
__global__ void postrel_kernel() {
    int idx = blockIdx.x * blockDim.x + threadIdx.x;
    if (idx >= NN * (HH / 4)) return;
    int n = idx >> 6, c4 = idx & 63;
    float4 v[RR];
#pragma unroll
    for (int rr = 0; rr < RR; rr++) {
        size_t b = (size_t)n * RH + rr * HH + 4 * c4;
        v[rr] = load_hl4(g_rel_h + b, g_rel_l + b);
    }
    float4 s = make_float4(0.f, 0.f, 0.f, 0.f);
#pragma unroll
    for (int rr = 0; rr < RR; rr++) {
        float w = g_interw[n * NHD + rr];
        s.x += w * v[rr].x; s.y += w * v[rr].y; s.z += w * v[rr].z; s.w += w * v[rr].w;
    }
    size_t oc = (size_t)n * 2 * HH + 4 * c4;
    split_store4(s, g_cat_h + oc, g_cat_l + oc);
    float4 p0 = make_float4(v[2].x + v[3].x, v[2].y + v[3].y, v[2].z + v[3].z, v[2].w + v[3].w);
    float4 p1 = make_float4(v[4].x + v[0].x, v[4].y + v[0].y, v[4].z + v[0].z, v[4].w + v[0].w);
    float4 p2 = make_float4(v[1].x + v[5].x, v[1].y + v[5].y, v[1].z + v[5].z, v[1].w + v[5].w);
    size_t o0 = ((size_t)0 * NP + n) * HH + 4 * c4;
    size_t o1 = ((size_t)1 * NP + n) * HH + 4 * c4;
    size_t o2 = ((size_t)2 * NP + n) * HH + 4 * c4;
    split_store4(p0, g_pth_h + o0, g_pth_l + o0);
    split_store4(p1, g_pth_h + o1, g_pth_l + o1);
    split_store4(p2, g_pth_h + o2, g_pth_l + o2);
}

__global__ void attnmeta_kernel(const float* __restrict__ Wa2,
                                const float* __restrict__ gm, const float* __restrict__ bm_) {
    __shared__ float lg[3];
    __shared__ float sm[8];
    int n = blockIdx.x, t = threadIdx.x;
    int lane = t & 31, w = t >> 5;
    if (w < 3) {
        float a = 0.f;
        for (int j = lane; j < 128; j += 32)
            a += g_t[((size_t)n * 3 + w) * 128 + j] * Wa2[j];
#pragma unroll
        for (int off = 16; off; off >>= 1) a += __shfl_down_sync(0xffffffff, a, off);
        if (lane == 0) lg[w] = a;
    }
    __syncthreads();
    float l0 = lg[0], l1 = lg[1], l2 = lg[2];
    float mx = fmaxf(l0, fmaxf(l1, l2));
    float e0 = expf(l0 - mx), e1 = expf(l1 - mx), e2 = expf(l2 - mx);
    float inv = 1.f / (e0 + e1 + e2);
    const float* st = g_stacked + (size_t)n * 3 * HH;
    float s = (e0 * st[t] + e1 * st[HH + t] + e2 * st[2 * HH + t]) * inv;
    float mu = block_sum256(s, sm) * (1.f / 256.f);
    float d = s - mu;
    float var = block_sum256(d * d, sm) * (1.f / 256.f);
    float o = d * rsqrtf(var + 1e-5f) * gm[t] + bm_[t];
    split_store(o, g_cat_h + (size_t)n * 2 * HH + HH + t, g_cat_l + (size_t)n * 2 * HH + HH + t);
}

__global__ void outln_kernel(const float* __restrict__ x, const float* __restrict__ gout,
                             const float* __restrict__ bout, float* __restrict__ out) {
    __shared__ float sm[8];
    int n = blockIdx.x, t = threadIdx.x;
    float v = x[(size_t)n * HH + t] + g_hbuf[(size_t)n * HH + t];
    float mu = block_sum256(v, sm) * (1.f / 256.f);
    float d = v - mu;
    float var = block_sum256(d * d, sm) * (1.f / 256.f);
    out[(size_t)n * HH + t] = d * rsqrtf(var + 1e-5f) * gout[t] + bout[t];
}

// ---------------- host ----------------
extern "C" void kernel_launch(void* const* d_in, const int* in_sizes, int n_in,
                              void* d_out, int out_size) {
    const float* x     = (const float*)d_in[0];
    const int*   ei    = (const int*)d_in[1];
    const float* ea    = (const float*)d_in[2];
    const float* Wq    = (const float*)d_in[3];
    const float* bq    = (const float*)d_in[4];
    const float* Wk    = (const float*)d_in[5];
    const float* bk    = (const float*)d_in[6];
    const float* Wv    = (const float*)d_in[7];
    const float* bv    = (const float*)d_in[8];
    const float* prior = (const float*)d_in[9];
    const float* Wm    = (const float*)d_in[10];
    const float* bm    = (const float*)d_in[11];
    const float* W_ir1 = (const float*)d_in[12];
    const float* b_ir1 = (const float*)d_in[13];
    const float* W_ir2 = (const float*)d_in[14];
    const float* b_ir2 = (const float*)d_in[15];
    const float* Wmp   = (const float*)d_in[16];
    const float* bmp   = (const float*)d_in[17];
    const float* Wa1   = (const float*)d_in[18];
    const float* ba1   = (const float*)d_in[19];
    const float* Wa2   = (const float*)d_in[20];
    const float* gmeta = (const float*)d_in[21];
    const float* bmeta = (const float*)d_in[22];
    const float* Wc    = (const float*)d_in[23];
    const float* bc    = (const float*)d_in[24];
    const float* gout  = (const float*)d_in[25];
    const float* bout  = (const float*)d_in[26];
    float* out = (float*)d_out;

    void* p;
#define SYM(v, s) cudaGetSymbolAddress(&p, s); auto* v = (decltype(&s[0]))p
    SYM(p_kvin_h, g_kvin_h);  SYM(p_kvin_l, g_kvin_l);
    SYM(p_xd_h, g_xd_h);      SYM(p_xd_l, g_xd_l);
    SYM(p_qe, g_qe); SYM(p_k, g_k); SYM(p_v, g_v);
    SYM(p_agg_h, g_agg_h);    SYM(p_agg_l, g_agg_l);
    SYM(p_rel_h, g_rel_h);    SYM(p_rel_l, g_rel_l);
    SYM(p_hbuf, g_hbuf);
    SYM(p_cat_h, g_cat_h);    SYM(p_cat_l, g_cat_l);
    SYM(p_pth_h, g_pth_h);    SYM(p_pth_l, g_pth_l);
    SYM(p_stacked, g_stacked);
    SYM(p_stk_h, g_stk_h);    SYM(p_stk_l, g_stk_l);
    SYM(p_t, g_t);
    SYM(p_wqt_h, g_wqt_h);    SYM(p_wqt_l, g_wqt_l);
    SYM(p_wkt_h, g_wkt_h);    SYM(p_wkt_l, g_wkt_l);
    SYM(p_wvt_h, g_wvt_h);    SYM(p_wvt_l, g_wvt_l);
    SYM(p_wmt_h, g_wmt_h);    SYM(p_wmt_l, g_wmt_l);
    SYM(p_wir1t_h, g_wir1t_h); SYM(p_wir1t_l, g_wir1t_l);
    SYM(p_wmpt_h, g_wmpt_h);  SYM(p_wmpt_l, g_wmpt_l);
    SYM(p_wa1t_h, g_wa1t_h);  SYM(p_wa1t_l, g_wa1t_l);
    SYM(p_wct_h, g_wct_h);    SYM(p_wct_l, g_wct_l);
#undef SYM

    const int SMB = 81920;
    cudaFuncSetAttribute((const void*)&tcmm<0, 0>, cudaFuncAttributeMaxDynamicSharedMemorySize, SMB);
    cudaFuncSetAttribute((const void*)&tcmm<1, 2>, cudaFuncAttributeMaxDynamicSharedMemorySize, SMB);
    cudaFuncSetAttribute((const void*)&tcmm<1, 0>, cudaFuncAttributeMaxDynamicSharedMemorySize, SMB);
    cudaFuncSetAttribute((const void*)&tcmm<0, 1>, cudaFuncAttributeMaxDynamicSharedMemorySize, SMB);
    cudaFuncSetAttribute((const void*)&tcmm<2, 0>, cudaFuncAttributeMaxDynamicSharedMemorySize, SMB);

    const int TB = 256;
    bf16* nb16 = nullptr;
    float* nf32 = nullptr;

    // 0: weight transposes+splits
    tsplit_all<<<dim3((RR * HH * KVP + TB - 1) / TB, 8), TB>>>(Wq, Wk, Wv, Wm, W_ir1, Wmp, Wa1, Wc);
    // 1: fills (vectorized)
    {
        long tot = (long)RR * NN * NHD / 4 + (long)RR * NN * HH / 4;
        fill_all<<<(int)((tot + TB - 1) / TB), TB>>>();
    }
    // 2: gather (vectorized)
    gather_split<<<(int)(((long)RR * EE * (KVP / 4 + HH / 4) + TB - 1) / TB), TB>>>(x, ei, ea);

    // 3,4,5: q/k/v GEMMs
    tcmm<0, 0><<<dim3(2, EE / 128, RR), 256, SMB>>>(
        p_xd_h, p_xd_l, (long)EE * HH,
        p_wqt_h, p_wqt_l, (long)HH * HH,
        bq, HH,
        p_qe, HH, 0, (long)EE * HH, 0,
        nb16, nb16, 0, 0, 0, 0, EE, HH);
    tcmm<0, 0><<<dim3(2, EE / 128, RR), 256, SMB>>>(
        p_kvin_h, p_kvin_l, (long)EE * KVP,
        p_wkt_h, p_wkt_l, (long)HH * KVP,
        bk, HH,
        p_k, HH, 0, (long)EE * HH, 0,
        nb16, nb16, 0, 0, 0, 0, EE, KVP);
    tcmm<0, 0><<<dim3(2, EE / 128, RR), 256, SMB>>>(
        p_kvin_h, p_kvin_l, (long)EE * KVP,
        p_wvt_h, p_wvt_l, (long)HH * KVP,
        bv, HH,
        p_v, HH, 0, (long)EE * HH, 0,
        nb16, nb16, 0, 0, 0, 0, EE, KVP);

    // 6-9: attention softmax + aggregation
    scores_kernel<<<RR * EE / 8, TB>>>(ei, prior);
    ex_kernel<<<RR * EE * NHD / TB, TB>>>(ei);
    agg_kernel<<<(int)(((long)RR * EE * (HH / 4) + TB - 1) / TB), TB>>>(ei);
    agg_split_kernel<<<(int)(((long)RR * NN * (HH / 4) + TB - 1) / TB), TB>>>();

    // 10: Wm GEMM -> rel_out
    tcmm<1, 2><<<dim3(2, NP / 128, RR), 256, SMB>>>(
        p_agg_h, p_agg_l, (long)NP * HH,
        p_wmt_h, p_wmt_l, (long)HH * HH,
        bm, HH,
        nf32, 0, 0, 0, 0,
        p_rel_h, p_rel_l, RH, 0, 0, HH, NN, HH);

    // 11-13: inter-relation attention + fused post-rel
    tcmm<1, 0><<<dim3(2, NP / 128, 1), 256, SMB>>>(
        p_rel_h, p_rel_l, 0,
        p_wir1t_h, p_wir1t_l, 0,
        b_ir1, 0,
        p_hbuf, HH, 0, 0, 0,
        nb16, nb16, 0, 0, 0, 0, NN, RH);
    interw_kernel<<<(NN * 32 + TB - 1) / TB, TB>>>(W_ir2, b_ir2);
    postrel_kernel<<<(NN * (HH / 4) + TB - 1) / TB, TB>>>();

    // 14-16: meta paths
    tcmm<0, 1><<<dim3(2, NP / 128, 3), 256, SMB>>>(
        p_pth_h, p_pth_l, (long)NP * HH,
        p_wmpt_h, p_wmpt_l, (long)HH * HH,
        bmp, HH,
        p_stacked, 3 * HH, 0, 0, HH,
        p_stk_h, p_stk_l, 3 * HH, 0, 0, HH, NN, HH);
    tcmm<2, 0><<<dim3(1, (3 * NN + 127) / 128, 1), 256, SMB>>>(
        p_stk_h, p_stk_l, 0,
        p_wa1t_h, p_wa1t_l, 0,
        ba1, 0,
        p_t, HH / 2, 0, 0, 0,
        nb16, nb16, 0, 0, 0, 0, 3 * NN, HH);
    attnmeta_kernel<<<NN, TB>>>(Wa2, gmeta, bmeta);

    // 17-18: combine + output LN
    tcmm<1, 0><<<dim3(2, NP / 128, 1), 256, SMB>>>(
        p_cat_h, p_cat_l, 0,
        p_wct_h, p_wct_l, 0,
        bc, 0,
        p_hbuf, HH, 0, 0, 0,
        nb16, nb16, 0, 0, 0, 0, NN, 2 * HH);
    outln_kernel<<<NN, TB>>>(x, gout, bout, out);
}

// round 11
// speedup vs baseline: 2.3315x; 1.5465x over previous
#include <cuda_runtime.h>
#include <cuda_fp16.h>
#include <math.h>
#include <stdint.h>

#define NN 50000
#define NP 50048          // NN padded to 128
#define RR 6
#define EE 32768
#define HH 256
#define FF 16
#define KVO 272
#define KVP 320           // 272 padded to 64-multiple
#define NHD 8
#define HDD 32
#define RH 1536

typedef __half fp16;

#if defined(__CUDA_ARCH__) && (defined(__CUDA_ARCH_FEAT_SM103_ALL) \
    || (defined(__CUDA_ARCH_SPECIFIC__) && (__CUDA_ARCH_SPECIFIC__ == 1030)) \
    || (defined(__CUDA_ARCH_FAMILY_SPECIFIC__) && (__CUDA_ARCH_FAMILY_SPECIFIC__ == 1030)))
#define HAS_TC05 1
#else
#define HAS_TC05 0
#endif

// ---------------- scratch (device globals; zero-initialized at load) ----------------
__device__ __align__(1024) fp16 g_kvin[RR * EE * KVP];
__device__ __align__(1024) fp16 g_xd[RR * EE * HH];
__device__ float g_qe[(size_t)RR * EE * HH], g_k[(size_t)RR * EE * HH], g_v[(size_t)RR * EE * HH];
__device__ float g_sc[RR * EE * NHD], g_m[RR * NN * NHD], g_denom[RR * NN * NHD];
__device__ float g_agg[(size_t)RR * NN * HH];
__device__ __align__(1024) fp16 g_aggh[(size_t)RR * NP * HH];
__device__ __align__(1024) fp16 g_rel[(size_t)NP * RH];
__device__ float g_hbuf[NP * HH];
__device__ float g_interw[NN * NHD];
__device__ __align__(1024) fp16 g_cat[NP * 2 * HH];
__device__ __align__(1024) fp16 g_pth[3 * NP * HH];
__device__ float g_stacked[NP * 3 * HH];
__device__ __align__(1024) fp16 g_stk[NP * 3 * HH];
__device__ float g_t[3 * NP * (HH / 2)];
// transposed weights: [Ncol][Kpad]
__device__ __align__(1024) fp16 g_wqt[RR * HH * HH];
__device__ __align__(1024) fp16 g_wkt[RR * HH * KVP];
__device__ __align__(1024) fp16 g_wvt[RR * HH * KVP];
__device__ __align__(1024) fp16 g_wmt[RR * HH * HH];
__device__ __align__(1024) fp16 g_wir1t[HH * RH];
__device__ __align__(1024) fp16 g_wmpt[3 * HH * HH];
__device__ __align__(1024) fp16 g_wa1t[(HH/2) * HH];
__device__ __align__(1024) fp16 g_wct[HH * 2 * HH];

// ---------------- common helpers ----------------
__device__ __forceinline__ float gelu_exact(float x) {
    return 0.5f * x * (1.0f + erff(x * 0.7071067811865475f));
}
// packed 4-wide fp16 store (8B aligned)
__device__ __forceinline__ void store4h(float4 v, fp16* p) {
    union { __half2 h[2]; uint2 u; } U;
    U.h[0] = __halves2half2(__float2half_rn(v.x), __float2half_rn(v.y));
    U.h[1] = __halves2half2(__float2half_rn(v.z), __float2half_rn(v.w));
    *(uint2*)p = U.u;
}
__device__ __forceinline__ float4 load4h(const fp16* p) {
    union { uint2 u; __half2 h[2]; } U;
    U.u = *(const uint2*)p;
    float4 r;
    float2 a = __half22float2(U.h[0]), b = __half22float2(U.h[1]);
    r.x = a.x; r.y = a.y; r.z = b.x; r.w = b.y;
    return r;
}
__device__ __forceinline__ void atomicMaxF(float* addr, float v) {
    int* ai = (int*)addr;
    int old = *ai;
    while (__int_as_float(old) < v) {
        int assumed = old;
        old = atomicCAS(ai, assumed, __float_as_int(v));
        if (old == assumed) break;
    }
}
__device__ __forceinline__ float block_sum256(float v, float* sm) {
    int lane = threadIdx.x & 31, w = threadIdx.x >> 5;
#pragma unroll
    for (int o = 16; o; o >>= 1) v += __shfl_xor_sync(0xffffffffu, v, o);
    if (lane == 0) sm[w] = v;
    __syncthreads();
    float r;
    if (threadIdx.x < 8) {
        float s = sm[threadIdx.x];
#pragma unroll
        for (int o = 4; o; o >>= 1) s += __shfl_xor_sync(0xffu, s, o);
        if (threadIdx.x == 0) sm[0] = s;
    }
    __syncthreads();
    r = sm[0];
    __syncthreads();
    return r;
}
__device__ __forceinline__ uint32_t smem_u32(const void* p) {
    uint32_t a;
    asm("{ .reg .u64 t; cvta.to.shared.u64 t, %1; cvt.u32.u64 %0, t; }" : "=r"(a) : "l"(p));
    return a;
}
#define CP_ASYNC16(dst, src) \
    asm volatile("cp.async.cg.shared.global [%0], [%1], 16;" :: "r"(dst), "l"(src))
#define CP_COMMIT() asm volatile("cp.async.commit_group;")
#define CP_WAIT1()  asm volatile("cp.async.wait_group 1;")
#define CP_WAIT0()  asm volatile("cp.async.wait_group 0;")

#if HAS_TC05
#define SWZ128(o) ((o) ^ (((o) >> 3) & 0x70))
__device__ __forceinline__ uint64_t mkdesc(uint32_t addr) {
    return ((uint64_t)2 << 61) | ((uint64_t)1 << 46) | ((uint64_t)64 << 32) |
           ((uint64_t)1 << 16) | ((addr >> 4) & 0x3FFF);
}
__device__ __forceinline__ void mma_f16_ss(uint32_t d, uint64_t ad, uint64_t bd,
                                           uint32_t idesc, bool acc) {
    uint32_t en = acc ? 1u : 0u;
    asm volatile(
        "{\n\t.reg .pred p;\n\tsetp.ne.u32 p, %5, 0;\n\t"
        "tcgen05.mma.cta_group::1.kind::f16 [%0], %1, %2, %3, {%4,%4,%4,%4}, p;\n\t}"
        :: "r"(d), "l"(ad), "l"(bd), "r"(idesc), "r"(0u), "r"(en) : "memory");
}
__device__ __forceinline__ void mbar_init(uint32_t mb, uint32_t cnt) {
    asm volatile("mbarrier.init.shared.b64 [%0], %1;" :: "r"(mb), "r"(cnt) : "memory");
}
__device__ __forceinline__ void mbar_wait(uint32_t mb, int parity) {
    asm volatile(
        "{\n\t.reg .pred P1;\n\t"
        "WL_%=:\n\t"
        "mbarrier.try_wait.parity.acquire.cta.shared::cta.b64 P1, [%0], %1, 0x989680;\n\t"
        "@P1 bra.uni WD_%=;\n\t"
        "bra.uni WL_%=;\n\t"
        "WD_%=:\n\t}"
        :: "r"(mb), "r"(parity) : "memory");
}
#define LDTM_X32(r, a) \
    asm volatile( \
        "tcgen05.ld.sync.aligned.32x32b.x32.b32 " \
        "{%0, %1, %2, %3, %4, %5, %6, %7, " \
        " %8, %9, %10, %11, %12, %13, %14, %15, " \
        " %16, %17, %18, %19, %20, %21, %22, %23, " \
        " %24, %25, %26, %27, %28, %29, %30, %31}, [%32];" \
        : "=r"((r)[0]),  "=r"((r)[1]),  "=r"((r)[2]),  "=r"((r)[3]), \
          "=r"((r)[4]),  "=r"((r)[5]),  "=r"((r)[6]),  "=r"((r)[7]), \
          "=r"((r)[8]),  "=r"((r)[9]),  "=r"((r)[10]), "=r"((r)[11]), \
          "=r"((r)[12]), "=r"((r)[13]), "=r"((r)[14]), "=r"((r)[15]), \
          "=r"((r)[16]), "=r"((r)[17]), "=r"((r)[18]), "=r"((r)[19]), \
          "=r"((r)[20]), "=r"((r)[21]), "=r"((r)[22]), "=r"((r)[23]), \
          "=r"((r)[24]), "=r"((r)[25]), "=r"((r)[26]), "=r"((r)[27]), \
          "=r"((r)[28]), "=r"((r)[29]), "=r"((r)[30]), "=r"((r)[31]) \
        : "r"(a))
#else
__device__ __forceinline__ void hmma16816(float* c, const uint32_t* a, const uint32_t* b) {
    asm volatile(
        "mma.sync.aligned.m16n8k16.row.col.f32.f16.f16.f32 "
        "{%0,%1,%2,%3}, {%4,%5,%6,%7}, {%8,%9}, {%0,%1,%2,%3};"
        : "+f"(c[0]), "+f"(c[1]), "+f"(c[2]), "+f"(c[3])
        : "r"(a[0]), "r"(a[1]), "r"(a[2]), "r"(a[3]), "r"(b[0]), "r"(b[1]));
}
#define LDSM_X4(r, addr) \
    asm volatile("ldmatrix.sync.aligned.m8n8.x4.shared.b16 {%0,%1,%2,%3}, [%4];" \
        : "=r"((r)[0]), "=r"((r)[1]), "=r"((r)[2]), "=r"((r)[3]) : "r"(addr))
#endif

// ---------------- fp16 GEMM (z-batched) ----------------
// Block tile 128x128; 64-K slabs; 2-stage cp.async; 3 CTAs/SM.
// STORE: 0 = fp32 C only; 1 = fp32 C + fp16; 2 = fp16 only.
template <int ACT, int STORE>
__global__ __launch_bounds__(256, 3)
void tcmm(const fp16* __restrict__ A, long az,
          const fp16* __restrict__ B, long bz,
          const float* __restrict__ bias, int biasz,
          float* __restrict__ C, int ldc, int coff, long cz, int coffz,
          fp16* __restrict__ Ch, int ldh, int offh, long chz, int offhz,
          int M, int K) {
    extern __shared__ char smem[];
    const int tid = threadIdx.x, wid = tid >> 5, lid = tid & 31;
    const int m0 = blockIdx.y * 128;
    const int n0 = blockIdx.x * 128;
    const int z = blockIdx.z;
    A += (size_t)z * az;
    B += (size_t)z * bz;
    bias += (size_t)z * biasz;
    if (STORE != 2) { C += (size_t)z * cz; coff += z * coffz; }
    if (STORE != 0) { Ch += (size_t)z * chz; offh += z * offhz; }

#if HAS_TC05
    // ================= tcgen05 path =================
    const uint32_t sb = smem_u32(smem);
    const int ABYTES = 128 * 128;
    const int BUF = 2 * ABYTES;
    const uint32_t mbar0 = sb + 8, mbar1 = sb + 16;
    const uint32_t buf0 = sb + 1024;

    if (wid == 0) {
        asm volatile("tcgen05.alloc.cta_group::1.sync.aligned.shared::cta.b32 [%0], %1;"
                     :: "r"(sb), "r"(128u) : "memory");
        asm volatile("tcgen05.relinquish_alloc_permit.cta_group::1.sync.aligned;");
    }
    __syncthreads();
    uint32_t tmem;
    asm volatile("ld.shared.b32 %0, [%1];" : "=r"(tmem) : "r"(sb));
    if (tid == 0) { mbar_init(mbar0, 1); mbar_init(mbar1, 1); }
    __syncthreads();

    const int T = K >> 6;
    // kind::f16, F16 inputs (atype=btype=0), F32 accum, M=128, N=64
    const uint32_t idesc64 = (1u << 4) | (8u << 17) | (8u << 24);

    auto load_chunk = [&](int c, uint32_t bufbase) {
        int kc = c << 6;
        for (int i = tid; i < 2048; i += 256) {
            uint32_t dst;
            const fp16* src;
            if (i < 1024) {
                int r = i >> 3, g = i & 7;
                dst = bufbase + SWZ128(r * 128 + g * 16);
                src = A + (size_t)(m0 + r) * K + kc + g * 8;
            } else {
                int j = i - 1024;
                int r = j >> 3, g = j & 7;
                dst = bufbase + ABYTES + SWZ128(r * 128 + g * 16);
                src = B + (size_t)(n0 + r) * K + kc + g * 8;
            }
            CP_ASYNC16(dst, src);
        }
        CP_COMMIT();
    };

    int ph0 = 0, ph1 = 0;
    load_chunk(0, buf0);
    for (int c = 0; c < T; c++) {
        int b = c & 1;
        if (c + 1 < T) {
            int nb = b ^ 1;
            if (c >= 1) {
                if (nb) { mbar_wait(mbar1, ph1); ph1 ^= 1; }
                else    { mbar_wait(mbar0, ph0); ph0 ^= 1; }
            }
            load_chunk(c + 1, buf0 + nb * BUF);
            CP_WAIT1();
        } else {
            CP_WAIT0();
        }
        __syncthreads();
        if (tid == 0) {
            asm volatile("fence.proxy.async.shared::cta;" ::: "memory");
            uint64_t ad = mkdesc(buf0 + b * BUF);
            uint64_t bd = mkdesc(buf0 + b * BUF + ABYTES);
#pragma unroll
            for (int ks = 0; ks < 4; ks++)
#pragma unroll
                for (int ns = 0; ns < 2; ns++)
                    mma_f16_ss(tmem + ns * 64, ad + ks * 2, bd + ns * 512 + ks * 2,
                               idesc64, (c > 0) || (ks > 0));
            asm volatile("tcgen05.commit.cta_group::1.mbarrier::arrive::one.shared::cluster.b64 [%0];"
                         :: "r"(b ? mbar1 : mbar0) : "memory");
        }
    }
    {
        int lb = (T - 1) & 1;
        if (lb) mbar_wait(mbar1, ph1); else mbar_wait(mbar0, ph0);
    }
    asm volatile("tcgen05.fence::after_thread_sync;" ::: "memory");

    {
        int row = m0 + (wid & 3) * 32 + lid;
        int colbase = (wid >> 2) * 64;
        for (int cb = 0; cb < 64; cb += 32) {
            uint32_t regs[32];
            LDTM_X32(regs, tmem + colbase + cb);
            asm volatile("tcgen05.wait::ld.sync.aligned;" ::: "memory");
            if (row < M) {
#pragma unroll
                for (int j = 0; j < 32; j++) {
                    int col = n0 + colbase + cb + j;
                    float v = __uint_as_float(regs[j]) + bias[col];
                    if (ACT == 1) v = gelu_exact(v);
                    else if (ACT == 2) v = tanhf(v);
                    if (STORE != 2) C[(size_t)row * ldc + coff + col] = v;
                    if (STORE != 0) Ch[(size_t)row * ldh + offh + col] = __float2half_rn(v);
                }
            }
        }
    }
    __syncthreads();
    if (wid == 0)
        asm volatile("tcgen05.dealloc.cta_group::1.sync.aligned.b32 %0, %1;"
                     :: "r"(tmem), "r"(128u));

#else
    // ================= ldmatrix + mma.sync path =================
    // Stage: A 128x144B + B 128x144B (64-half K-slab) = 36,864 B; 2 stages.
    const uint32_t sm_u = smem_u32(smem);
    const int STG = 36864;
    const int g = lid >> 2, tig = lid & 3;
    const int wr = wid >> 2, wc = wid & 3;
    const int rowbase = wr * 64, colbase = wc * 32;
    const int S = K >> 6;

    const uint32_t a_lane = (uint32_t)(rowbase + (lid & 15)) * 144 + ((lid >> 4) << 4);
    const uint32_t b_lane = (uint32_t)(colbase + (lid & 7) + (((lid >> 4) & 1) << 3)) * 144
                          + (((lid >> 3) & 1) << 4);

    auto load_stage = [&](int s, int buf) {
        int k0 = s << 6;
        uint32_t ab = sm_u + buf * STG, bb = ab + 18432;
#pragma unroll
        for (int rep = 0; rep < 4; rep++) {
            int i = tid + 256 * rep;
            int r = i >> 3, sc = i & 7;
            CP_ASYNC16(ab + r * 144 + sc * 16, A + (size_t)(m0 + r) * K + k0 + sc * 8);
        }
#pragma unroll
        for (int rep = 0; rep < 4; rep++) {
            int i = tid + 256 * rep;
            int r = i >> 3, sc = i & 7;
            CP_ASYNC16(bb + r * 144 + sc * 16, B + (size_t)(n0 + r) * K + k0 + sc * 8);
        }
        CP_COMMIT();
    };

    float acc[4][4][4];
#pragma unroll
    for (int mf = 0; mf < 4; mf++)
#pragma unroll
        for (int nf = 0; nf < 4; nf++)
#pragma unroll
            for (int q = 0; q < 4; q++) acc[mf][nf][q] = 0.f;

    load_stage(0, 0);
    for (int s = 0; s < S; s++) {
        if (s + 1 < S) { load_stage(s + 1, (s + 1) & 1); CP_WAIT1(); }
        else CP_WAIT0();
        __syncthreads();
        uint32_t ab = sm_u + (s & 1) * STG;
        uint32_t bb = ab + 18432;
#pragma unroll
        for (int kk = 0; kk < 64; kk += 16) {
            uint32_t afr[4][4], bfr[2][4];
#pragma unroll
            for (int mf = 0; mf < 4; mf++)
                LDSM_X4(afr[mf], ab + a_lane + mf * 2304 + kk * 2);
#pragma unroll
            for (int np = 0; np < 2; np++)
                LDSM_X4(bfr[np], bb + b_lane + np * 2304 + kk * 2);
#pragma unroll
            for (int mf = 0; mf < 4; mf++)
#pragma unroll
                for (int nf = 0; nf < 4; nf++)
                    hmma16816(acc[mf][nf], afr[mf], &bfr[nf >> 1][(nf & 1) * 2]);
        }
        __syncthreads();
    }

#pragma unroll
    for (int mf = 0; mf < 4; mf++)
#pragma unroll
        for (int nf = 0; nf < 4; nf++) {
            int col0 = n0 + colbase + nf * 8 + 2 * tig;
#pragma unroll
            for (int r8 = 0; r8 < 2; r8++) {
                int row = m0 + rowbase + mf * 16 + g + r8 * 8;
                if (row < M) {
#pragma unroll
                    for (int cc = 0; cc < 2; cc++) {
                        int col = col0 + cc;
                        float v = acc[mf][nf][r8 * 2 + cc] + bias[col];
                        if (ACT == 1) v = gelu_exact(v);
                        else if (ACT == 2) v = tanhf(v);
                        if (STORE != 2) C[(size_t)row * ldc + coff + col] = v;
                        if (STORE != 0) Ch[(size_t)row * ldh + offh + col] = __float2half_rn(v);
                    }
                }
            }
        }
#endif
}

// ---------------- fused weight transpose (ALL weights, 1 launch) ----------------
__global__ void tsplit_all(const float* __restrict__ Wq, const float* __restrict__ Wk,
                           const float* __restrict__ Wv, const float* __restrict__ Wm,
                           const float* __restrict__ Wir1, const float* __restrict__ Wmp,
                           const float* __restrict__ Wa1, const float* __restrict__ Wc) {
    int idx = blockIdx.x * blockDim.x + threadIdx.x;
    int seg = blockIdx.y;
    float v;
    switch (seg) {
    case 0: {
        if (idx >= RR * HH * HH) return;
        int z = idx >> 16, w = idx & 65535, n = w >> 8, k = w & 255;
        v = Wq[(size_t)z * 65536 + k * HH + n];
        g_wqt[idx] = __float2half_rn(v);
        break; }
    case 1: {
        if (idx >= RR * HH * KVP) return;
        int z = idx / 81920, w = idx - z * 81920, n = w / KVP, k = w - n * KVP;
        v = (k < KVO) ? Wk[(size_t)z * KVO * HH + k * HH + n] : 0.f;
        g_wkt[idx] = __float2half_rn(v);
        break; }
    case 2: {
        if (idx >= RR * HH * KVP) return;
        int z = idx / 81920, w = idx - z * 81920, n = w / KVP, k = w - n * KVP;
        v = (k < KVO) ? Wv[(size_t)z * KVO * HH + k * HH + n] : 0.f;
        g_wvt[idx] = __float2half_rn(v);
        break; }
    case 3: {
        if (idx >= RR * HH * HH) return;
        int z = idx >> 16, w = idx & 65535, n = w >> 8, k = w & 255;
        v = Wm[(size_t)z * 65536 + k * HH + n];
        g_wmt[idx] = __float2half_rn(v);
        break; }
    case 4: {
        if (idx >= HH * RH) return;
        int n = idx / RH, k = idx - n * RH;
        v = Wir1[(size_t)k * HH + n];
        g_wir1t[idx] = __float2half_rn(v);
        break; }
    case 5: {
        if (idx >= 3 * HH * HH) return;
        int z = idx >> 16, w = idx & 65535, n = w >> 8, k = w & 255;
        v = Wmp[(size_t)z * 65536 + k * HH + n];
        g_wmpt[idx] = __float2half_rn(v);
        break; }
    case 6: {
        if (idx >= (HH / 2) * HH) return;
        int n = idx >> 8, k = idx & 255;
        v = Wa1[(size_t)k * (HH / 2) + n];
        g_wa1t[idx] = __float2half_rn(v);
        break; }
    default: {
        if (idx >= HH * 2 * HH) return;
        int n = idx >> 9, k = idx & 511;
        v = Wc[(size_t)k * HH + n];
        g_wct[idx] = __float2half_rn(v);
        break; }
    }
}

// ---------------- fused fills (vectorized) ----------------
__global__ void fill_all() {
    const int T14 = RR * NN * NHD / 4;
    const long T24 = (long)RR * NN * HH / 4;
    long idx = (long)blockIdx.x * blockDim.x + threadIdx.x;
    if (idx < T14) {
        ((float4*)g_m)[idx] = make_float4(-INFINITY, -INFINITY, -INFINITY, -INFINITY);
        ((float4*)g_denom)[idx] = make_float4(0.f, 0.f, 0.f, 0.f);
    } else {
        long j = idx - T14;
        if (j < T24) ((float4*)g_agg)[j] = make_float4(0.f, 0.f, 0.f, 0.f);
    }
}

// ---------------- gather (vectorized float4 -> fp16x4) ----------------
__global__ void gather_split(const float* __restrict__ x, const int* __restrict__ ei,
                             const float* __restrict__ ea) {
    long idx = (long)blockIdx.x * blockDim.x + threadIdx.x;
    const long perR = (long)EE * (KVP / 4 + HH / 4);
    if (idx >= RR * perR) return;
    int r = (int)(idx / perR);
    long rem = idx - (long)r * perR;
    if (rem < (long)EE * (KVP / 4)) {
        int e = (int)(rem / (KVP / 4)), c4 = (int)(rem - (long)e * (KVP / 4));
        int src = ei[(r * 2 + 0) * EE + e];
        float4 v;
        if (c4 < 64)      v = ((const float4*)(x + (size_t)src * HH))[c4];
        else if (c4 < 68) v = ((const float4*)(ea + ((size_t)r * EE + e) * FF))[c4 - 64];
        else              v = make_float4(0.f, 0.f, 0.f, 0.f);
        store4h(v, g_kvin + ((size_t)r * EE + e) * KVP + 4 * c4);
    } else {
        long j = rem - (long)EE * (KVP / 4);
        int e = (int)(j >> 6), c4 = (int)(j & 63);
        int dst = ei[(r * 2 + 1) * EE + e];
        float4 v = ((const float4*)(x + (size_t)dst * HH))[c4];
        store4h(v, g_xd + ((size_t)r * EE + e) * HH + 4 * c4);
    }
}

// ---------------- scores: warp per (r, e), coalesced float4 ----------------
__global__ void scores_kernel(const int* __restrict__ ei, const float* __restrict__ prior) {
    int w = (blockIdx.x * blockDim.x + threadIdx.x) >> 5;
    int lane = threadIdx.x & 31;
    if (w >= RR * EE) return;
    int r = w >> 15, e = w & (EE - 1);
    const float4* q4 = (const float4*)g_qe + ((size_t)r * EE + e) * 64;
    const float4* k4 = (const float4*)g_k  + ((size_t)r * EE + e) * 64;
    float4 qa = q4[lane], ka = k4[lane];
    float4 qb = q4[lane + 32], kb = k4[lane + 32];
    float p1 = qa.x * ka.x + qa.y * ka.y + qa.z * ka.z + qa.w * ka.w;
    float p2 = qb.x * kb.x + qb.y * kb.y + qb.z * kb.z + qb.w * kb.w;
#pragma unroll
    for (int off = 1; off < 8; off <<= 1) {
        p1 += __shfl_xor_sync(0xffffffff, p1, off);
        p2 += __shfl_xor_sync(0xffffffff, p2, off);
    }
    if ((lane & 7) == 0) {
        int dst = ei[(r * 2 + 1) * EE + e];
        int h1 = lane >> 3, h2 = h1 + 4;
        float s1 = p1 * 0.17677669529663687f * prior[r * NHD + h1];
        float s2 = p2 * 0.17677669529663687f * prior[r * NHD + h2];
        g_sc[((size_t)r * EE + e) * NHD + h1] = s1;
        g_sc[((size_t)r * EE + e) * NHD + h2] = s2;
        atomicMaxF(&g_m[((size_t)r * NN + dst) * NHD + h1], s1);
        atomicMaxF(&g_m[((size_t)r * NN + dst) * NHD + h2], s2);
    }
}

__global__ void ex_kernel(const int* __restrict__ ei) {
    int idx = blockIdx.x * blockDim.x + threadIdx.x;
    if (idx >= RR * EE * NHD) return;
    int r = idx >> 18;
    int e = (idx >> 3) & (EE - 1), h = idx & 7;
    int dst = ei[(r * 2 + 1) * EE + e];
    float exv = expf(g_sc[idx] - g_m[((size_t)r * NN + dst) * NHD + h]);
    g_sc[idx] = exv;
    atomicAdd(&g_denom[((size_t)r * NN + dst) * NHD + h], exv);
}

// ---------------- aggregation (float4 v + 4 atomics) ----------------
__global__ void agg_kernel(const int* __restrict__ ei) {
    long idx = (long)blockIdx.x * blockDim.x + threadIdx.x;
    if (idx >= (long)RR * EE * (HH / 4)) return;
    int r = (int)(idx >> 21);
    long w_ = idx & ((1L << 21) - 1);
    int e = (int)(w_ >> 6), c4 = (int)(w_ & 63);
    int h = c4 >> 3;
    int dst = ei[(r * 2 + 1) * EE + e];
    float w = g_sc[((size_t)r * EE + e) * NHD + h] /
              (g_denom[((size_t)r * NN + dst) * NHD + h] + 1e-16f);
    float4 vv = ((const float4*)g_v)[idx];
    float* base = &g_agg[((size_t)r * NN + dst) * HH + 4 * c4];
    atomicAdd(base + 0, w * vv.x);
    atomicAdd(base + 1, w * vv.y);
    atomicAdd(base + 2, w * vv.z);
    atomicAdd(base + 3, w * vv.w);
}

__global__ void agg_split_kernel() {
    long idx = (long)blockIdx.x * blockDim.x + threadIdx.x;
    if (idx >= (long)RR * NN * (HH / 4)) return;
    int r = (int)(idx / ((long)NN * 64));
    long w_ = idx - (long)r * NN * 64;
    int n = (int)(w_ >> 6), c4 = (int)(w_ & 63);
    float4 v = ((const float4*)g_agg)[idx];
    store4h(v, g_aggh + ((size_t)r * NP + n) * HH + 4 * c4);
}

__global__ void interw_kernel(const float* __restrict__ Wir2, const float* __restrict__ bir2) {
    int gwarp = (blockIdx.x * blockDim.x + threadIdx.x) >> 5;
    int lane = threadIdx.x & 31;
    if (gwarp >= NN) return;
    float acc[RR] = {};
    for (int k = lane; k < HH; k += 32) {
        float hv = g_hbuf[gwarp * HH + k];
#pragma unroll
        for (int rr = 0; rr < RR; rr++) acc[rr] += hv * Wir2[k * RR + rr];
    }
#pragma unroll
    for (int rr = 0; rr < RR; rr++)
#pragma unroll
        for (int off = 16; off; off >>= 1)
            acc[rr] += __shfl_down_sync(0xffffffff, acc[rr], off);
    if (lane == 0) {
        float mx = -1e30f;
#pragma unroll
        for (int rr = 0; rr < RR; rr++) { acc[rr] += bir2[rr]; mx = fmaxf(mx, acc[rr]); }
        float s = 0.f;
#pragma unroll
        for (int rr = 0; rr < RR; rr++) { acc[rr] = expf(acc[rr] - mx); s += acc[rr]; }
        float inv = 1.f / s;
#pragma unroll
        for (int rr = 0; rr < RR; rr++) g_interw[gwarp * NHD + rr] = acc[rr] * inv;
    }
}

// fused interagg + paths (vectorized)
__global__ void postrel_kernel() {
    int idx = blockIdx.x * blockDim.x + threadIdx.x;
    if (idx >= NN * (HH / 4)) return;
    int n = idx >> 6, c4 = idx & 63;
    float4 v[RR];
#pragma unroll
    for (int rr = 0; rr < RR; rr++)
        v[rr] = load4h(g_rel + (size_t)n * RH + rr * HH + 4 * c4);
    float4 s = make_float4(0.f, 0.f, 0.f, 0.f);
#pragma unroll
    for (int rr = 0; rr < RR; rr++) {
        float w = g_interw[n * NHD + rr];
        s.x += w * v[rr].x; s.y += w * v[rr].y; s.z += w * v[rr].z; s.w += w * v[rr].w;
    }
    store4h(s, g_cat + (size_t)n * 2 * HH + 4 * c4);
    float4 p0 = make_float4(v[2].x + v[3].x, v[2].y + v[3].y, v[2].z + v[3].z, v[2].w + v[3].w);
    float4 p1 = make_float4(v[4].x + v[0].x, v[4].y + v[0].y, v[4].z + v[0].z, v[4].w + v[0].w);
    float4 p2 = make_float4(v[1].x + v[5].x, v[1].y + v[5].y, v[1].z + v[5].z, v[1].w + v[5].w);
    store4h(p0, g_pth + ((size_t)0 * NP + n) * HH + 4 * c4);
    store4h(p1, g_pth + ((size_t)1 * NP + n) * HH + 4 * c4);
    store4h(p2, g_pth + ((size_t)2 * NP + n) * HH + 4 * c4);
}

__global__ void attnmeta_kernel(const float* __restrict__ Wa2,
                                const float* __restrict__ gm, const float* __restrict__ bm_) {
    __shared__ float lg[3];
    __shared__ float sm[8];
    int n = blockIdx.x, t = threadIdx.x;
    int lane = t & 31, w = t >> 5;
    if (w < 3) {
        float a = 0.f;
        for (int j = lane; j < 128; j += 32)
            a += g_t[((size_t)n * 3 + w) * 128 + j] * Wa2[j];
#pragma unroll
        for (int off = 16; off; off >>= 1) a += __shfl_down_sync(0xffffffff, a, off);
        if (lane == 0) lg[w] = a;
    }
    __syncthreads();
    float l0 = lg[0], l1 = lg[1], l2 = lg[2];
    float mx = fmaxf(l0, fmaxf(l1, l2));
    float e0 = expf(l0 - mx), e1 = expf(l1 - mx), e2 = expf(l2 - mx);
    float inv = 1.f / (e0 + e1 + e2);
    const float* st = g_stacked + (size_t)n * 3 * HH;
    float s = (e0 * st[t] + e1 * st[HH + t] + e2 * st[2 * HH + t]) * inv;
    float mu = block_sum256(s, sm) * (1.f / 256.f);
    float d = s - mu;
    float var = block_sum256(d * d, sm) * (1.f / 256.f);
    float o = d * rsqrtf(var + 1e-5f) * gm[t] + bm_[t];
    g_cat[(size_t)n * 2 * HH + HH + t] = __float2half_rn(o);
}

__global__ void outln_kernel(const float* __restrict__ x, const float* __restrict__ gout,
                             const float* __restrict__ bout, float* __restrict__ out) {
    __shared__ float sm[8];
    int n = blockIdx.x, t = threadIdx.x;
    float v = x[(size_t)n * HH + t] + g_hbuf[(size_t)n * HH + t];
    float mu = block_sum256(v, sm) * (1.f / 256.f);
    float d = v - mu;
    float var = block_sum256(d * d, sm) * (1.f / 256.f);
    out[(size_t)n * HH + t] = d * rsqrtf(var + 1e-5f) * gout[t] + bout[t];
}

// ---------------- host ----------------
extern "C" void kernel_launch(void* const* d_in, const int* in_sizes, int n_in,
                              void* d_out, int out_size) {
    const float* x     = (const float*)d_in[0];
    const int*   ei    = (const int*)d_in[1];
    const float* ea    = (const float*)d_in[2];
    const float* Wq    = (const float*)d_in[3];
    const float* bq    = (const float*)d_in[4];
    const float* Wk    = (const float*)d_in[5];
    const float* bk    = (const float*)d_in[6];
    const float* Wv    = (const float*)d_in[7];
    const float* bv    = (const float*)d_in[8];
    const float* prior = (const float*)d_in[9];
    const float* Wm    = (const float*)d_in[10];
    const float* bm    = (const float*)d_in[11];
    const float* W_ir1 = (const float*)d_in[12];
    const float* b_ir1 = (const float*)d_in[13];
    const float* W_ir2 = (const float*)d_in[14];
    const float* b_ir2 = (const float*)d_in[15];
    const float* Wmp   = (const float*)d_in[16];
    const float* bmp   = (const float*)d_in[17];
    const float* Wa1   = (const float*)d_in[18];
    const float* ba1   = (const float*)d_in[19];
    const float* Wa2   = (const float*)d_in[20];
    const float* gmeta = (const float*)d_in[21];
    const float* bmeta = (const float*)d_in[22];
    const float* Wc    = (const float*)d_in[23];
    const float* bc    = (const float*)d_in[24];
    const float* gout  = (const float*)d_in[25];
    const float* bout  = (const float*)d_in[26];
    float* out = (float*)d_out;

    void* p;
#define SYM(v, s) cudaGetSymbolAddress(&p, s); auto* v = (decltype(&s[0]))p
    SYM(p_kvin, g_kvin);
    SYM(p_xd, g_xd);
    SYM(p_qe, g_qe); SYM(p_k, g_k); SYM(p_v, g_v);
    SYM(p_aggh, g_aggh);
    SYM(p_rel, g_rel);
    SYM(p_hbuf, g_hbuf);
    SYM(p_cat, g_cat);
    SYM(p_pth, g_pth);
    SYM(p_stacked, g_stacked);
    SYM(p_stk, g_stk);
    SYM(p_t, g_t);
    SYM(p_wqt, g_wqt);
    SYM(p_wkt, g_wkt);
    SYM(p_wvt, g_wvt);
    SYM(p_wmt, g_wmt);
    SYM(p_wir1t, g_wir1t);
    SYM(p_wmpt, g_wmpt);
    SYM(p_wa1t, g_wa1t);
    SYM(p_wct, g_wct);
#undef SYM

    const int SMB = 73728;   // 2 stages x 36,864 B -> 3 CTAs/SM; tcgen05 path 66,560
    cudaFuncSetAttribute((const void*)&tcmm<0, 0>, cudaFuncAttributeMaxDynamicSharedMemorySize, SMB);
    cudaFuncSetAttribute((const void*)&tcmm<1, 2>, cudaFuncAttributeMaxDynamicSharedMemorySize, SMB);
    cudaFuncSetAttribute((const void*)&tcmm<1, 0>, cudaFuncAttributeMaxDynamicSharedMemorySize, SMB);
    cudaFuncSetAttribute((const void*)&tcmm<0, 1>, cudaFuncAttributeMaxDynamicSharedMemorySize, SMB);
    cudaFuncSetAttribute((const void*)&tcmm<2, 0>, cudaFuncAttributeMaxDynamicSharedMemorySize, SMB);

    const int TB = 256;
    fp16* nh = nullptr;
    float* nf32 = nullptr;

    // 0: weight transposes
    tsplit_all<<<dim3((RR * HH * KVP + TB - 1) / TB, 8), TB>>>(Wq, Wk, Wv, Wm, W_ir1, Wmp, Wa1, Wc);
    // 1: fills
    {
        long tot = (long)RR * NN * NHD / 4 + (long)RR * NN * HH / 4;
        fill_all<<<(int)((tot + TB - 1) / TB), TB>>>();
    }
    // 2: gather
    gather_split<<<(int)(((long)RR * EE * (KVP / 4 + HH / 4) + TB - 1) / TB), TB>>>(x, ei, ea);

    // 3,4,5: q/k/v GEMMs
    tcmm<0, 0><<<dim3(2, EE / 128, RR), 256, SMB>>>(
        p_xd, (long)EE * HH,
        p_wqt, (long)HH * HH,
        bq, HH,
        p_qe, HH, 0, (long)EE * HH, 0,
        nh, 0, 0, 0, 0, EE, HH);
    tcmm<0, 0><<<dim3(2, EE / 128, RR), 256, SMB>>>(
        p_kvin, (long)EE * KVP,
        p_wkt, (long)HH * KVP,
        bk, HH,
        p_k, HH, 0, (long)EE * HH, 0,
        nh, 0, 0, 0, 0, EE, KVP);
    tcmm<0, 0><<<dim3(2, EE / 128, RR), 256, SMB>>>(
        p_kvin, (long)EE * KVP,
        p_wvt, (long)HH * KVP,
        bv, HH,
        p_v, HH, 0, (long)EE * HH, 0,
        nh, 0, 0, 0, 0, EE, KVP);

    // 6-9: attention softmax + aggregation
    scores_kernel<<<RR * EE / 8, TB>>>(ei, prior);
    ex_kernel<<<RR * EE * NHD / TB, TB>>>(ei);
    agg_kernel<<<(int)(((long)RR * EE * (HH / 4) + TB - 1) / TB), TB>>>(ei);
    agg_split_kernel<<<(int)(((long)RR * NN * (HH / 4) + TB - 1) / TB), TB>>>();

    // 10: Wm GEMM -> rel_out (fp16 only)
    tcmm<1, 2><<<dim3(2, NP / 128, RR), 256, SMB>>>(
        p_aggh, (long)NP * HH,
        p_wmt, (long)HH * HH,
        bm, HH,
        nf32, 0, 0, 0, 0,
        p_rel, RH, 0, 0, HH, NN, HH);

    // 11-13: inter-relation attention + fused post-rel
    tcmm<1, 0><<<dim3(2, NP / 128, 1), 256, SMB>>>(
        p_rel, 0,
        p_wir1t, 0,
        b_ir1, 0,
        p_hbuf, HH, 0, 0, 0,
        nh, 0, 0, 0, 0, NN, RH);
    interw_kernel<<<(NN * 32 + TB - 1) / TB, TB>>>(W_ir2, b_ir2);
    postrel_kernel<<<(NN * (HH / 4) + TB - 1) / TB, TB>>>();

    // 14-16: meta paths
    tcmm<0, 1><<<dim3(2, NP / 128, 3), 256, SMB>>>(
        p_pth, (long)NP * HH,
        p_wmpt, (long)HH * HH,
        bmp, HH,
        p_stacked, 3 * HH, 0, 0, HH,
        p_stk, 3 * HH, 0, 0, HH, NN, HH);
    tcmm<2, 0><<<dim3(1, (3 * NN + 127) / 128, 1), 256, SMB>>>(
        p_stk, 0,
        p_wa1t, 0,
        ba1, 0,
        p_t, HH / 2, 0, 0, 0,
        nh, 0, 0, 0, 0, 3 * NN, HH);
    attnmeta_kernel<<<NN, TB>>>(Wa2, gmeta, bmeta);

    // 17-18: combine + output LN
    tcmm<1, 0><<<dim3(2, NP / 128, 1), 256, SMB>>>(
        p_cat, 0,
        p_wct, 0,
        bc, 0,
        p_hbuf, HH, 0, 0, 0,
        nh, 0, 0, 0, 0, NN, 2 * HH);
    outln_kernel<<<NN, TB>>>(x, gout, bout, out);
}